// round 12
// baseline (speedup 1.0000x reference)
#include <cuda_runtime.h>
#include <cuda_bf16.h>
#include <stdint.h>
#include <math.h>

#define SEQ 4096
#define DIM 768
#define NH  12
#define HD  64
#define NL  12
#define FFD 3072
#define WIN 256
#define EPSF 1e-5f

// ---------------- scratch (static device globals; no runtime allocation) ----
__device__ float g_x[SEQ * DIM];
__device__ float g_t[SEQ * DIM];
__device__ float g_bcat[3 * DIM];
__device__ int   g_pos[SEQ];

__device__ __nv_bfloat16 g_xh[SEQ * DIM],  g_xl[SEQ * DIM];
__device__ __nv_bfloat16 g_qkvh[SEQ * 3 * DIM], g_qkvl[SEQ * 3 * DIM];
__device__ __nv_bfloat16 g_ah[SEQ * DIM],  g_al[SEQ * DIM];
__device__ __nv_bfloat16 g_hh[SEQ * FFD],  g_hl[SEQ * FFD];
__device__ __nv_bfloat16 g_wqh[DIM * 3 * DIM], g_wql[DIM * 3 * DIM];
__device__ __nv_bfloat16 g_w1h[DIM * FFD], g_w1l[DIM * FFD];
__device__ __nv_bfloat16 g_w2h[FFD * DIM], g_w2l[FFD * DIM];
__device__ __nv_bfloat16 g_woh[DIM * DIM], g_wol[DIM * DIM];

// ---------------- helpers ---------------------------------------------------
__device__ __forceinline__ float gelu_exact(float x) {
    return 0.5f * x * (1.0f + erff(x * 0.70710678118654752f));
}

__device__ __forceinline__ uint32_t pack_bf16x2(float x, float y) {
    __nv_bfloat162 h = __floats2bfloat162_rn(x, y);
    return *(uint32_t*)&h;
}

__device__ __forceinline__ void mma_bf16(float& d0, float& d1, float& d2, float& d3,
                                         uint32_t a0, uint32_t a1, uint32_t a2, uint32_t a3,
                                         uint32_t b0, uint32_t b1) {
    asm volatile("mma.sync.aligned.m16n8k16.row.col.f32.bf16.bf16.f32 "
                 "{%0,%1,%2,%3}, {%4,%5,%6,%7}, {%8,%9}, {%0,%1,%2,%3};"
                 : "+f"(d0), "+f"(d1), "+f"(d2), "+f"(d3)
                 : "r"(a0), "r"(a1), "r"(a2), "r"(a3), "r"(b0), "r"(b1));
}

__device__ __forceinline__ void ldsm4(uint32_t& r0, uint32_t& r1, uint32_t& r2, uint32_t& r3,
                                      uint32_t addr) {
    asm volatile("ldmatrix.sync.aligned.m8n8.x4.shared.b16 {%0,%1,%2,%3}, [%4];"
                 : "=r"(r0), "=r"(r1), "=r"(r2), "=r"(r3) : "r"(addr));
}

__device__ __forceinline__ void ldsm4t(uint32_t& r0, uint32_t& r1, uint32_t& r2, uint32_t& r3,
                                       uint32_t addr) {
    asm volatile("ldmatrix.sync.aligned.m8n8.x4.trans.shared.b16 {%0,%1,%2,%3}, [%4];"
                 : "=r"(r0), "=r"(r1), "=r"(r2), "=r"(r3) : "r"(addr));
}

__device__ __forceinline__ void cp16(uint32_t saddr, const void* gaddr) {
    asm volatile("cp.async.cg.shared.global [%0], [%1], 16;" :: "r"(saddr), "l"(gaddr));
}

__device__ __forceinline__ float blk_sum256(float v, float* red) {
    #pragma unroll
    for (int o = 16; o > 0; o >>= 1) v += __shfl_down_sync(0xffffffffu, v, o);
    int w = threadIdx.x >> 5;
    if ((threadIdx.x & 31) == 0) red[w] = v;
    __syncthreads();
    if (threadIdx.x < 32) {
        v = (threadIdx.x < 8) ? red[threadIdx.x] : 0.0f;
        #pragma unroll
        for (int o = 4; o > 0; o >>= 1) v += __shfl_down_sync(0xffffffffu, v, o);
        if (threadIdx.x == 0) red[0] = v;
    }
    __syncthreads();
    float r = red[0];
    __syncthreads();
    return r;
}

// ---------------- pos_ids = cumsum(mask)*mask + 1 ---------------------------
__global__ void pos_kernel(const int* __restrict__ mask, int* __restrict__ pos) {
    __shared__ int ss[1024];
    int t = threadIdx.x;
    int m0 = mask[t * 4 + 0], m1 = mask[t * 4 + 1];
    int m2 = mask[t * 4 + 2], m3 = mask[t * 4 + 3];
    int s = m0 + m1 + m2 + m3;
    ss[t] = s;
    __syncthreads();
    for (int off = 1; off < 1024; off <<= 1) {
        int vprev = (t >= off) ? ss[t - off] : 0;
        __syncthreads();
        ss[t] += vprev;
        __syncthreads();
    }
    int run = ss[t] - s;
    run += m0; pos[t * 4 + 0] = run * m0 + 1;
    run += m1; pos[t * 4 + 1] = run * m1 + 1;
    run += m2; pos[t * 4 + 2] = run * m2 + 1;
    run += m3; pos[t * 4 + 3] = run * m3 + 1;
}

// ---------------- embedding + layernorm (writes f32 + bf16 hi/lo) -----------
__global__ void embed_ln_kernel(const int* __restrict__ ids, const int* __restrict__ pos,
                                const float* __restrict__ ew, const float* __restrict__ ep,
                                const float* __restrict__ et, const float* __restrict__ g,
                                const float* __restrict__ b, float* __restrict__ x,
                                __nv_bfloat16* __restrict__ xh, __nv_bfloat16* __restrict__ xl) {
    __shared__ float red[32];
    int srow = blockIdx.x;
    int t = threadIdx.x;
    int wid = ids[srow];
    int pid = pos[srow];
    float val[3];
    #pragma unroll
    for (int r = 0; r < 3; r++) {
        int i = t + r * 256;
        val[r] = ew[(size_t)wid * DIM + i] + ep[(size_t)pid * DIM + i] + et[i];
    }
    float mu = blk_sum256(val[0] + val[1] + val[2], red) * (1.0f / DIM);
    float vs = 0.0f;
    #pragma unroll
    for (int r = 0; r < 3; r++) { float d = val[r] - mu; vs += d * d; }
    float var = blk_sum256(vs, red) * (1.0f / DIM);
    float rs = rsqrtf(var + EPSF);
    #pragma unroll
    for (int r = 0; r < 3; r++) {
        int i = t + r * 256;
        float y = (val[r] - mu) * rs * g[i] + b[i];
        size_t idx = (size_t)srow * DIM + i;
        x[idx] = y;
        __nv_bfloat16 h = __float2bfloat16_rn(y);
        xh[idx] = h;
        xl[idx] = __float2bfloat16_rn(y - __bfloat162float(h));
    }
}

// ---------------- x = LN(x + delta), writes f32 + bf16 hi/lo -----------------
__global__ void lnres_kernel(float* __restrict__ x, const float* __restrict__ delta,
                             const float* __restrict__ g, const float* __restrict__ b,
                             __nv_bfloat16* __restrict__ xh, __nv_bfloat16* __restrict__ xl) {
    __shared__ float red[32];
    int srow = blockIdx.x;
    int t = threadIdx.x;
    float val[3];
    #pragma unroll
    for (int r = 0; r < 3; r++) {
        int i = t + r * 256;
        val[r] = x[(size_t)srow * DIM + i] + delta[(size_t)srow * DIM + i];
    }
    float mu = blk_sum256(val[0] + val[1] + val[2], red) * (1.0f / DIM);
    float vs = 0.0f;
    #pragma unroll
    for (int r = 0; r < 3; r++) { float d = val[r] - mu; vs += d * d; }
    float var = blk_sum256(vs, red) * (1.0f / DIM);
    float rs = rsqrtf(var + EPSF);
    #pragma unroll
    for (int r = 0; r < 3; r++) {
        int i = t + r * 256;
        float y = (val[r] - mu) * rs * g[i] + b[i];
        size_t idx = (size_t)srow * DIM + i;
        x[idx] = y;
        __nv_bfloat16 h = __float2bfloat16_rn(y);
        xh[idx] = h;
        xl[idx] = __float2bfloat16_rn(y - __bfloat162float(h));
    }
}

// ---------------- generic f32 -> bf16 hi/lo split -----------------------------
__global__ void split_kernel(const float* __restrict__ s, __nv_bfloat16* __restrict__ hi,
                             __nv_bfloat16* __restrict__ lo, int n4) {
    int i = blockIdx.x * blockDim.x + threadIdx.x;
    if (i >= n4) return;
    float4 v = ((const float4*)s)[i];
    __nv_bfloat16 h0 = __float2bfloat16_rn(v.x), h1 = __float2bfloat16_rn(v.y);
    __nv_bfloat16 h2 = __float2bfloat16_rn(v.z), h3 = __float2bfloat16_rn(v.w);
    uint2 hp, lp;
    hp.x = ((uint32_t)*(uint16_t*)&h0) | ((uint32_t)*(uint16_t*)&h1 << 16);
    hp.y = ((uint32_t)*(uint16_t*)&h2) | ((uint32_t)*(uint16_t*)&h3 << 16);
    lp.x = pack_bf16x2(v.x - __bfloat162float(h0), v.y - __bfloat162float(h1));
    lp.y = pack_bf16x2(v.z - __bfloat162float(h2), v.w - __bfloat162float(h3));
    ((uint2*)hi)[i] = hp;
    ((uint2*)lo)[i] = lp;
}

// ---------------- concat QKV weights (split to bf16) + bias ------------------
__global__ void concat_qkv_kernel(const float* __restrict__ Wq, const float* __restrict__ Wk,
                                  const float* __restrict__ Wv, const float* __restrict__ bq,
                                  const float* __restrict__ bk, const float* __restrict__ bv,
                                  __nv_bfloat16* __restrict__ Wh, __nv_bfloat16* __restrict__ Wl,
                                  float* __restrict__ bc) {
    int i4 = blockIdx.x * blockDim.x + threadIdx.x;
    if (i4 < DIM * DIM / 4) {
        int k = i4 / (DIM / 4);
        int n4 = i4 % (DIM / 4);
        const float* srcs[3] = {Wq, Wk, Wv};
        #pragma unroll
        for (int s = 0; s < 3; s++) {
            float4 v = ((const float4*)srcs[s])[i4];
            __nv_bfloat16 h0 = __float2bfloat16_rn(v.x), h1 = __float2bfloat16_rn(v.y);
            __nv_bfloat16 h2 = __float2bfloat16_rn(v.z), h3 = __float2bfloat16_rn(v.w);
            uint2 hp, lp;
            hp.x = ((uint32_t)*(uint16_t*)&h0) | ((uint32_t)*(uint16_t*)&h1 << 16);
            hp.y = ((uint32_t)*(uint16_t*)&h2) | ((uint32_t)*(uint16_t*)&h3 << 16);
            lp.x = pack_bf16x2(v.x - __bfloat162float(h0), v.y - __bfloat162float(h1));
            lp.y = pack_bf16x2(v.z - __bfloat162float(h2), v.w - __bfloat162float(h3));
            int e = k * 3 * DIM + s * DIM + n4 * 4;
            ((uint2*)Wh)[e >> 2] = hp;
            ((uint2*)Wl)[e >> 2] = lp;
        }
    }
    if (i4 < DIM / 4) {
        ((float4*)bc)[i4] = ((const float4*)bq)[i4];
        ((float4*)(bc + DIM))[i4] = ((const float4*)bk)[i4];
        ((float4*)(bc + 2 * DIM))[i4] = ((const float4*)bv)[i4];
    }
}

// ---------------- bf16x3 tensor-core GEMM (BK=32, cp.async + ldmatrix) -------
// OUT=0: f32 C + bias.  OUT=2: gelu(C+bias) -> bf16 hi/lo.  OUT=3: (C+bias) -> bf16 hi/lo.
template <int BM, int OUT>
__global__ __launch_bounds__(256) void tgemm_kernel(
    const __nv_bfloat16* __restrict__ Ah, const __nv_bfloat16* __restrict__ Al,
    const __nv_bfloat16* __restrict__ Bh, const __nv_bfloat16* __restrict__ Bl,
    const float* __restrict__ bias, float* __restrict__ C,
    __nv_bfloat16* __restrict__ Chi, __nv_bfloat16* __restrict__ Clo,
    int M, int N, int K) {
    constexpr int MT = BM / 64;
    constexpr int OFF_AL = BM * 64;
    constexpr int OFF_BH = 2 * BM * 64;
    constexpr int OFF_BL = 2 * BM * 64 + 8192;
    constexpr int STAGE  = 2 * BM * 64 + 16384;
    constexpr int AITERS = BM * 4 / 256;

    extern __shared__ __align__(16) unsigned char smem_raw[];
    uint32_t smemb = (uint32_t)__cvta_generic_to_shared(smem_raw);

    const int bx = blockIdx.x;
    const int by = blockIdx.y;
    const int tid = threadIdx.x;
    const int lane = tid & 31;
    const int wid = tid >> 5;
    const int warpM = wid & 3;
    const int warpN = wid >> 2;
    const int gid = lane >> 2;
    const int tig = lane & 3;
    const int mBase = warpM * 16 * MT;
    const int nBase = warpN * 64;
    const int rowbase = by * BM;
    const int colbase = bx * 128;

    float acc[MT][8][4];
    #pragma unroll
    for (int mt = 0; mt < MT; mt++)
        #pragma unroll
        for (int nt = 0; nt < 8; nt++)
            #pragma unroll
            for (int r = 0; r < 4; r++) acc[mt][nt][r] = 0.0f;

    auto issue = [&](int st, int k0) {
        uint32_t sb = smemb + st * STAGE;
        #pragma unroll
        for (int it = 0; it < AITERS; it++) {
            int idx = tid + it * 256;
            int r = idx >> 2, ch = idx & 3;
            size_t go = (size_t)(rowbase + r) * K + k0 + ch * 8;
            uint32_t so = (uint32_t)(r * 64 + ((ch ^ ((r >> 1) & 3)) << 4));
            cp16(sb + so, Ah + go);
            cp16(sb + OFF_AL + so, Al + go);
        }
        #pragma unroll
        for (int it = 0; it < 2; it++) {
            int idx = tid + it * 256;
            int krow = idx >> 4, ch = idx & 15;
            size_t go = (size_t)(k0 + krow) * N + colbase + ch * 8;
            uint32_t so = (uint32_t)(krow * 256 + ((ch ^ (krow & 7)) << 4));
            cp16(sb + OFF_BH + so, Bh + go);
            cp16(sb + OFF_BL + so, Bl + go);
        }
    };

    const int KT = K >> 5;
    issue(0, 0);
    asm volatile("cp.async.commit_group;" ::: "memory");

    const int lane15 = lane & 15;
    const int laneh = lane >> 4;
    const int bk = lane & 15;
    const int bs = (lane >> 4) & 1;

    for (int t = 0; t < KT; t++) {
        if (t + 1 < KT) {
            issue((t + 1) & 1, (t + 1) * 32);
            asm volatile("cp.async.commit_group;" ::: "memory");
            asm volatile("cp.async.wait_group 1;" ::: "memory");
        } else {
            asm volatile("cp.async.wait_group 0;" ::: "memory");
        }
        __syncthreads();

        uint32_t sb = smemb + (t & 1) * STAGE;
        #pragma unroll
        for (int kk = 0; kk < 2; kk++) {
            uint32_t aHi[MT][4], aLo[MT][4];
            #pragma unroll
            for (int mt = 0; mt < MT; mt++) {
                int row = mBase + mt * 16 + lane15;
                int ch = (kk * 2 + laneh) ^ ((row >> 1) & 3);
                uint32_t ad = sb + (uint32_t)(row * 64 + (ch << 4));
                ldsm4(aHi[mt][0], aHi[mt][1], aHi[mt][2], aHi[mt][3], ad);
                ldsm4(aLo[mt][0], aLo[mt][1], aLo[mt][2], aLo[mt][3], ad + OFF_AL);
            }
            int krow = kk * 16 + bk;
            uint32_t bRow = sb + OFF_BH + (uint32_t)(krow * 256);
            #pragma unroll
            for (int nt2 = 0; nt2 < 4; nt2++) {
                uint32_t ch = (uint32_t)((((warpN * 8 + nt2 * 2 + bs) ^ (bk & 7))) * 16);
                uint32_t bh0, bh1, bh2, bh3, bl0, bl1, bl2, bl3;
                ldsm4t(bh0, bh1, bh2, bh3, bRow + ch);
                ldsm4t(bl0, bl1, bl2, bl3, bRow + (OFF_BL - OFF_BH) + ch);
                #pragma unroll
                for (int mt = 0; mt < MT; mt++) {
                    float* a0 = acc[mt][nt2 * 2];
                    mma_bf16(a0[0], a0[1], a0[2], a0[3],
                             aHi[mt][0], aHi[mt][1], aHi[mt][2], aHi[mt][3], bh0, bh1);
                    mma_bf16(a0[0], a0[1], a0[2], a0[3],
                             aHi[mt][0], aHi[mt][1], aHi[mt][2], aHi[mt][3], bl0, bl1);
                    mma_bf16(a0[0], a0[1], a0[2], a0[3],
                             aLo[mt][0], aLo[mt][1], aLo[mt][2], aLo[mt][3], bh0, bh1);
                    float* a1 = acc[mt][nt2 * 2 + 1];
                    mma_bf16(a1[0], a1[1], a1[2], a1[3],
                             aHi[mt][0], aHi[mt][1], aHi[mt][2], aHi[mt][3], bh2, bh3);
                    mma_bf16(a1[0], a1[1], a1[2], a1[3],
                             aHi[mt][0], aHi[mt][1], aHi[mt][2], aHi[mt][3], bl2, bl3);
                    mma_bf16(a1[0], a1[1], a1[2], a1[3],
                             aLo[mt][0], aLo[mt][1], aLo[mt][2], aLo[mt][3], bh2, bh3);
                }
            }
        }
        __syncthreads();
    }

    #pragma unroll
    for (int nt = 0; nt < 8; nt++) {
        int col = colbase + nBase + nt * 8 + tig * 2;
        float b0 = bias[col], b1 = bias[col + 1];
        #pragma unroll
        for (int mt = 0; mt < MT; mt++) {
            int row0 = rowbase + mBase + mt * 16 + gid;
            float v0 = acc[mt][nt][0] + b0;
            float v1 = acc[mt][nt][1] + b1;
            float v2 = acc[mt][nt][2] + b0;
            float v3 = acc[mt][nt][3] + b1;
            if (OUT == 0) {
                *(float2*)(C + (size_t)row0 * N + col) = make_float2(v0, v1);
                *(float2*)(C + (size_t)(row0 + 8) * N + col) = make_float2(v2, v3);
            } else {
                if (OUT == 2) {
                    v0 = gelu_exact(v0); v1 = gelu_exact(v1);
                    v2 = gelu_exact(v2); v3 = gelu_exact(v3);
                }
                size_t i0 = ((size_t)row0 * N + col) >> 1;
                size_t i1 = ((size_t)(row0 + 8) * N + col) >> 1;
                __nv_bfloat16 h0 = __float2bfloat16_rn(v0), h1 = __float2bfloat16_rn(v1);
                __nv_bfloat16 h2 = __float2bfloat16_rn(v2), h3 = __float2bfloat16_rn(v3);
                ((uint32_t*)Chi)[i0] = ((uint32_t)*(uint16_t*)&h0) | ((uint32_t)*(uint16_t*)&h1 << 16);
                ((uint32_t*)Chi)[i1] = ((uint32_t)*(uint16_t*)&h2) | ((uint32_t)*(uint16_t*)&h3 << 16);
                ((uint32_t*)Clo)[i0] = pack_bf16x2(v0 - __bfloat162float(h0), v1 - __bfloat162float(h1));
                ((uint32_t*)Clo)[i1] = pack_bf16x2(v2 - __bfloat162float(h2), v3 - __bfloat162float(h3));
            }
        }
    }
}

// ---------------- tensor-core sliding-window flash attention ------------------
// Pipelined: qkv pre-split bf16 hi/lo in gmem, cp.async double-buffered K/V.
// Two barriers per chunk (leading after wait_group; trailing protects WAR on
// the buffer the next iteration's cp.async overwrites). Scale folded into softmax.
#define ATT_SMEM (65536 + 256)
__global__ __launch_bounds__(128) void attn_mma_kernel(
    const __nv_bfloat16* __restrict__ qkvh, const __nv_bfloat16* __restrict__ qkvl,
    const int* __restrict__ mask,
    __nv_bfloat16* __restrict__ oh, __nv_bfloat16* __restrict__ ol) {
    extern __shared__ __align__(16) unsigned char asmem[];
    const uint32_t sb = (uint32_t)__cvta_generic_to_shared(asmem);
    const uint32_t QH = sb, QL = sb + 16384;
    int* mskbuf = (int*)(asmem + 65536);

    const int h = blockIdx.y;
    const int q0 = blockIdx.x * 128;
    const int tid = threadIdx.x, lane = tid & 31, wid = tid >> 5;
    const int gid = lane >> 2, tig = lane & 3;
    const int mBase = wid * 32;
    const int STR = 3 * DIM;
    const int NC = (128 + 2 * WIN) / 32;   // 20 chunks

    auto issueKV = [&](int st, int c) {
        uint32_t kb = sb + 32768 + st * 16384;
        #pragma unroll
        for (int i = 0; i < 2; i++) {
            int idx = tid + i * 128;
            int row = idx >> 3, ch = idx & 7;
            int kp = c + row;
            int kc = kp < 0 ? 0 : (kp >= SEQ ? SEQ - 1 : kp);
            size_t gk = (size_t)kc * STR + DIM + h * 64 + ch * 8;
            size_t gv = (size_t)kc * STR + 2 * DIM + h * 64 + ch * 8;
            uint32_t so = (uint32_t)(row * 128 + ((ch ^ (row & 7)) << 4));
            cp16(kb + so, qkvh + gk);
            cp16(kb + 4096 + so, qkvl + gk);
            cp16(kb + 8192 + so, qkvh + gv);
            cp16(kb + 12288 + so, qkvl + gv);
        }
        if (tid < 32) {
            int kp = c + tid;
            mskbuf[st * 32 + tid] = (kp >= 0 && kp < SEQ) ? mask[kp] : 0;
        }
    };

    // ---- prologue: Q tiles + first KV chunk ----
    #pragma unroll
    for (int i = 0; i < 8; i++) {
        int idx = tid + i * 128;
        int row = idx >> 3, ch = idx & 7;
        size_t gq = (size_t)(q0 + row) * STR + h * 64 + ch * 8;
        uint32_t so = (uint32_t)(row * 128 + ((ch ^ (row & 7)) << 4));
        cp16(QH + so, qkvh + gq);
        cp16(QL + so, qkvl + gq);
    }
    const int cstart = q0 - WIN;
    issueKV(0, cstart);
    asm volatile("cp.async.commit_group;" ::: "memory");

    uint32_t Qhi[2][4][4], Qlo[2][4][4];
    float O[2][8][4];
    #pragma unroll
    for (int mt = 0; mt < 2; mt++)
        #pragma unroll
        for (int dj = 0; dj < 8; dj++)
            #pragma unroll
            for (int r = 0; r < 4; r++) O[mt][dj][r] = 0.0f;
    float mrow[2][2] = {{-1e30f, -1e30f}, {-1e30f, -1e30f}};
    float lrow[2][2] = {{0.0f, 0.0f}, {0.0f, 0.0f}};

    const int warpLo = q0 + mBase - WIN;
    const int warpHi = q0 + mBase + 31 + WIN;

    for (int t = 0; t < NC; t++) {
        const int c = cstart + t * 32;
        if (t + 1 < NC) {
            issueKV((t + 1) & 1, c + 32);
            asm volatile("cp.async.commit_group;" ::: "memory");
            asm volatile("cp.async.wait_group 1;" ::: "memory");
        } else {
            asm volatile("cp.async.wait_group 0;" ::: "memory");
        }
        __syncthreads();

        if (t == 0) {
            int arow = (lane & 7) + 8 * ((lane >> 3) & 1);
            int achsel = lane >> 4;
            #pragma unroll
            for (int mt = 0; mt < 2; mt++) {
                int row = mBase + mt * 16 + arow;
                #pragma unroll
                for (int kk = 0; kk < 4; kk++) {
                    int chunk = kk * 2 + achsel;
                    uint32_t ad = (uint32_t)(row * 128 + ((chunk ^ (row & 7)) << 4));
                    ldsm4(Qhi[mt][kk][0], Qhi[mt][kk][1], Qhi[mt][kk][2], Qhi[mt][kk][3], QH + ad);
                    ldsm4(Qlo[mt][kk][0], Qlo[mt][kk][1], Qlo[mt][kk][2], Qlo[mt][kk][3], QL + ad);
                }
            }
        }

        if (c + 31 >= warpLo && c <= warpHi) {
            const uint32_t KB = sb + 32768 + (t & 1) * 16384;
            const int* msk = mskbuf + (t & 1) * 32;

            float S[2][4][4];
            #pragma unroll
            for (int mt = 0; mt < 2; mt++)
                #pragma unroll
                for (int j = 0; j < 4; j++)
                    #pragma unroll
                    for (int r = 0; r < 4; r++) S[mt][j][r] = 0.0f;

            #pragma unroll
            for (int j = 0; j < 4; j++) {
                uint32_t kh[4][2], kl[4][2];
                int krow = j * 8 + (lane & 7);
                #pragma unroll
                for (int h32 = 0; h32 < 2; h32++) {
                    int chunk = h32 * 4 + (lane >> 3);
                    uint32_t ad = (uint32_t)(krow * 128 + ((chunk ^ (krow & 7)) << 4));
                    uint32_t r0, r1, r2, r3;
                    ldsm4(r0, r1, r2, r3, KB + ad);
                    kh[h32 * 2][0] = r0; kh[h32 * 2][1] = r1;
                    kh[h32 * 2 + 1][0] = r2; kh[h32 * 2 + 1][1] = r3;
                    ldsm4(r0, r1, r2, r3, KB + 4096 + ad);
                    kl[h32 * 2][0] = r0; kl[h32 * 2][1] = r1;
                    kl[h32 * 2 + 1][0] = r2; kl[h32 * 2 + 1][1] = r3;
                }
                #pragma unroll
                for (int kk = 0; kk < 4; kk++)
                    #pragma unroll
                    for (int mt = 0; mt < 2; mt++) {
                        float* s = S[mt][j];
                        mma_bf16(s[0], s[1], s[2], s[3],
                                 Qhi[mt][kk][0], Qhi[mt][kk][1], Qhi[mt][kk][2], Qhi[mt][kk][3],
                                 kh[kk][0], kh[kk][1]);
                        mma_bf16(s[0], s[1], s[2], s[3],
                                 Qhi[mt][kk][0], Qhi[mt][kk][1], Qhi[mt][kk][2], Qhi[mt][kk][3],
                                 kl[kk][0], kl[kk][1]);
                        mma_bf16(s[0], s[1], s[2], s[3],
                                 Qlo[mt][kk][0], Qlo[mt][kk][1], Qlo[mt][kk][2], Qlo[mt][kk][3],
                                 kh[kk][0], kh[kk][1]);
                    }
            }

            float p[2][4][4];
            #pragma unroll
            for (int mt = 0; mt < 2; mt++) {
                int rA = q0 + mBase + mt * 16 + gid;
                int rB = rA + 8;
                float mxA = -1e30f, mxB = -1e30f;
                #pragma unroll
                for (int j = 0; j < 4; j++) {
                    int c0 = c + j * 8 + tig * 2;
                    int c1 = c0 + 1;
                    int mk0 = msk[j * 8 + tig * 2];
                    int mk1 = msk[j * 8 + tig * 2 + 1];
                    bool v00 = mk0 && (c0 >= rA - WIN) && (c0 <= rA + WIN);
                    bool v01 = mk1 && (c1 >= rA - WIN) && (c1 <= rA + WIN);
                    bool v10 = mk0 && (c0 >= rB - WIN) && (c0 <= rB + WIN);
                    bool v11 = mk1 && (c1 >= rB - WIN) && (c1 <= rB + WIN);
                    S[mt][j][0] = v00 ? S[mt][j][0] * 0.125f : -1e30f;
                    S[mt][j][1] = v01 ? S[mt][j][1] * 0.125f : -1e30f;
                    S[mt][j][2] = v10 ? S[mt][j][2] * 0.125f : -1e30f;
                    S[mt][j][3] = v11 ? S[mt][j][3] * 0.125f : -1e30f;
                    mxA = fmaxf(mxA, fmaxf(S[mt][j][0], S[mt][j][1]));
                    mxB = fmaxf(mxB, fmaxf(S[mt][j][2], S[mt][j][3]));
                }
                mxA = fmaxf(mxA, __shfl_xor_sync(0xffffffffu, mxA, 1));
                mxA = fmaxf(mxA, __shfl_xor_sync(0xffffffffu, mxA, 2));
                mxB = fmaxf(mxB, __shfl_xor_sync(0xffffffffu, mxB, 1));
                mxB = fmaxf(mxB, __shfl_xor_sync(0xffffffffu, mxB, 2));
                float mnA = fmaxf(mrow[mt][0], mxA);
                float mnB = fmaxf(mrow[mt][1], mxB);
                float scA = __expf(mrow[mt][0] - mnA);
                float scB = __expf(mrow[mt][1] - mnB);
                mrow[mt][0] = mnA; mrow[mt][1] = mnB;
                float sA = 0.0f, sB = 0.0f;
                #pragma unroll
                for (int j = 0; j < 4; j++) {
                    float p0 = (S[mt][j][0] > -1e29f) ? __expf(S[mt][j][0] - mnA) : 0.0f;
                    float p1 = (S[mt][j][1] > -1e29f) ? __expf(S[mt][j][1] - mnA) : 0.0f;
                    float p2 = (S[mt][j][2] > -1e29f) ? __expf(S[mt][j][2] - mnB) : 0.0f;
                    float p3 = (S[mt][j][3] > -1e29f) ? __expf(S[mt][j][3] - mnB) : 0.0f;
                    p[mt][j][0] = p0; p[mt][j][1] = p1; p[mt][j][2] = p2; p[mt][j][3] = p3;
                    sA += p0 + p1; sB += p2 + p3;
                }
                sA += __shfl_xor_sync(0xffffffffu, sA, 1);
                sA += __shfl_xor_sync(0xffffffffu, sA, 2);
                sB += __shfl_xor_sync(0xffffffffu, sB, 1);
                sB += __shfl_xor_sync(0xffffffffu, sB, 2);
                lrow[mt][0] = lrow[mt][0] * scA + sA;
                lrow[mt][1] = lrow[mt][1] * scB + sB;
                #pragma unroll
                for (int dj = 0; dj < 8; dj++) {
                    O[mt][dj][0] *= scA; O[mt][dj][1] *= scA;
                    O[mt][dj][2] *= scB; O[mt][dj][3] *= scB;
                }
            }

            uint32_t Phi[2][2][4], Plo[2][2][4];
            #pragma unroll
            for (int mt = 0; mt < 2; mt++)
                #pragma unroll
                for (int kk = 0; kk < 2; kk++) {
                    #pragma unroll
                    for (int q = 0; q < 4; q++) {
                        int j = 2 * kk + (q >> 1);
                        int r0 = (q & 1) * 2;
                        float x0 = p[mt][j][r0], x1 = p[mt][j][r0 + 1];
                        __nv_bfloat162 hh = __floats2bfloat162_rn(x0, x1);
                        Phi[mt][kk][q] = *(uint32_t*)&hh;
                        Plo[mt][kk][q] = pack_bf16x2(x0 - __bfloat162float(hh.x),
                                                     x1 - __bfloat162float(hh.y));
                    }
                }

            #pragma unroll
            for (int djp = 0; djp < 4; djp++) {
                #pragma unroll
                for (int kk = 0; kk < 2; kk++) {
                    int vrow = kk * 16 + (lane & 7) + 8 * ((lane >> 3) & 1);
                    int chunk = djp * 2 + (lane >> 4);
                    uint32_t ad = (uint32_t)(vrow * 128 + ((chunk ^ (vrow & 7)) << 4));
                    uint32_t h0, h1, h2, h3, l0, l1, l2, l3;
                    ldsm4t(h0, h1, h2, h3, KB + 8192 + ad);
                    ldsm4t(l0, l1, l2, l3, KB + 12288 + ad);
                    #pragma unroll
                    for (int mt = 0; mt < 2; mt++) {
                        float* o0 = O[mt][djp * 2];
                        float* o1 = O[mt][djp * 2 + 1];
                        mma_bf16(o0[0], o0[1], o0[2], o0[3],
                                 Phi[mt][kk][0], Phi[mt][kk][1], Phi[mt][kk][2], Phi[mt][kk][3],
                                 h0, h1);
                        mma_bf16(o0[0], o0[1], o0[2], o0[3],
                                 Plo[mt][kk][0], Plo[mt][kk][1], Plo[mt][kk][2], Plo[mt][kk][3],
                                 h0, h1);
                        mma_bf16(o0[0], o0[1], o0[2], o0[3],
                                 Phi[mt][kk][0], Phi[mt][kk][1], Phi[mt][kk][2], Phi[mt][kk][3],
                                 l0, l1);
                        mma_bf16(o1[0], o1[1], o1[2], o1[3],
                                 Phi[mt][kk][0], Phi[mt][kk][1], Phi[mt][kk][2], Phi[mt][kk][3],
                                 h2, h3);
                        mma_bf16(o1[0], o1[1], o1[2], o1[3],
                                 Plo[mt][kk][0], Plo[mt][kk][1], Plo[mt][kk][2], Plo[mt][kk][3],
                                 h2, h3);
                        mma_bf16(o1[0], o1[1], o1[2], o1[3],
                                 Phi[mt][kk][0], Phi[mt][kk][1], Phi[mt][kk][2], Phi[mt][kk][3],
                                 l2, l3);
                    }
                }
            }
        }
        __syncthreads();   // WAR guard: buffer t&1 is overwritten at iteration t+1
    }

    #pragma unroll
    for (int mt = 0; mt < 2; mt++) {
        float invA = (lrow[mt][0] > 0.0f) ? (1.0f / lrow[mt][0]) : 0.0f;
        float invB = (lrow[mt][1] > 0.0f) ? (1.0f / lrow[mt][1]) : 0.0f;
        int rA = q0 + mBase + mt * 16 + gid;
        int rB = rA + 8;
        #pragma unroll
        for (int dj = 0; dj < 8; dj++) {
            int col = h * 64 + dj * 8 + tig * 2;
            float v0 = O[mt][dj][0] * invA, v1 = O[mt][dj][1] * invA;
            float v2 = O[mt][dj][2] * invB, v3 = O[mt][dj][3] * invB;
            size_t iA = ((size_t)rA * DIM + col) >> 1;
            size_t iB = ((size_t)rB * DIM + col) >> 1;
            __nv_bfloat162 hA = __floats2bfloat162_rn(v0, v1);
            __nv_bfloat162 hB = __floats2bfloat162_rn(v2, v3);
            ((uint32_t*)oh)[iA] = *(uint32_t*)&hA;
            ((uint32_t*)oh)[iB] = *(uint32_t*)&hB;
            ((uint32_t*)ol)[iA] = pack_bf16x2(v0 - __bfloat162float(hA.x),
                                              v1 - __bfloat162float(hA.y));
            ((uint32_t*)ol)[iB] = pack_bf16x2(v2 - __bfloat162float(hB.x),
                                              v3 - __bfloat162float(hB.y));
        }
    }
}

// ---------------- classification heads (768 -> 512 relu -> nout) ------------
__global__ void head_kernel(const float* __restrict__ x, const float* __restrict__ W1,
                            const float* __restrict__ b1, const float* __restrict__ W2,
                            const float* __restrict__ b2, float* __restrict__ out, int nout) {
    __shared__ float xs[768];
    __shared__ float hsm[512];
    int t = threadIdx.x;
    for (int i = t; i < 768; i += 512) xs[i] = x[i];
    __syncthreads();
    float acc = b1[t];
    for (int kk = 0; kk < 768; kk++) acc += xs[kk] * W1[(size_t)kk * 512 + t];
    hsm[t] = fmaxf(acc, 0.0f);
    __syncthreads();
    if (t < nout) {
        float ov = b2[t];
        for (int kk = 0; kk < 512; kk++) ov += hsm[kk] * W2[(size_t)kk * nout + t];
        out[t] = ov;
    }
}

// ---------------- host launcher ---------------------------------------------
extern "C" void kernel_launch(void* const* d_in, const int* in_sizes, int n_in,
                              void* d_out, int out_size) {
    const int*   ids      = (const int*)d_in[0];
    const int*   mask     = (const int*)d_in[1];
    const float* emb_word = (const float*)d_in[2];
    const float* emb_pos  = (const float*)d_in[3];
    const float* emb_type = (const float*)d_in[4];
    const float* emb_g    = (const float*)d_in[5];
    const float* emb_b    = (const float*)d_in[6];
    const float* Wq = (const float*)d_in[7];
    const float* bq = (const float*)d_in[8];
    const float* Wk = (const float*)d_in[9];
    const float* bk = (const float*)d_in[10];
    const float* Wv = (const float*)d_in[11];
    const float* bv = (const float*)d_in[12];
    const float* Wo = (const float*)d_in[13];
    const float* bo = (const float*)d_in[14];
    const float* ln1g = (const float*)d_in[15];
    const float* ln1b = (const float*)d_in[16];
    const float* W1 = (const float*)d_in[17];
    const float* b1 = (const float*)d_in[18];
    const float* W2 = (const float*)d_in[19];
    const float* b2 = (const float*)d_in[20];
    const float* ln2g = (const float*)d_in[21];
    const float* ln2b = (const float*)d_in[22];
    const float* cW1 = (const float*)d_in[23];
    const float* cb1 = (const float*)d_in[24];
    const float* cW2 = (const float*)d_in[25];
    const float* cb2 = (const float*)d_in[26];
    const float* dW1 = (const float*)d_in[27];
    const float* db1 = (const float*)d_in[28];
    const float* dW2 = (const float*)d_in[29];
    const float* db2 = (const float*)d_in[30];
    float* out = (float*)d_out;

    float *x, *t, *bcat;
    int* pos;
    __nv_bfloat16 *xh, *xl, *qkvh, *qkvl, *ah, *al, *hh, *hl;
    __nv_bfloat16 *wqh, *wql, *w1h, *w1l, *w2h, *w2l, *woh, *wol;
    cudaGetSymbolAddress((void**)&x, g_x);
    cudaGetSymbolAddress((void**)&t, g_t);
    cudaGetSymbolAddress((void**)&bcat, g_bcat);
    cudaGetSymbolAddress((void**)&pos, g_pos);
    cudaGetSymbolAddress((void**)&xh, g_xh);
    cudaGetSymbolAddress((void**)&xl, g_xl);
    cudaGetSymbolAddress((void**)&qkvh, g_qkvh);
    cudaGetSymbolAddress((void**)&qkvl, g_qkvl);
    cudaGetSymbolAddress((void**)&ah, g_ah);
    cudaGetSymbolAddress((void**)&al, g_al);
    cudaGetSymbolAddress((void**)&hh, g_hh);
    cudaGetSymbolAddress((void**)&hl, g_hl);
    cudaGetSymbolAddress((void**)&wqh, g_wqh);
    cudaGetSymbolAddress((void**)&wql, g_wql);
    cudaGetSymbolAddress((void**)&w1h, g_w1h);
    cudaGetSymbolAddress((void**)&w1l, g_w1l);
    cudaGetSymbolAddress((void**)&w2h, g_w2h);
    cudaGetSymbolAddress((void**)&w2l, g_w2l);
    cudaGetSymbolAddress((void**)&woh, g_woh);
    cudaGetSymbolAddress((void**)&wol, g_wol);

    const int SM128 = 2 * (2 * 128 * 64 + 16384);   // 65536
    const int SM64  = 2 * (2 * 64 * 64 + 16384);    // 49152
    cudaFuncSetAttribute(tgemm_kernel<128, 3>, cudaFuncAttributeMaxDynamicSharedMemorySize, SM128);
    cudaFuncSetAttribute(tgemm_kernel<128, 2>, cudaFuncAttributeMaxDynamicSharedMemorySize, SM128);
    cudaFuncSetAttribute(tgemm_kernel<64, 0>, cudaFuncAttributeMaxDynamicSharedMemorySize, SM64);
    cudaFuncSetAttribute(attn_mma_kernel, cudaFuncAttributeMaxDynamicSharedMemorySize, ATT_SMEM);

    pos_kernel<<<1, 1024>>>(mask, pos);
    embed_ln_kernel<<<SEQ, 256>>>(ids, pos, emb_word, emb_pos, emb_type, emb_g, emb_b, x, xh, xl);

    dim3 gqkv(3 * DIM / 128, SEQ / 128);   // (18, 32)
    dim3 go(DIM / 128, SEQ / 64);          // (6, 64) BM=64
    dim3 gff1(FFD / 128, SEQ / 128);       // (24, 32)
    dim3 gff2(DIM / 128, SEQ / 64);        // (6, 64) BM=64
    dim3 gattn(SEQ / 128, NH);
    int cgrid = (DIM * DIM / 4 + 255) / 256;

    for (int i = 0; i < NL; i++) {
        const float* wq = Wq + (size_t)i * DIM * DIM;
        const float* wk = Wk + (size_t)i * DIM * DIM;
        const float* wv = Wv + (size_t)i * DIM * DIM;
        const float* wo = Wo + (size_t)i * DIM * DIM;
        const float* w1 = W1 + (size_t)i * DIM * FFD;
        const float* w2 = W2 + (size_t)i * FFD * DIM;

        concat_qkv_kernel<<<cgrid, 256>>>(wq, wk, wv, bq + i * DIM, bk + i * DIM, bv + i * DIM,
                                          wqh, wql, bcat);
        split_kernel<<<(DIM * FFD / 4 + 255) / 256, 256>>>(w1, w1h, w1l, DIM * FFD / 4);
        split_kernel<<<(FFD * DIM / 4 + 255) / 256, 256>>>(w2, w2h, w2l, FFD * DIM / 4);
        split_kernel<<<(DIM * DIM / 4 + 255) / 256, 256>>>(wo, woh, wol, DIM * DIM / 4);

        tgemm_kernel<128, 3><<<gqkv, 256, SM128>>>(xh, xl, wqh, wql, bcat, nullptr, qkvh, qkvl,
                                                   SEQ, 3 * DIM, DIM);
        attn_mma_kernel<<<gattn, 128, ATT_SMEM>>>(qkvh, qkvl, mask, ah, al);
        tgemm_kernel<64, 0><<<go, 256, SM64>>>(ah, al, woh, wol, bo + i * DIM, t, nullptr, nullptr,
                                               SEQ, DIM, DIM);
        lnres_kernel<<<SEQ, 256>>>(x, t, ln1g + i * DIM, ln1b + i * DIM, xh, xl);
        tgemm_kernel<128, 2><<<gff1, 256, SM128>>>(xh, xl, w1h, w1l, b1 + i * FFD, nullptr,
                                                   hh, hl, SEQ, FFD, DIM);
        tgemm_kernel<64, 0><<<gff2, 256, SM64>>>(hh, hl, w2h, w2l, b2 + i * DIM, t,
                                                 nullptr, nullptr, SEQ, DIM, FFD);
        lnres_kernel<<<SEQ, 256>>>(x, t, ln2g + i * DIM, ln2b + i * DIM, xh, xl);
    }

    head_kernel<<<1, 512>>>(x, cW1, cb1, cW2, cb2, out, 5);
    head_kernel<<<1, 512>>>(x, dW1, db1, dW2, db2, out + 5, 10);
}

// round 13
// speedup vs baseline: 1.0060x; 1.0060x over previous
#include <cuda_runtime.h>
#include <cuda_bf16.h>
#include <stdint.h>
#include <math.h>

#define SEQ 4096
#define DIM 768
#define NH  12
#define HD  64
#define NL  12
#define FFD 3072
#define WIN 256
#define EPSF 1e-5f

// ---------------- scratch (static device globals; no runtime allocation) ----
__device__ float g_x[SEQ * DIM];
__device__ float g_t[SEQ * DIM];
__device__ float g_t2[SEQ * DIM];
__device__ float g_bcat[3 * DIM];
__device__ int   g_pos[SEQ];

__device__ __nv_bfloat16 g_xh[SEQ * DIM],  g_xl[SEQ * DIM];
__device__ __nv_bfloat16 g_qkvh[SEQ * 3 * DIM], g_qkvl[SEQ * 3 * DIM];
__device__ __nv_bfloat16 g_ah[SEQ * DIM],  g_al[SEQ * DIM];
__device__ __nv_bfloat16 g_hh[SEQ * FFD],  g_hl[SEQ * FFD];
__device__ __nv_bfloat16 g_wqh[DIM * 3 * DIM], g_wql[DIM * 3 * DIM];
__device__ __nv_bfloat16 g_w1h[DIM * FFD], g_w1l[DIM * FFD];
__device__ __nv_bfloat16 g_w2h[FFD * DIM], g_w2l[FFD * DIM];
__device__ __nv_bfloat16 g_woh[DIM * DIM], g_wol[DIM * DIM];

// ---------------- helpers ---------------------------------------------------
__device__ __forceinline__ float gelu_exact(float x) {
    return 0.5f * x * (1.0f + erff(x * 0.70710678118654752f));
}

__device__ __forceinline__ uint32_t pack_bf16x2(float x, float y) {
    __nv_bfloat162 h = __floats2bfloat162_rn(x, y);
    return *(uint32_t*)&h;
}

__device__ __forceinline__ void mma_bf16(float& d0, float& d1, float& d2, float& d3,
                                         uint32_t a0, uint32_t a1, uint32_t a2, uint32_t a3,
                                         uint32_t b0, uint32_t b1) {
    asm volatile("mma.sync.aligned.m16n8k16.row.col.f32.bf16.bf16.f32 "
                 "{%0,%1,%2,%3}, {%4,%5,%6,%7}, {%8,%9}, {%0,%1,%2,%3};"
                 : "+f"(d0), "+f"(d1), "+f"(d2), "+f"(d3)
                 : "r"(a0), "r"(a1), "r"(a2), "r"(a3), "r"(b0), "r"(b1));
}

__device__ __forceinline__ void ldsm4(uint32_t& r0, uint32_t& r1, uint32_t& r2, uint32_t& r3,
                                      uint32_t addr) {
    asm volatile("ldmatrix.sync.aligned.m8n8.x4.shared.b16 {%0,%1,%2,%3}, [%4];"
                 : "=r"(r0), "=r"(r1), "=r"(r2), "=r"(r3) : "r"(addr));
}

__device__ __forceinline__ void ldsm4t(uint32_t& r0, uint32_t& r1, uint32_t& r2, uint32_t& r3,
                                       uint32_t addr) {
    asm volatile("ldmatrix.sync.aligned.m8n8.x4.trans.shared.b16 {%0,%1,%2,%3}, [%4];"
                 : "=r"(r0), "=r"(r1), "=r"(r2), "=r"(r3) : "r"(addr));
}

__device__ __forceinline__ void cp16(uint32_t saddr, const void* gaddr) {
    asm volatile("cp.async.cg.shared.global [%0], [%1], 16;" :: "r"(saddr), "l"(gaddr));
}

__device__ __forceinline__ float blk_sum256(float v, float* red) {
    #pragma unroll
    for (int o = 16; o > 0; o >>= 1) v += __shfl_down_sync(0xffffffffu, v, o);
    int w = threadIdx.x >> 5;
    if ((threadIdx.x & 31) == 0) red[w] = v;
    __syncthreads();
    if (threadIdx.x < 32) {
        v = (threadIdx.x < 8) ? red[threadIdx.x] : 0.0f;
        #pragma unroll
        for (int o = 4; o > 0; o >>= 1) v += __shfl_down_sync(0xffffffffu, v, o);
        if (threadIdx.x == 0) red[0] = v;
    }
    __syncthreads();
    float r = red[0];
    __syncthreads();
    return r;
}

// ---------------- pos_ids = cumsum(mask)*mask + 1 ---------------------------
__global__ void pos_kernel(const int* __restrict__ mask, int* __restrict__ pos) {
    __shared__ int ss[1024];
    int t = threadIdx.x;
    int m0 = mask[t * 4 + 0], m1 = mask[t * 4 + 1];
    int m2 = mask[t * 4 + 2], m3 = mask[t * 4 + 3];
    int s = m0 + m1 + m2 + m3;
    ss[t] = s;
    __syncthreads();
    for (int off = 1; off < 1024; off <<= 1) {
        int vprev = (t >= off) ? ss[t - off] : 0;
        __syncthreads();
        ss[t] += vprev;
        __syncthreads();
    }
    int run = ss[t] - s;
    run += m0; pos[t * 4 + 0] = run * m0 + 1;
    run += m1; pos[t * 4 + 1] = run * m1 + 1;
    run += m2; pos[t * 4 + 2] = run * m2 + 1;
    run += m3; pos[t * 4 + 3] = run * m3 + 1;
}

// ---------------- embedding + layernorm (writes f32 + bf16 hi/lo) -----------
__global__ void embed_ln_kernel(const int* __restrict__ ids, const int* __restrict__ pos,
                                const float* __restrict__ ew, const float* __restrict__ ep,
                                const float* __restrict__ et, const float* __restrict__ g,
                                const float* __restrict__ b, float* __restrict__ x,
                                __nv_bfloat16* __restrict__ xh, __nv_bfloat16* __restrict__ xl) {
    __shared__ float red[32];
    int srow = blockIdx.x;
    int t = threadIdx.x;
    int wid = ids[srow];
    int pid = pos[srow];
    float val[3];
    #pragma unroll
    for (int r = 0; r < 3; r++) {
        int i = t + r * 256;
        val[r] = ew[(size_t)wid * DIM + i] + ep[(size_t)pid * DIM + i] + et[i];
    }
    float mu = blk_sum256(val[0] + val[1] + val[2], red) * (1.0f / DIM);
    float vs = 0.0f;
    #pragma unroll
    for (int r = 0; r < 3; r++) { float d = val[r] - mu; vs += d * d; }
    float var = blk_sum256(vs, red) * (1.0f / DIM);
    float rs = rsqrtf(var + EPSF);
    #pragma unroll
    for (int r = 0; r < 3; r++) {
        int i = t + r * 256;
        float y = (val[r] - mu) * rs * g[i] + b[i];
        size_t idx = (size_t)srow * DIM + i;
        x[idx] = y;
        __nv_bfloat16 h = __float2bfloat16_rn(y);
        xh[idx] = h;
        xl[idx] = __float2bfloat16_rn(y - __bfloat162float(h));
    }
}

// ---------------- x = LN(x + d1 + d2), writes f32 + bf16 hi/lo ---------------
__global__ void lnres_kernel(float* __restrict__ x, const float* __restrict__ d1,
                             const float* __restrict__ d2,
                             const float* __restrict__ g, const float* __restrict__ b,
                             __nv_bfloat16* __restrict__ xh, __nv_bfloat16* __restrict__ xl) {
    __shared__ float red[32];
    int srow = blockIdx.x;
    int t = threadIdx.x;
    float val[3];
    #pragma unroll
    for (int r = 0; r < 3; r++) {
        int i = t + r * 256;
        size_t idx = (size_t)srow * DIM + i;
        val[r] = x[idx] + d1[idx] + d2[idx];
    }
    float mu = blk_sum256(val[0] + val[1] + val[2], red) * (1.0f / DIM);
    float vs = 0.0f;
    #pragma unroll
    for (int r = 0; r < 3; r++) { float d = val[r] - mu; vs += d * d; }
    float var = blk_sum256(vs, red) * (1.0f / DIM);
    float rs = rsqrtf(var + EPSF);
    #pragma unroll
    for (int r = 0; r < 3; r++) {
        int i = t + r * 256;
        float y = (val[r] - mu) * rs * g[i] + b[i];
        size_t idx = (size_t)srow * DIM + i;
        x[idx] = y;
        __nv_bfloat16 h = __float2bfloat16_rn(y);
        xh[idx] = h;
        xl[idx] = __float2bfloat16_rn(y - __bfloat162float(h));
    }
}

// ---------------- generic f32 -> bf16 hi/lo split -----------------------------
__global__ void split_kernel(const float* __restrict__ s, __nv_bfloat16* __restrict__ hi,
                             __nv_bfloat16* __restrict__ lo, int n4) {
    int i = blockIdx.x * blockDim.x + threadIdx.x;
    if (i >= n4) return;
    float4 v = ((const float4*)s)[i];
    __nv_bfloat16 h0 = __float2bfloat16_rn(v.x), h1 = __float2bfloat16_rn(v.y);
    __nv_bfloat16 h2 = __float2bfloat16_rn(v.z), h3 = __float2bfloat16_rn(v.w);
    uint2 hp, lp;
    hp.x = ((uint32_t)*(uint16_t*)&h0) | ((uint32_t)*(uint16_t*)&h1 << 16);
    hp.y = ((uint32_t)*(uint16_t*)&h2) | ((uint32_t)*(uint16_t*)&h3 << 16);
    lp.x = pack_bf16x2(v.x - __bfloat162float(h0), v.y - __bfloat162float(h1));
    lp.y = pack_bf16x2(v.z - __bfloat162float(h2), v.w - __bfloat162float(h3));
    ((uint2*)hi)[i] = hp;
    ((uint2*)lo)[i] = lp;
}

// ---------------- concat QKV weights (split to bf16) + bias ------------------
__global__ void concat_qkv_kernel(const float* __restrict__ Wq, const float* __restrict__ Wk,
                                  const float* __restrict__ Wv, const float* __restrict__ bq,
                                  const float* __restrict__ bk, const float* __restrict__ bv,
                                  __nv_bfloat16* __restrict__ Wh, __nv_bfloat16* __restrict__ Wl,
                                  float* __restrict__ bc) {
    int i4 = blockIdx.x * blockDim.x + threadIdx.x;
    if (i4 < DIM * DIM / 4) {
        int k = i4 / (DIM / 4);
        int n4 = i4 % (DIM / 4);
        const float* srcs[3] = {Wq, Wk, Wv};
        #pragma unroll
        for (int s = 0; s < 3; s++) {
            float4 v = ((const float4*)srcs[s])[i4];
            __nv_bfloat16 h0 = __float2bfloat16_rn(v.x), h1 = __float2bfloat16_rn(v.y);
            __nv_bfloat16 h2 = __float2bfloat16_rn(v.z), h3 = __float2bfloat16_rn(v.w);
            uint2 hp, lp;
            hp.x = ((uint32_t)*(uint16_t*)&h0) | ((uint32_t)*(uint16_t*)&h1 << 16);
            hp.y = ((uint32_t)*(uint16_t*)&h2) | ((uint32_t)*(uint16_t*)&h3 << 16);
            lp.x = pack_bf16x2(v.x - __bfloat162float(h0), v.y - __bfloat162float(h1));
            lp.y = pack_bf16x2(v.z - __bfloat162float(h2), v.w - __bfloat162float(h3));
            int e = k * 3 * DIM + s * DIM + n4 * 4;
            ((uint2*)Wh)[e >> 2] = hp;
            ((uint2*)Wl)[e >> 2] = lp;
        }
    }
    if (i4 < DIM / 4) {
        ((float4*)bc)[i4] = ((const float4*)bq)[i4];
        ((float4*)(bc + DIM))[i4] = ((const float4*)bk)[i4];
        ((float4*)(bc + 2 * DIM))[i4] = ((const float4*)bv)[i4];
    }
}

// ---------------- bf16x3 tensor-core GEMM (BK=32, cp.async, split-K) ---------
// K here is total reduction dim; gridDim.z splits it. lda = A row stride.
// z=0 adds bias and writes C; z=1 writes partial to C2 (bias 0).
// OUT=0: f32 + bias.  OUT=2: gelu -> bf16 hi/lo.  OUT=3: -> bf16 hi/lo.
template <int BM, int OUT>
__global__ __launch_bounds__(256) void tgemm_kernel(
    const __nv_bfloat16* __restrict__ Ah, const __nv_bfloat16* __restrict__ Al,
    const __nv_bfloat16* __restrict__ Bh, const __nv_bfloat16* __restrict__ Bl,
    const float* __restrict__ bias, float* __restrict__ C, float* __restrict__ C2,
    __nv_bfloat16* __restrict__ Chi, __nv_bfloat16* __restrict__ Clo,
    int M, int N, int K, int lda) {
    constexpr int MT = BM / 64;
    constexpr int OFF_AL = BM * 64;
    constexpr int OFF_BH = 2 * BM * 64;
    constexpr int OFF_BL = 2 * BM * 64 + 8192;
    constexpr int STAGE  = 2 * BM * 64 + 16384;
    constexpr int AITERS = BM * 4 / 256;

    extern __shared__ __align__(16) unsigned char smem_raw[];
    uint32_t smemb = (uint32_t)__cvta_generic_to_shared(smem_raw);

    const int bx = blockIdx.x;
    const int by = blockIdx.y;
    const int Klocal = K / gridDim.z;
    const int kbase = blockIdx.z * Klocal;
    const int tid = threadIdx.x;
    const int lane = tid & 31;
    const int wid = tid >> 5;
    const int warpM = wid & 3;
    const int warpN = wid >> 2;
    const int gid = lane >> 2;
    const int tig = lane & 3;
    const int mBase = warpM * 16 * MT;
    const int nBase = warpN * 64;
    const int rowbase = by * BM;
    const int colbase = bx * 128;

    float acc[MT][8][4];
    #pragma unroll
    for (int mt = 0; mt < MT; mt++)
        #pragma unroll
        for (int nt = 0; nt < 8; nt++)
            #pragma unroll
            for (int r = 0; r < 4; r++) acc[mt][nt][r] = 0.0f;

    auto issue = [&](int st, int k0) {
        uint32_t sb = smemb + st * STAGE;
        #pragma unroll
        for (int it = 0; it < AITERS; it++) {
            int idx = tid + it * 256;
            int r = idx >> 2, ch = idx & 3;
            size_t go = (size_t)(rowbase + r) * lda + kbase + k0 + ch * 8;
            uint32_t so = (uint32_t)(r * 64 + ((ch ^ ((r >> 1) & 3)) << 4));
            cp16(sb + so, Ah + go);
            cp16(sb + OFF_AL + so, Al + go);
        }
        #pragma unroll
        for (int it = 0; it < 2; it++) {
            int idx = tid + it * 256;
            int krow = idx >> 4, ch = idx & 15;
            size_t go = (size_t)(kbase + k0 + krow) * N + colbase + ch * 8;
            uint32_t so = (uint32_t)(krow * 256 + ((ch ^ (krow & 7)) << 4));
            cp16(sb + OFF_BH + so, Bh + go);
            cp16(sb + OFF_BL + so, Bl + go);
        }
    };

    const int KT = Klocal >> 5;
    issue(0, 0);
    asm volatile("cp.async.commit_group;" ::: "memory");

    const int lane15 = lane & 15;
    const int laneh = lane >> 4;
    const int bk = lane & 15;
    const int bs = (lane >> 4) & 1;

    for (int t = 0; t < KT; t++) {
        if (t + 1 < KT) {
            issue((t + 1) & 1, (t + 1) * 32);
            asm volatile("cp.async.commit_group;" ::: "memory");
            asm volatile("cp.async.wait_group 1;" ::: "memory");
        } else {
            asm volatile("cp.async.wait_group 0;" ::: "memory");
        }
        __syncthreads();

        uint32_t sb = smemb + (t & 1) * STAGE;
        #pragma unroll
        for (int kk = 0; kk < 2; kk++) {
            uint32_t aHi[MT][4], aLo[MT][4];
            #pragma unroll
            for (int mt = 0; mt < MT; mt++) {
                int row = mBase + mt * 16 + lane15;
                int ch = (kk * 2 + laneh) ^ ((row >> 1) & 3);
                uint32_t ad = sb + (uint32_t)(row * 64 + (ch << 4));
                ldsm4(aHi[mt][0], aHi[mt][1], aHi[mt][2], aHi[mt][3], ad);
                ldsm4(aLo[mt][0], aLo[mt][1], aLo[mt][2], aLo[mt][3], ad + OFF_AL);
            }
            int krow = kk * 16 + bk;
            uint32_t bRow = sb + OFF_BH + (uint32_t)(krow * 256);
            #pragma unroll
            for (int nt2 = 0; nt2 < 4; nt2++) {
                uint32_t ch = (uint32_t)((((warpN * 8 + nt2 * 2 + bs) ^ (bk & 7))) * 16);
                uint32_t bh0, bh1, bh2, bh3, bl0, bl1, bl2, bl3;
                ldsm4t(bh0, bh1, bh2, bh3, bRow + ch);
                ldsm4t(bl0, bl1, bl2, bl3, bRow + (OFF_BL - OFF_BH) + ch);
                #pragma unroll
                for (int mt = 0; mt < MT; mt++) {
                    float* a0 = acc[mt][nt2 * 2];
                    mma_bf16(a0[0], a0[1], a0[2], a0[3],
                             aHi[mt][0], aHi[mt][1], aHi[mt][2], aHi[mt][3], bh0, bh1);
                    mma_bf16(a0[0], a0[1], a0[2], a0[3],
                             aHi[mt][0], aHi[mt][1], aHi[mt][2], aHi[mt][3], bl0, bl1);
                    mma_bf16(a0[0], a0[1], a0[2], a0[3],
                             aLo[mt][0], aLo[mt][1], aLo[mt][2], aLo[mt][3], bh0, bh1);
                    float* a1 = acc[mt][nt2 * 2 + 1];
                    mma_bf16(a1[0], a1[1], a1[2], a1[3],
                             aHi[mt][0], aHi[mt][1], aHi[mt][2], aHi[mt][3], bh2, bh3);
                    mma_bf16(a1[0], a1[1], a1[2], a1[3],
                             aHi[mt][0], aHi[mt][1], aHi[mt][2], aHi[mt][3], bl2, bl3);
                    mma_bf16(a1[0], a1[1], a1[2], a1[3],
                             aLo[mt][0], aLo[mt][1], aLo[mt][2], aLo[mt][3], bh2, bh3);
                }
            }
        }
        __syncthreads();
    }

    float* Cout = (blockIdx.z == 0) ? C : C2;
    const bool addb = (blockIdx.z == 0);
    #pragma unroll
    for (int nt = 0; nt < 8; nt++) {
        int col = colbase + nBase + nt * 8 + tig * 2;
        float b0 = addb ? bias[col] : 0.0f;
        float b1 = addb ? bias[col + 1] : 0.0f;
        #pragma unroll
        for (int mt = 0; mt < MT; mt++) {
            int row0 = rowbase + mBase + mt * 16 + gid;
            float v0 = acc[mt][nt][0] + b0;
            float v1 = acc[mt][nt][1] + b1;
            float v2 = acc[mt][nt][2] + b0;
            float v3 = acc[mt][nt][3] + b1;
            if (OUT == 0) {
                *(float2*)(Cout + (size_t)row0 * N + col) = make_float2(v0, v1);
                *(float2*)(Cout + (size_t)(row0 + 8) * N + col) = make_float2(v2, v3);
            } else {
                if (OUT == 2) {
                    v0 = gelu_exact(v0); v1 = gelu_exact(v1);
                    v2 = gelu_exact(v2); v3 = gelu_exact(v3);
                }
                size_t i0 = ((size_t)row0 * N + col) >> 1;
                size_t i1 = ((size_t)(row0 + 8) * N + col) >> 1;
                __nv_bfloat16 h0 = __float2bfloat16_rn(v0), h1 = __float2bfloat16_rn(v1);
                __nv_bfloat16 h2 = __float2bfloat16_rn(v2), h3 = __float2bfloat16_rn(v3);
                ((uint32_t*)Chi)[i0] = ((uint32_t)*(uint16_t*)&h0) | ((uint32_t)*(uint16_t*)&h1 << 16);
                ((uint32_t*)Chi)[i1] = ((uint32_t)*(uint16_t*)&h2) | ((uint32_t)*(uint16_t*)&h3 << 16);
                ((uint32_t*)Clo)[i0] = pack_bf16x2(v0 - __bfloat162float(h0), v1 - __bfloat162float(h1));
                ((uint32_t*)Clo)[i1] = pack_bf16x2(v2 - __bfloat162float(h2), v3 - __bfloat162float(h3));
            }
        }
    }
}

// ---------------- tensor-core sliding-window flash attention ------------------
#define ATT_SMEM (65536 + 256)
__global__ __launch_bounds__(128) void attn_mma_kernel(
    const __nv_bfloat16* __restrict__ qkvh, const __nv_bfloat16* __restrict__ qkvl,
    const int* __restrict__ mask,
    __nv_bfloat16* __restrict__ oh, __nv_bfloat16* __restrict__ ol) {
    extern __shared__ __align__(16) unsigned char asmem[];
    const uint32_t sb = (uint32_t)__cvta_generic_to_shared(asmem);
    const uint32_t QH = sb, QL = sb + 16384;
    int* mskbuf = (int*)(asmem + 65536);

    const int h = blockIdx.y;
    const int q0 = blockIdx.x * 128;
    const int tid = threadIdx.x, lane = tid & 31, wid = tid >> 5;
    const int gid = lane >> 2, tig = lane & 3;
    const int mBase = wid * 32;
    const int STR = 3 * DIM;
    const int NC = (128 + 2 * WIN) / 32;

    auto issueKV = [&](int st, int c) {
        uint32_t kb = sb + 32768 + st * 16384;
        #pragma unroll
        for (int i = 0; i < 2; i++) {
            int idx = tid + i * 128;
            int row = idx >> 3, ch = idx & 7;
            int kp = c + row;
            int kc = kp < 0 ? 0 : (kp >= SEQ ? SEQ - 1 : kp);
            size_t gk = (size_t)kc * STR + DIM + h * 64 + ch * 8;
            size_t gv = (size_t)kc * STR + 2 * DIM + h * 64 + ch * 8;
            uint32_t so = (uint32_t)(row * 128 + ((ch ^ (row & 7)) << 4));
            cp16(kb + so, qkvh + gk);
            cp16(kb + 4096 + so, qkvl + gk);
            cp16(kb + 8192 + so, qkvh + gv);
            cp16(kb + 12288 + so, qkvl + gv);
        }
        if (tid < 32) {
            int kp = c + tid;
            mskbuf[st * 32 + tid] = (kp >= 0 && kp < SEQ) ? mask[kp] : 0;
        }
    };

    #pragma unroll
    for (int i = 0; i < 8; i++) {
        int idx = tid + i * 128;
        int row = idx >> 3, ch = idx & 7;
        size_t gq = (size_t)(q0 + row) * STR + h * 64 + ch * 8;
        uint32_t so = (uint32_t)(row * 128 + ((ch ^ (row & 7)) << 4));
        cp16(QH + so, qkvh + gq);
        cp16(QL + so, qkvl + gq);
    }
    const int cstart = q0 - WIN;
    issueKV(0, cstart);
    asm volatile("cp.async.commit_group;" ::: "memory");

    uint32_t Qhi[2][4][4], Qlo[2][4][4];
    float O[2][8][4];
    #pragma unroll
    for (int mt = 0; mt < 2; mt++)
        #pragma unroll
        for (int dj = 0; dj < 8; dj++)
            #pragma unroll
            for (int r = 0; r < 4; r++) O[mt][dj][r] = 0.0f;
    float mrow[2][2] = {{-1e30f, -1e30f}, {-1e30f, -1e30f}};
    float lrow[2][2] = {{0.0f, 0.0f}, {0.0f, 0.0f}};

    const int warpLo = q0 + mBase - WIN;
    const int warpHi = q0 + mBase + 31 + WIN;

    for (int t = 0; t < NC; t++) {
        const int c = cstart + t * 32;
        if (t + 1 < NC) {
            issueKV((t + 1) & 1, c + 32);
            asm volatile("cp.async.commit_group;" ::: "memory");
            asm volatile("cp.async.wait_group 1;" ::: "memory");
        } else {
            asm volatile("cp.async.wait_group 0;" ::: "memory");
        }
        __syncthreads();

        if (t == 0) {
            int arow = (lane & 7) + 8 * ((lane >> 3) & 1);
            int achsel = lane >> 4;
            #pragma unroll
            for (int mt = 0; mt < 2; mt++) {
                int row = mBase + mt * 16 + arow;
                #pragma unroll
                for (int kk = 0; kk < 4; kk++) {
                    int chunk = kk * 2 + achsel;
                    uint32_t ad = (uint32_t)(row * 128 + ((chunk ^ (row & 7)) << 4));
                    ldsm4(Qhi[mt][kk][0], Qhi[mt][kk][1], Qhi[mt][kk][2], Qhi[mt][kk][3], QH + ad);
                    ldsm4(Qlo[mt][kk][0], Qlo[mt][kk][1], Qlo[mt][kk][2], Qlo[mt][kk][3], QL + ad);
                }
            }
        }

        if (c + 31 >= warpLo && c <= warpHi) {
            const uint32_t KB = sb + 32768 + (t & 1) * 16384;
            const int* msk = mskbuf + (t & 1) * 32;

            float S[2][4][4];
            #pragma unroll
            for (int mt = 0; mt < 2; mt++)
                #pragma unroll
                for (int j = 0; j < 4; j++)
                    #pragma unroll
                    for (int r = 0; r < 4; r++) S[mt][j][r] = 0.0f;

            #pragma unroll
            for (int j = 0; j < 4; j++) {
                uint32_t kh[4][2], kl[4][2];
                int krow = j * 8 + (lane & 7);
                #pragma unroll
                for (int h32 = 0; h32 < 2; h32++) {
                    int chunk = h32 * 4 + (lane >> 3);
                    uint32_t ad = (uint32_t)(krow * 128 + ((chunk ^ (krow & 7)) << 4));
                    uint32_t r0, r1, r2, r3;
                    ldsm4(r0, r1, r2, r3, KB + ad);
                    kh[h32 * 2][0] = r0; kh[h32 * 2][1] = r1;
                    kh[h32 * 2 + 1][0] = r2; kh[h32 * 2 + 1][1] = r3;
                    ldsm4(r0, r1, r2, r3, KB + 4096 + ad);
                    kl[h32 * 2][0] = r0; kl[h32 * 2][1] = r1;
                    kl[h32 * 2 + 1][0] = r2; kl[h32 * 2 + 1][1] = r3;
                }
                #pragma unroll
                for (int kk = 0; kk < 4; kk++)
                    #pragma unroll
                    for (int mt = 0; mt < 2; mt++) {
                        float* s = S[mt][j];
                        mma_bf16(s[0], s[1], s[2], s[3],
                                 Qhi[mt][kk][0], Qhi[mt][kk][1], Qhi[mt][kk][2], Qhi[mt][kk][3],
                                 kh[kk][0], kh[kk][1]);
                        mma_bf16(s[0], s[1], s[2], s[3],
                                 Qhi[mt][kk][0], Qhi[mt][kk][1], Qhi[mt][kk][2], Qhi[mt][kk][3],
                                 kl[kk][0], kl[kk][1]);
                        mma_bf16(s[0], s[1], s[2], s[3],
                                 Qlo[mt][kk][0], Qlo[mt][kk][1], Qlo[mt][kk][2], Qlo[mt][kk][3],
                                 kh[kk][0], kh[kk][1]);
                    }
            }

            float p[2][4][4];
            #pragma unroll
            for (int mt = 0; mt < 2; mt++) {
                int rA = q0 + mBase + mt * 16 + gid;
                int rB = rA + 8;
                float mxA = -1e30f, mxB = -1e30f;
                #pragma unroll
                for (int j = 0; j < 4; j++) {
                    int c0 = c + j * 8 + tig * 2;
                    int c1 = c0 + 1;
                    int mk0 = msk[j * 8 + tig * 2];
                    int mk1 = msk[j * 8 + tig * 2 + 1];
                    bool v00 = mk0 && (c0 >= rA - WIN) && (c0 <= rA + WIN);
                    bool v01 = mk1 && (c1 >= rA - WIN) && (c1 <= rA + WIN);
                    bool v10 = mk0 && (c0 >= rB - WIN) && (c0 <= rB + WIN);
                    bool v11 = mk1 && (c1 >= rB - WIN) && (c1 <= rB + WIN);
                    S[mt][j][0] = v00 ? S[mt][j][0] * 0.125f : -1e30f;
                    S[mt][j][1] = v01 ? S[mt][j][1] * 0.125f : -1e30f;
                    S[mt][j][2] = v10 ? S[mt][j][2] * 0.125f : -1e30f;
                    S[mt][j][3] = v11 ? S[mt][j][3] * 0.125f : -1e30f;
                    mxA = fmaxf(mxA, fmaxf(S[mt][j][0], S[mt][j][1]));
                    mxB = fmaxf(mxB, fmaxf(S[mt][j][2], S[mt][j][3]));
                }
                mxA = fmaxf(mxA, __shfl_xor_sync(0xffffffffu, mxA, 1));
                mxA = fmaxf(mxA, __shfl_xor_sync(0xffffffffu, mxA, 2));
                mxB = fmaxf(mxB, __shfl_xor_sync(0xffffffffu, mxB, 1));
                mxB = fmaxf(mxB, __shfl_xor_sync(0xffffffffu, mxB, 2));
                float mnA = fmaxf(mrow[mt][0], mxA);
                float mnB = fmaxf(mrow[mt][1], mxB);
                float scA = __expf(mrow[mt][0] - mnA);
                float scB = __expf(mrow[mt][1] - mnB);
                mrow[mt][0] = mnA; mrow[mt][1] = mnB;
                float sA = 0.0f, sB = 0.0f;
                #pragma unroll
                for (int j = 0; j < 4; j++) {
                    float p0 = (S[mt][j][0] > -1e29f) ? __expf(S[mt][j][0] - mnA) : 0.0f;
                    float p1 = (S[mt][j][1] > -1e29f) ? __expf(S[mt][j][1] - mnA) : 0.0f;
                    float p2 = (S[mt][j][2] > -1e29f) ? __expf(S[mt][j][2] - mnB) : 0.0f;
                    float p3 = (S[mt][j][3] > -1e29f) ? __expf(S[mt][j][3] - mnB) : 0.0f;
                    p[mt][j][0] = p0; p[mt][j][1] = p1; p[mt][j][2] = p2; p[mt][j][3] = p3;
                    sA += p0 + p1; sB += p2 + p3;
                }
                sA += __shfl_xor_sync(0xffffffffu, sA, 1);
                sA += __shfl_xor_sync(0xffffffffu, sA, 2);
                sB += __shfl_xor_sync(0xffffffffu, sB, 1);
                sB += __shfl_xor_sync(0xffffffffu, sB, 2);
                lrow[mt][0] = lrow[mt][0] * scA + sA;
                lrow[mt][1] = lrow[mt][1] * scB + sB;
                #pragma unroll
                for (int dj = 0; dj < 8; dj++) {
                    O[mt][dj][0] *= scA; O[mt][dj][1] *= scA;
                    O[mt][dj][2] *= scB; O[mt][dj][3] *= scB;
                }
            }

            uint32_t Phi[2][2][4], Plo[2][2][4];
            #pragma unroll
            for (int mt = 0; mt < 2; mt++)
                #pragma unroll
                for (int kk = 0; kk < 2; kk++) {
                    #pragma unroll
                    for (int q = 0; q < 4; q++) {
                        int j = 2 * kk + (q >> 1);
                        int r0 = (q & 1) * 2;
                        float x0 = p[mt][j][r0], x1 = p[mt][j][r0 + 1];
                        __nv_bfloat162 hh = __floats2bfloat162_rn(x0, x1);
                        Phi[mt][kk][q] = *(uint32_t*)&hh;
                        Plo[mt][kk][q] = pack_bf16x2(x0 - __bfloat162float(hh.x),
                                                     x1 - __bfloat162float(hh.y));
                    }
                }

            #pragma unroll
            for (int djp = 0; djp < 4; djp++) {
                #pragma unroll
                for (int kk = 0; kk < 2; kk++) {
                    int vrow = kk * 16 + (lane & 7) + 8 * ((lane >> 3) & 1);
                    int chunk = djp * 2 + (lane >> 4);
                    uint32_t ad = (uint32_t)(vrow * 128 + ((chunk ^ (vrow & 7)) << 4));
                    uint32_t h0, h1, h2, h3, l0, l1, l2, l3;
                    ldsm4t(h0, h1, h2, h3, KB + 8192 + ad);
                    ldsm4t(l0, l1, l2, l3, KB + 12288 + ad);
                    #pragma unroll
                    for (int mt = 0; mt < 2; mt++) {
                        float* o0 = O[mt][djp * 2];
                        float* o1 = O[mt][djp * 2 + 1];
                        mma_bf16(o0[0], o0[1], o0[2], o0[3],
                                 Phi[mt][kk][0], Phi[mt][kk][1], Phi[mt][kk][2], Phi[mt][kk][3],
                                 h0, h1);
                        mma_bf16(o0[0], o0[1], o0[2], o0[3],
                                 Plo[mt][kk][0], Plo[mt][kk][1], Plo[mt][kk][2], Plo[mt][kk][3],
                                 h0, h1);
                        mma_bf16(o0[0], o0[1], o0[2], o0[3],
                                 Phi[mt][kk][0], Phi[mt][kk][1], Phi[mt][kk][2], Phi[mt][kk][3],
                                 l0, l1);
                        mma_bf16(o1[0], o1[1], o1[2], o1[3],
                                 Phi[mt][kk][0], Phi[mt][kk][1], Phi[mt][kk][2], Phi[mt][kk][3],
                                 h2, h3);
                        mma_bf16(o1[0], o1[1], o1[2], o1[3],
                                 Plo[mt][kk][0], Plo[mt][kk][1], Plo[mt][kk][2], Plo[mt][kk][3],
                                 h2, h3);
                        mma_bf16(o1[0], o1[1], o1[2], o1[3],
                                 Phi[mt][kk][0], Phi[mt][kk][1], Phi[mt][kk][2], Phi[mt][kk][3],
                                 l2, l3);
                    }
                }
            }
        }
        __syncthreads();   // WAR guard
    }

    #pragma unroll
    for (int mt = 0; mt < 2; mt++) {
        float invA = (lrow[mt][0] > 0.0f) ? (1.0f / lrow[mt][0]) : 0.0f;
        float invB = (lrow[mt][1] > 0.0f) ? (1.0f / lrow[mt][1]) : 0.0f;
        int rA = q0 + mBase + mt * 16 + gid;
        int rB = rA + 8;
        #pragma unroll
        for (int dj = 0; dj < 8; dj++) {
            int col = h * 64 + dj * 8 + tig * 2;
            float v0 = O[mt][dj][0] * invA, v1 = O[mt][dj][1] * invA;
            float v2 = O[mt][dj][2] * invB, v3 = O[mt][dj][3] * invB;
            size_t iA = ((size_t)rA * DIM + col) >> 1;
            size_t iB = ((size_t)rB * DIM + col) >> 1;
            __nv_bfloat162 hA = __floats2bfloat162_rn(v0, v1);
            __nv_bfloat162 hB = __floats2bfloat162_rn(v2, v3);
            ((uint32_t*)oh)[iA] = *(uint32_t*)&hA;
            ((uint32_t*)oh)[iB] = *(uint32_t*)&hB;
            ((uint32_t*)ol)[iA] = pack_bf16x2(v0 - __bfloat162float(hA.x),
                                              v1 - __bfloat162float(hA.y));
            ((uint32_t*)ol)[iB] = pack_bf16x2(v2 - __bfloat162float(hB.x),
                                              v3 - __bfloat162float(hB.y));
        }
    }
}

// ---------------- classification heads (768 -> 512 relu -> nout) ------------
__global__ void head_kernel(const float* __restrict__ x, const float* __restrict__ W1,
                            const float* __restrict__ b1, const float* __restrict__ W2,
                            const float* __restrict__ b2, float* __restrict__ out, int nout) {
    __shared__ float xs[768];
    __shared__ float hsm[512];
    int t = threadIdx.x;
    for (int i = t; i < 768; i += 512) xs[i] = x[i];
    __syncthreads();
    float acc = b1[t];
    for (int kk = 0; kk < 768; kk++) acc += xs[kk] * W1[(size_t)kk * 512 + t];
    hsm[t] = fmaxf(acc, 0.0f);
    __syncthreads();
    if (t < nout) {
        float ov = b2[t];
        for (int kk = 0; kk < 512; kk++) ov += hsm[kk] * W2[(size_t)kk * nout + t];
        out[t] = ov;
    }
}

// ---------------- host launcher ---------------------------------------------
extern "C" void kernel_launch(void* const* d_in, const int* in_sizes, int n_in,
                              void* d_out, int out_size) {
    const int*   ids      = (const int*)d_in[0];
    const int*   mask     = (const int*)d_in[1];
    const float* emb_word = (const float*)d_in[2];
    const float* emb_pos  = (const float*)d_in[3];
    const float* emb_type = (const float*)d_in[4];
    const float* emb_g    = (const float*)d_in[5];
    const float* emb_b    = (const float*)d_in[6];
    const float* Wq = (const float*)d_in[7];
    const float* bq = (const float*)d_in[8];
    const float* Wk = (const float*)d_in[9];
    const float* bk = (const float*)d_in[10];
    const float* Wv = (const float*)d_in[11];
    const float* bv = (const float*)d_in[12];
    const float* Wo = (const float*)d_in[13];
    const float* bo = (const float*)d_in[14];
    const float* ln1g = (const float*)d_in[15];
    const float* ln1b = (const float*)d_in[16];
    const float* W1 = (const float*)d_in[17];
    const float* b1 = (const float*)d_in[18];
    const float* W2 = (const float*)d_in[19];
    const float* b2 = (const float*)d_in[20];
    const float* ln2g = (const float*)d_in[21];
    const float* ln2b = (const float*)d_in[22];
    const float* cW1 = (const float*)d_in[23];
    const float* cb1 = (const float*)d_in[24];
    const float* cW2 = (const float*)d_in[25];
    const float* cb2 = (const float*)d_in[26];
    const float* dW1 = (const float*)d_in[27];
    const float* db1 = (const float*)d_in[28];
    const float* dW2 = (const float*)d_in[29];
    const float* db2 = (const float*)d_in[30];
    float* out = (float*)d_out;

    float *x, *t, *t2, *bcat;
    int* pos;
    __nv_bfloat16 *xh, *xl, *qkvh, *qkvl, *ah, *al, *hh, *hl;
    __nv_bfloat16 *wqh, *wql, *w1h, *w1l, *w2h, *w2l, *woh, *wol;
    cudaGetSymbolAddress((void**)&x, g_x);
    cudaGetSymbolAddress((void**)&t, g_t);
    cudaGetSymbolAddress((void**)&t2, g_t2);
    cudaGetSymbolAddress((void**)&bcat, g_bcat);
    cudaGetSymbolAddress((void**)&pos, g_pos);
    cudaGetSymbolAddress((void**)&xh, g_xh);
    cudaGetSymbolAddress((void**)&xl, g_xl);
    cudaGetSymbolAddress((void**)&qkvh, g_qkvh);
    cudaGetSymbolAddress((void**)&qkvl, g_qkvl);
    cudaGetSymbolAddress((void**)&ah, g_ah);
    cudaGetSymbolAddress((void**)&al, g_al);
    cudaGetSymbolAddress((void**)&hh, g_hh);
    cudaGetSymbolAddress((void**)&hl, g_hl);
    cudaGetSymbolAddress((void**)&wqh, g_wqh);
    cudaGetSymbolAddress((void**)&wql, g_wql);
    cudaGetSymbolAddress((void**)&w1h, g_w1h);
    cudaGetSymbolAddress((void**)&w1l, g_w1l);
    cudaGetSymbolAddress((void**)&w2h, g_w2h);
    cudaGetSymbolAddress((void**)&w2l, g_w2l);
    cudaGetSymbolAddress((void**)&woh, g_woh);
    cudaGetSymbolAddress((void**)&wol, g_wol);

    const int SM128 = 2 * (2 * 128 * 64 + 16384);   // 65536
    const int SM64  = 2 * (2 * 64 * 64 + 16384);    // 49152
    cudaFuncSetAttribute(tgemm_kernel<128, 3>, cudaFuncAttributeMaxDynamicSharedMemorySize, SM128);
    cudaFuncSetAttribute(tgemm_kernel<128, 2>, cudaFuncAttributeMaxDynamicSharedMemorySize, SM128);
    cudaFuncSetAttribute(tgemm_kernel<64, 0>, cudaFuncAttributeMaxDynamicSharedMemorySize, SM64);
    cudaFuncSetAttribute(attn_mma_kernel, cudaFuncAttributeMaxDynamicSharedMemorySize, ATT_SMEM);

    pos_kernel<<<1, 1024>>>(mask, pos);
    embed_ln_kernel<<<SEQ, 256>>>(ids, pos, emb_word, emb_pos, emb_type, emb_g, emb_b, x, xh, xl);

    dim3 gqkv(3 * DIM / 128, SEQ / 128, 1);   // (18, 32)
    dim3 go(DIM / 128, SEQ / 64, 2);          // (6, 64, 2) split-K
    dim3 gff1(FFD / 128, SEQ / 128, 1);       // (24, 32)
    dim3 gff2(DIM / 128, SEQ / 64, 2);        // (6, 64, 2) split-K
    dim3 gattn(SEQ / 128, NH);
    int cgrid = (DIM * DIM / 4 + 255) / 256;

    for (int i = 0; i < NL; i++) {
        const float* wq = Wq + (size_t)i * DIM * DIM;
        const float* wk = Wk + (size_t)i * DIM * DIM;
        const float* wv = Wv + (size_t)i * DIM * DIM;
        const float* wo = Wo + (size_t)i * DIM * DIM;
        const float* w1 = W1 + (size_t)i * DIM * FFD;
        const float* w2 = W2 + (size_t)i * FFD * DIM;

        concat_qkv_kernel<<<cgrid, 256>>>(wq, wk, wv, bq + i * DIM, bk + i * DIM, bv + i * DIM,
                                          wqh, wql, bcat);
        split_kernel<<<(DIM * FFD / 4 + 255) / 256, 256>>>(w1, w1h, w1l, DIM * FFD / 4);
        split_kernel<<<(FFD * DIM / 4 + 255) / 256, 256>>>(w2, w2h, w2l, FFD * DIM / 4);
        split_kernel<<<(DIM * DIM / 4 + 255) / 256, 256>>>(wo, woh, wol, DIM * DIM / 4);

        tgemm_kernel<128, 3><<<gqkv, 256, SM128>>>(xh, xl, wqh, wql, bcat, nullptr, nullptr,
                                                   qkvh, qkvl, SEQ, 3 * DIM, DIM, DIM);
        attn_mma_kernel<<<gattn, 128, ATT_SMEM>>>(qkvh, qkvl, mask, ah, al);
        tgemm_kernel<64, 0><<<go, 256, SM64>>>(ah, al, woh, wol, bo + i * DIM, t, t2,
                                               nullptr, nullptr, SEQ, DIM, DIM, DIM);
        lnres_kernel<<<SEQ, 256>>>(x, t, t2, ln1g + i * DIM, ln1b + i * DIM, xh, xl);
        tgemm_kernel<128, 2><<<gff1, 256, SM128>>>(xh, xl, w1h, w1l, b1 + i * FFD, nullptr,
                                                   nullptr, hh, hl, SEQ, FFD, DIM, DIM);
        tgemm_kernel<64, 0><<<gff2, 256, SM64>>>(hh, hl, w2h, w2l, b2 + i * DIM, t, t2,
                                                 nullptr, nullptr, SEQ, DIM, FFD, FFD);
        lnres_kernel<<<SEQ, 256>>>(x, t, t2, ln2g + i * DIM, ln2b + i * DIM, xh, xl);
    }

    head_kernel<<<1, 512>>>(x, cW1, cb1, cW2, cb2, out, 5);
    head_kernel<<<1, 512>>>(x, dW1, db1, dW2, db2, out + 5, 10);
}

// round 14
// speedup vs baseline: 1.0159x; 1.0099x over previous
#include <cuda_runtime.h>
#include <cuda_bf16.h>
#include <stdint.h>
#include <math.h>

#define SEQ 4096
#define DIM 768
#define NH  12
#define HD  64
#define NL  12
#define FFD 3072
#define WIN 256
#define EPSF 1e-5f

// ---------------- scratch (static device globals; no runtime allocation) ----
__device__ float g_x[SEQ * DIM];
__device__ float g_t[SEQ * DIM];
__device__ float g_t2[SEQ * DIM];
__device__ float g_bcat[3 * DIM];
__device__ int   g_pos[SEQ];

__device__ __nv_bfloat16 g_xh[SEQ * DIM],  g_xl[SEQ * DIM];
__device__ __nv_bfloat16 g_qkvh[SEQ * 3 * DIM], g_qkvl[SEQ * 3 * DIM];
__device__ __nv_bfloat16 g_ah[SEQ * DIM],  g_al[SEQ * DIM];
__device__ __nv_bfloat16 g_hh[SEQ * FFD],  g_hl[SEQ * FFD];
__device__ __nv_bfloat16 g_wqh[DIM * 3 * DIM], g_wql[DIM * 3 * DIM];
__device__ __nv_bfloat16 g_w1h[DIM * FFD], g_w1l[DIM * FFD];
__device__ __nv_bfloat16 g_w2h[FFD * DIM], g_w2l[FFD * DIM];
__device__ __nv_bfloat16 g_woh[DIM * DIM], g_wol[DIM * DIM];

// ---------------- helpers ---------------------------------------------------
__device__ __forceinline__ float gelu_exact(float x) {
    return 0.5f * x * (1.0f + erff(x * 0.70710678118654752f));
}

__device__ __forceinline__ uint32_t pack_bf16x2(float x, float y) {
    __nv_bfloat162 h = __floats2bfloat162_rn(x, y);
    return *(uint32_t*)&h;
}

__device__ __forceinline__ void mma_bf16(float& d0, float& d1, float& d2, float& d3,
                                         uint32_t a0, uint32_t a1, uint32_t a2, uint32_t a3,
                                         uint32_t b0, uint32_t b1) {
    asm volatile("mma.sync.aligned.m16n8k16.row.col.f32.bf16.bf16.f32 "
                 "{%0,%1,%2,%3}, {%4,%5,%6,%7}, {%8,%9}, {%0,%1,%2,%3};"
                 : "+f"(d0), "+f"(d1), "+f"(d2), "+f"(d3)
                 : "r"(a0), "r"(a1), "r"(a2), "r"(a3), "r"(b0), "r"(b1));
}

__device__ __forceinline__ void ldsm4(uint32_t& r0, uint32_t& r1, uint32_t& r2, uint32_t& r3,
                                      uint32_t addr) {
    asm volatile("ldmatrix.sync.aligned.m8n8.x4.shared.b16 {%0,%1,%2,%3}, [%4];"
                 : "=r"(r0), "=r"(r1), "=r"(r2), "=r"(r3) : "r"(addr));
}

__device__ __forceinline__ void ldsm4t(uint32_t& r0, uint32_t& r1, uint32_t& r2, uint32_t& r3,
                                       uint32_t addr) {
    asm volatile("ldmatrix.sync.aligned.m8n8.x4.trans.shared.b16 {%0,%1,%2,%3}, [%4];"
                 : "=r"(r0), "=r"(r1), "=r"(r2), "=r"(r3) : "r"(addr));
}

__device__ __forceinline__ void cp16(uint32_t saddr, const void* gaddr) {
    asm volatile("cp.async.cg.shared.global [%0], [%1], 16;" :: "r"(saddr), "l"(gaddr));
}

__device__ __forceinline__ float blk_sum256(float v, float* red) {
    #pragma unroll
    for (int o = 16; o > 0; o >>= 1) v += __shfl_down_sync(0xffffffffu, v, o);
    int w = threadIdx.x >> 5;
    if ((threadIdx.x & 31) == 0) red[w] = v;
    __syncthreads();
    if (threadIdx.x < 32) {
        v = (threadIdx.x < 8) ? red[threadIdx.x] : 0.0f;
        #pragma unroll
        for (int o = 4; o > 0; o >>= 1) v += __shfl_down_sync(0xffffffffu, v, o);
        if (threadIdx.x == 0) red[0] = v;
    }
    __syncthreads();
    float r = red[0];
    __syncthreads();
    return r;
}

// ---------------- pos_ids = cumsum(mask)*mask + 1 ---------------------------
__global__ void pos_kernel(const int* __restrict__ mask, int* __restrict__ pos) {
    __shared__ int ss[1024];
    int t = threadIdx.x;
    int m0 = mask[t * 4 + 0], m1 = mask[t * 4 + 1];
    int m2 = mask[t * 4 + 2], m3 = mask[t * 4 + 3];
    int s = m0 + m1 + m2 + m3;
    ss[t] = s;
    __syncthreads();
    for (int off = 1; off < 1024; off <<= 1) {
        int vprev = (t >= off) ? ss[t - off] : 0;
        __syncthreads();
        ss[t] += vprev;
        __syncthreads();
    }
    int run = ss[t] - s;
    run += m0; pos[t * 4 + 0] = run * m0 + 1;
    run += m1; pos[t * 4 + 1] = run * m1 + 1;
    run += m2; pos[t * 4 + 2] = run * m2 + 1;
    run += m3; pos[t * 4 + 3] = run * m3 + 1;
}

// ---------------- embedding + layernorm (writes f32 + bf16 hi/lo) -----------
__global__ void embed_ln_kernel(const int* __restrict__ ids, const int* __restrict__ pos,
                                const float* __restrict__ ew, const float* __restrict__ ep,
                                const float* __restrict__ et, const float* __restrict__ g,
                                const float* __restrict__ b, float* __restrict__ x,
                                __nv_bfloat16* __restrict__ xh, __nv_bfloat16* __restrict__ xl) {
    __shared__ float red[32];
    int srow = blockIdx.x;
    int t = threadIdx.x;
    int wid = ids[srow];
    int pid = pos[srow];
    float val[3];
    #pragma unroll
    for (int r = 0; r < 3; r++) {
        int i = t + r * 256;
        val[r] = ew[(size_t)wid * DIM + i] + ep[(size_t)pid * DIM + i] + et[i];
    }
    float mu = blk_sum256(val[0] + val[1] + val[2], red) * (1.0f / DIM);
    float vs = 0.0f;
    #pragma unroll
    for (int r = 0; r < 3; r++) { float d = val[r] - mu; vs += d * d; }
    float var = blk_sum256(vs, red) * (1.0f / DIM);
    float rs = rsqrtf(var + EPSF);
    #pragma unroll
    for (int r = 0; r < 3; r++) {
        int i = t + r * 256;
        float y = (val[r] - mu) * rs * g[i] + b[i];
        size_t idx = (size_t)srow * DIM + i;
        x[idx] = y;
        __nv_bfloat16 h = __float2bfloat16_rn(y);
        xh[idx] = h;
        xl[idx] = __float2bfloat16_rn(y - __bfloat162float(h));
    }
}

// ---------------- x = LN(x + d1 + d2), writes f32 + bf16 hi/lo ---------------
__global__ void lnres_kernel(float* __restrict__ x, const float* __restrict__ d1,
                             const float* __restrict__ d2,
                             const float* __restrict__ g, const float* __restrict__ b,
                             __nv_bfloat16* __restrict__ xh, __nv_bfloat16* __restrict__ xl) {
    __shared__ float red[32];
    int srow = blockIdx.x;
    int t = threadIdx.x;
    float val[3];
    #pragma unroll
    for (int r = 0; r < 3; r++) {
        int i = t + r * 256;
        size_t idx = (size_t)srow * DIM + i;
        val[r] = x[idx] + d1[idx] + d2[idx];
    }
    float mu = blk_sum256(val[0] + val[1] + val[2], red) * (1.0f / DIM);
    float vs = 0.0f;
    #pragma unroll
    for (int r = 0; r < 3; r++) { float d = val[r] - mu; vs += d * d; }
    float var = blk_sum256(vs, red) * (1.0f / DIM);
    float rs = rsqrtf(var + EPSF);
    #pragma unroll
    for (int r = 0; r < 3; r++) {
        int i = t + r * 256;
        float y = (val[r] - mu) * rs * g[i] + b[i];
        size_t idx = (size_t)srow * DIM + i;
        x[idx] = y;
        __nv_bfloat16 h = __float2bfloat16_rn(y);
        xh[idx] = h;
        xl[idx] = __float2bfloat16_rn(y - __bfloat162float(h));
    }
}

// ---------------- fused weight prep: w1 | w2 | wo | qkv-concat ---------------
// grid regions: [0,2304) w1, [2304,4608) w2, [4608,5184) wo, [5184,5760) qkv.
__device__ __forceinline__ void split4(const float* __restrict__ s,
                                       __nv_bfloat16* __restrict__ hi,
                                       __nv_bfloat16* __restrict__ lo, int i) {
    float4 v = ((const float4*)s)[i];
    __nv_bfloat16 h0 = __float2bfloat16_rn(v.x), h1 = __float2bfloat16_rn(v.y);
    __nv_bfloat16 h2 = __float2bfloat16_rn(v.z), h3 = __float2bfloat16_rn(v.w);
    uint2 hp, lp;
    hp.x = ((uint32_t)*(uint16_t*)&h0) | ((uint32_t)*(uint16_t*)&h1 << 16);
    hp.y = ((uint32_t)*(uint16_t*)&h2) | ((uint32_t)*(uint16_t*)&h3 << 16);
    lp.x = pack_bf16x2(v.x - __bfloat162float(h0), v.y - __bfloat162float(h1));
    lp.y = pack_bf16x2(v.z - __bfloat162float(h2), v.w - __bfloat162float(h3));
    ((uint2*)hi)[i] = hp;
    ((uint2*)lo)[i] = lp;
}

__global__ void prep_kernel(const float* __restrict__ w1, const float* __restrict__ w2,
                            const float* __restrict__ wo,
                            const float* __restrict__ Wq, const float* __restrict__ Wk,
                            const float* __restrict__ Wv, const float* __restrict__ bq,
                            const float* __restrict__ bk, const float* __restrict__ bv,
                            __nv_bfloat16* __restrict__ w1h, __nv_bfloat16* __restrict__ w1l,
                            __nv_bfloat16* __restrict__ w2h, __nv_bfloat16* __restrict__ w2l,
                            __nv_bfloat16* __restrict__ woh, __nv_bfloat16* __restrict__ wol,
                            __nv_bfloat16* __restrict__ Wh, __nv_bfloat16* __restrict__ Wl,
                            float* __restrict__ bc) {
    int b = blockIdx.x;
    int tid = threadIdx.x;
    if (b < 2304) {
        split4(w1, w1h, w1l, b * 256 + tid);
    } else if (b < 4608) {
        split4(w2, w2h, w2l, (b - 2304) * 256 + tid);
    } else if (b < 5184) {
        split4(wo, woh, wol, (b - 4608) * 256 + tid);
    } else {
        int i4 = (b - 5184) * 256 + tid;      // over DIM*DIM/4 = 147456
        int k = i4 / (DIM / 4);
        int n4 = i4 % (DIM / 4);
        const float* srcs[3] = {Wq, Wk, Wv};
        #pragma unroll
        for (int s = 0; s < 3; s++) {
            float4 v = ((const float4*)srcs[s])[i4];
            __nv_bfloat16 h0 = __float2bfloat16_rn(v.x), h1 = __float2bfloat16_rn(v.y);
            __nv_bfloat16 h2 = __float2bfloat16_rn(v.z), h3 = __float2bfloat16_rn(v.w);
            uint2 hp, lp;
            hp.x = ((uint32_t)*(uint16_t*)&h0) | ((uint32_t)*(uint16_t*)&h1 << 16);
            hp.y = ((uint32_t)*(uint16_t*)&h2) | ((uint32_t)*(uint16_t*)&h3 << 16);
            lp.x = pack_bf16x2(v.x - __bfloat162float(h0), v.y - __bfloat162float(h1));
            lp.y = pack_bf16x2(v.z - __bfloat162float(h2), v.w - __bfloat162float(h3));
            int e = k * 3 * DIM + s * DIM + n4 * 4;
            ((uint2*)Wh)[e >> 2] = hp;
            ((uint2*)Wl)[e >> 2] = lp;
        }
        if (i4 < DIM / 4) {
            ((float4*)bc)[i4] = ((const float4*)bq)[i4];
            ((float4*)(bc + DIM))[i4] = ((const float4*)bk)[i4];
            ((float4*)(bc + 2 * DIM))[i4] = ((const float4*)bv)[i4];
        }
    }
}

// ---------------- bf16x3 tensor-core GEMM (BK=32, cp.async, split-K) ---------
// NS = pipeline stages (2 or 3). K total; gridDim.z splits it. lda = A row stride.
// z=0 adds bias -> C; z=1 partial -> C2. OUT=0 f32; OUT=2 gelu->bf16; OUT=3 ->bf16.
template <int BM, int OUT, int NS>
__global__ __launch_bounds__(256) void tgemm_kernel(
    const __nv_bfloat16* __restrict__ Ah, const __nv_bfloat16* __restrict__ Al,
    const __nv_bfloat16* __restrict__ Bh, const __nv_bfloat16* __restrict__ Bl,
    const float* __restrict__ bias, float* __restrict__ C, float* __restrict__ C2,
    __nv_bfloat16* __restrict__ Chi, __nv_bfloat16* __restrict__ Clo,
    int M, int N, int K, int lda) {
    constexpr int MT = BM / 64;
    constexpr int OFF_AL = BM * 64;
    constexpr int OFF_BH = 2 * BM * 64;
    constexpr int OFF_BL = 2 * BM * 64 + 8192;
    constexpr int STAGE  = 2 * BM * 64 + 16384;
    constexpr int AITERS = BM * 4 / 256;

    extern __shared__ __align__(16) unsigned char smem_raw[];
    uint32_t smemb = (uint32_t)__cvta_generic_to_shared(smem_raw);

    const int bx = blockIdx.x;
    const int by = blockIdx.y;
    const int Klocal = K / gridDim.z;
    const int kbase = blockIdx.z * Klocal;
    const int tid = threadIdx.x;
    const int lane = tid & 31;
    const int wid = tid >> 5;
    const int warpM = wid & 3;
    const int warpN = wid >> 2;
    const int gid = lane >> 2;
    const int tig = lane & 3;
    const int mBase = warpM * 16 * MT;
    const int nBase = warpN * 64;
    const int rowbase = by * BM;
    const int colbase = bx * 128;

    float acc[MT][8][4];
    #pragma unroll
    for (int mt = 0; mt < MT; mt++)
        #pragma unroll
        for (int nt = 0; nt < 8; nt++)
            #pragma unroll
            for (int r = 0; r < 4; r++) acc[mt][nt][r] = 0.0f;

    auto issue = [&](int st, int k0) {
        uint32_t sb = smemb + st * STAGE;
        #pragma unroll
        for (int it = 0; it < AITERS; it++) {
            int idx = tid + it * 256;
            int r = idx >> 2, ch = idx & 3;
            size_t go = (size_t)(rowbase + r) * lda + kbase + k0 + ch * 8;
            uint32_t so = (uint32_t)(r * 64 + ((ch ^ ((r >> 1) & 3)) << 4));
            cp16(sb + so, Ah + go);
            cp16(sb + OFF_AL + so, Al + go);
        }
        #pragma unroll
        for (int it = 0; it < 2; it++) {
            int idx = tid + it * 256;
            int krow = idx >> 4, ch = idx & 15;
            size_t go = (size_t)(kbase + k0 + krow) * N + colbase + ch * 8;
            uint32_t so = (uint32_t)(krow * 256 + ((ch ^ (krow & 7)) << 4));
            cp16(sb + OFF_BH + so, Bh + go);
            cp16(sb + OFF_BL + so, Bl + go);
        }
        asm volatile("cp.async.commit_group;" ::: "memory");
    };

    const int KT = Klocal >> 5;
    issue(0, 0);
    if (NS == 3 && KT > 1) issue(1, 32);

    const int lane15 = lane & 15;
    const int laneh = lane >> 4;
    const int bk = lane & 15;
    const int bs = (lane >> 4) & 1;

    for (int t = 0; t < KT; t++) {
        if (NS == 2) {
            if (t + 1 < KT) {
                issue((t + 1) & 1, (t + 1) * 32);
                asm volatile("cp.async.wait_group 1;" ::: "memory");
            } else {
                asm volatile("cp.async.wait_group 0;" ::: "memory");
            }
        } else {
            if (t + 2 < KT) {
                int nb = t + 2;
                nb = nb - (nb / 3) * 3;
                issue(nb, (t + 2) * 32);
            }
            if (t + 3 <= KT) {
                asm volatile("cp.async.wait_group 2;" ::: "memory");
            } else if (t + 2 == KT) {
                asm volatile("cp.async.wait_group 1;" ::: "memory");
            } else {
                asm volatile("cp.async.wait_group 0;" ::: "memory");
            }
        }
        __syncthreads();

        int buf = (NS == 2) ? (t & 1) : (t - (t / 3) * 3);
        uint32_t sb = smemb + buf * STAGE;
        #pragma unroll
        for (int kk = 0; kk < 2; kk++) {
            uint32_t aHi[MT][4], aLo[MT][4];
            #pragma unroll
            for (int mt = 0; mt < MT; mt++) {
                int row = mBase + mt * 16 + lane15;
                int ch = (kk * 2 + laneh) ^ ((row >> 1) & 3);
                uint32_t ad = sb + (uint32_t)(row * 64 + (ch << 4));
                ldsm4(aHi[mt][0], aHi[mt][1], aHi[mt][2], aHi[mt][3], ad);
                ldsm4(aLo[mt][0], aLo[mt][1], aLo[mt][2], aLo[mt][3], ad + OFF_AL);
            }
            int krow = kk * 16 + bk;
            uint32_t bRow = sb + OFF_BH + (uint32_t)(krow * 256);
            #pragma unroll
            for (int nt2 = 0; nt2 < 4; nt2++) {
                uint32_t ch = (uint32_t)((((warpN * 8 + nt2 * 2 + bs) ^ (bk & 7))) * 16);
                uint32_t bh0, bh1, bh2, bh3, bl0, bl1, bl2, bl3;
                ldsm4t(bh0, bh1, bh2, bh3, bRow + ch);
                ldsm4t(bl0, bl1, bl2, bl3, bRow + (OFF_BL - OFF_BH) + ch);
                #pragma unroll
                for (int mt = 0; mt < MT; mt++) {
                    float* a0 = acc[mt][nt2 * 2];
                    mma_bf16(a0[0], a0[1], a0[2], a0[3],
                             aHi[mt][0], aHi[mt][1], aHi[mt][2], aHi[mt][3], bh0, bh1);
                    mma_bf16(a0[0], a0[1], a0[2], a0[3],
                             aHi[mt][0], aHi[mt][1], aHi[mt][2], aHi[mt][3], bl0, bl1);
                    mma_bf16(a0[0], a0[1], a0[2], a0[3],
                             aLo[mt][0], aLo[mt][1], aLo[mt][2], aLo[mt][3], bh0, bh1);
                    float* a1 = acc[mt][nt2 * 2 + 1];
                    mma_bf16(a1[0], a1[1], a1[2], a1[3],
                             aHi[mt][0], aHi[mt][1], aHi[mt][2], aHi[mt][3], bh2, bh3);
                    mma_bf16(a1[0], a1[1], a1[2], a1[3],
                             aHi[mt][0], aHi[mt][1], aHi[mt][2], aHi[mt][3], bl2, bl3);
                    mma_bf16(a1[0], a1[1], a1[2], a1[3],
                             aLo[mt][0], aLo[mt][1], aLo[mt][2], aLo[mt][3], bh2, bh3);
                }
            }
        }
        __syncthreads();
    }

    float* Cout = (blockIdx.z == 0) ? C : C2;
    const bool addb = (blockIdx.z == 0);
    #pragma unroll
    for (int nt = 0; nt < 8; nt++) {
        int col = colbase + nBase + nt * 8 + tig * 2;
        float b0 = addb ? bias[col] : 0.0f;
        float b1 = addb ? bias[col + 1] : 0.0f;
        #pragma unroll
        for (int mt = 0; mt < MT; mt++) {
            int row0 = rowbase + mBase + mt * 16 + gid;
            float v0 = acc[mt][nt][0] + b0;
            float v1 = acc[mt][nt][1] + b1;
            float v2 = acc[mt][nt][2] + b0;
            float v3 = acc[mt][nt][3] + b1;
            if (OUT == 0) {
                *(float2*)(Cout + (size_t)row0 * N + col) = make_float2(v0, v1);
                *(float2*)(Cout + (size_t)(row0 + 8) * N + col) = make_float2(v2, v3);
            } else {
                if (OUT == 2) {
                    v0 = gelu_exact(v0); v1 = gelu_exact(v1);
                    v2 = gelu_exact(v2); v3 = gelu_exact(v3);
                }
                size_t i0 = ((size_t)row0 * N + col) >> 1;
                size_t i1 = ((size_t)(row0 + 8) * N + col) >> 1;
                __nv_bfloat16 h0 = __float2bfloat16_rn(v0), h1 = __float2bfloat16_rn(v1);
                __nv_bfloat16 h2 = __float2bfloat16_rn(v2), h3 = __float2bfloat16_rn(v3);
                ((uint32_t*)Chi)[i0] = ((uint32_t)*(uint16_t*)&h0) | ((uint32_t)*(uint16_t*)&h1 << 16);
                ((uint32_t*)Chi)[i1] = ((uint32_t)*(uint16_t*)&h2) | ((uint32_t)*(uint16_t*)&h3 << 16);
                ((uint32_t*)Clo)[i0] = pack_bf16x2(v0 - __bfloat162float(h0), v1 - __bfloat162float(h1));
                ((uint32_t*)Clo)[i1] = pack_bf16x2(v2 - __bfloat162float(h2), v3 - __bfloat162float(h3));
            }
        }
    }
}

// ---------------- tensor-core sliding-window flash attention ------------------
#define ATT_SMEM (65536 + 256)
__global__ __launch_bounds__(128) void attn_mma_kernel(
    const __nv_bfloat16* __restrict__ qkvh, const __nv_bfloat16* __restrict__ qkvl,
    const int* __restrict__ mask,
    __nv_bfloat16* __restrict__ oh, __nv_bfloat16* __restrict__ ol) {
    extern __shared__ __align__(16) unsigned char asmem[];
    const uint32_t sb = (uint32_t)__cvta_generic_to_shared(asmem);
    const uint32_t QH = sb, QL = sb + 16384;
    int* mskbuf = (int*)(asmem + 65536);

    const int h = blockIdx.y;
    const int q0 = blockIdx.x * 128;
    const int tid = threadIdx.x, lane = tid & 31, wid = tid >> 5;
    const int gid = lane >> 2, tig = lane & 3;
    const int mBase = wid * 32;
    const int STR = 3 * DIM;
    const int NC = (128 + 2 * WIN) / 32;

    auto issueKV = [&](int st, int c) {
        uint32_t kb = sb + 32768 + st * 16384;
        #pragma unroll
        for (int i = 0; i < 2; i++) {
            int idx = tid + i * 128;
            int row = idx >> 3, ch = idx & 7;
            int kp = c + row;
            int kc = kp < 0 ? 0 : (kp >= SEQ ? SEQ - 1 : kp);
            size_t gk = (size_t)kc * STR + DIM + h * 64 + ch * 8;
            size_t gv = (size_t)kc * STR + 2 * DIM + h * 64 + ch * 8;
            uint32_t so = (uint32_t)(row * 128 + ((ch ^ (row & 7)) << 4));
            cp16(kb + so, qkvh + gk);
            cp16(kb + 4096 + so, qkvl + gk);
            cp16(kb + 8192 + so, qkvh + gv);
            cp16(kb + 12288 + so, qkvl + gv);
        }
        if (tid < 32) {
            int kp = c + tid;
            mskbuf[st * 32 + tid] = (kp >= 0 && kp < SEQ) ? mask[kp] : 0;
        }
    };

    #pragma unroll
    for (int i = 0; i < 8; i++) {
        int idx = tid + i * 128;
        int row = idx >> 3, ch = idx & 7;
        size_t gq = (size_t)(q0 + row) * STR + h * 64 + ch * 8;
        uint32_t so = (uint32_t)(row * 128 + ((ch ^ (row & 7)) << 4));
        cp16(QH + so, qkvh + gq);
        cp16(QL + so, qkvl + gq);
    }
    const int cstart = q0 - WIN;
    issueKV(0, cstart);
    asm volatile("cp.async.commit_group;" ::: "memory");

    uint32_t Qhi[2][4][4], Qlo[2][4][4];
    float O[2][8][4];
    #pragma unroll
    for (int mt = 0; mt < 2; mt++)
        #pragma unroll
        for (int dj = 0; dj < 8; dj++)
            #pragma unroll
            for (int r = 0; r < 4; r++) O[mt][dj][r] = 0.0f;
    float mrow[2][2] = {{-1e30f, -1e30f}, {-1e30f, -1e30f}};
    float lrow[2][2] = {{0.0f, 0.0f}, {0.0f, 0.0f}};

    const int warpLo = q0 + mBase - WIN;
    const int warpHi = q0 + mBase + 31 + WIN;

    for (int t = 0; t < NC; t++) {
        const int c = cstart + t * 32;
        if (t + 1 < NC) {
            issueKV((t + 1) & 1, c + 32);
            asm volatile("cp.async.commit_group;" ::: "memory");
            asm volatile("cp.async.wait_group 1;" ::: "memory");
        } else {
            asm volatile("cp.async.wait_group 0;" ::: "memory");
        }
        __syncthreads();

        if (t == 0) {
            int arow = (lane & 7) + 8 * ((lane >> 3) & 1);
            int achsel = lane >> 4;
            #pragma unroll
            for (int mt = 0; mt < 2; mt++) {
                int row = mBase + mt * 16 + arow;
                #pragma unroll
                for (int kk = 0; kk < 4; kk++) {
                    int chunk = kk * 2 + achsel;
                    uint32_t ad = (uint32_t)(row * 128 + ((chunk ^ (row & 7)) << 4));
                    ldsm4(Qhi[mt][kk][0], Qhi[mt][kk][1], Qhi[mt][kk][2], Qhi[mt][kk][3], QH + ad);
                    ldsm4(Qlo[mt][kk][0], Qlo[mt][kk][1], Qlo[mt][kk][2], Qlo[mt][kk][3], QL + ad);
                }
            }
        }

        if (c + 31 >= warpLo && c <= warpHi) {
            const uint32_t KB = sb + 32768 + (t & 1) * 16384;
            const int* msk = mskbuf + (t & 1) * 32;

            float S[2][4][4];
            #pragma unroll
            for (int mt = 0; mt < 2; mt++)
                #pragma unroll
                for (int j = 0; j < 4; j++)
                    #pragma unroll
                    for (int r = 0; r < 4; r++) S[mt][j][r] = 0.0f;

            #pragma unroll
            for (int j = 0; j < 4; j++) {
                uint32_t kh[4][2], kl[4][2];
                int krow = j * 8 + (lane & 7);
                #pragma unroll
                for (int h32 = 0; h32 < 2; h32++) {
                    int chunk = h32 * 4 + (lane >> 3);
                    uint32_t ad = (uint32_t)(krow * 128 + ((chunk ^ (krow & 7)) << 4));
                    uint32_t r0, r1, r2, r3;
                    ldsm4(r0, r1, r2, r3, KB + ad);
                    kh[h32 * 2][0] = r0; kh[h32 * 2][1] = r1;
                    kh[h32 * 2 + 1][0] = r2; kh[h32 * 2 + 1][1] = r3;
                    ldsm4(r0, r1, r2, r3, KB + 4096 + ad);
                    kl[h32 * 2][0] = r0; kl[h32 * 2][1] = r1;
                    kl[h32 * 2 + 1][0] = r2; kl[h32 * 2 + 1][1] = r3;
                }
                #pragma unroll
                for (int kk = 0; kk < 4; kk++)
                    #pragma unroll
                    for (int mt = 0; mt < 2; mt++) {
                        float* s = S[mt][j];
                        mma_bf16(s[0], s[1], s[2], s[3],
                                 Qhi[mt][kk][0], Qhi[mt][kk][1], Qhi[mt][kk][2], Qhi[mt][kk][3],
                                 kh[kk][0], kh[kk][1]);
                        mma_bf16(s[0], s[1], s[2], s[3],
                                 Qhi[mt][kk][0], Qhi[mt][kk][1], Qhi[mt][kk][2], Qhi[mt][kk][3],
                                 kl[kk][0], kl[kk][1]);
                        mma_bf16(s[0], s[1], s[2], s[3],
                                 Qlo[mt][kk][0], Qlo[mt][kk][1], Qlo[mt][kk][2], Qlo[mt][kk][3],
                                 kh[kk][0], kh[kk][1]);
                    }
            }

            float p[2][4][4];
            #pragma unroll
            for (int mt = 0; mt < 2; mt++) {
                int rA = q0 + mBase + mt * 16 + gid;
                int rB = rA + 8;
                float mxA = -1e30f, mxB = -1e30f;
                #pragma unroll
                for (int j = 0; j < 4; j++) {
                    int c0 = c + j * 8 + tig * 2;
                    int c1 = c0 + 1;
                    int mk0 = msk[j * 8 + tig * 2];
                    int mk1 = msk[j * 8 + tig * 2 + 1];
                    bool v00 = mk0 && (c0 >= rA - WIN) && (c0 <= rA + WIN);
                    bool v01 = mk1 && (c1 >= rA - WIN) && (c1 <= rA + WIN);
                    bool v10 = mk0 && (c0 >= rB - WIN) && (c0 <= rB + WIN);
                    bool v11 = mk1 && (c1 >= rB - WIN) && (c1 <= rB + WIN);
                    S[mt][j][0] = v00 ? S[mt][j][0] * 0.125f : -1e30f;
                    S[mt][j][1] = v01 ? S[mt][j][1] * 0.125f : -1e30f;
                    S[mt][j][2] = v10 ? S[mt][j][2] * 0.125f : -1e30f;
                    S[mt][j][3] = v11 ? S[mt][j][3] * 0.125f : -1e30f;
                    mxA = fmaxf(mxA, fmaxf(S[mt][j][0], S[mt][j][1]));
                    mxB = fmaxf(mxB, fmaxf(S[mt][j][2], S[mt][j][3]));
                }
                mxA = fmaxf(mxA, __shfl_xor_sync(0xffffffffu, mxA, 1));
                mxA = fmaxf(mxA, __shfl_xor_sync(0xffffffffu, mxA, 2));
                mxB = fmaxf(mxB, __shfl_xor_sync(0xffffffffu, mxB, 1));
                mxB = fmaxf(mxB, __shfl_xor_sync(0xffffffffu, mxB, 2));
                float mnA = fmaxf(mrow[mt][0], mxA);
                float mnB = fmaxf(mrow[mt][1], mxB);
                float scA = __expf(mrow[mt][0] - mnA);
                float scB = __expf(mrow[mt][1] - mnB);
                mrow[mt][0] = mnA; mrow[mt][1] = mnB;
                float sA = 0.0f, sB = 0.0f;
                #pragma unroll
                for (int j = 0; j < 4; j++) {
                    float p0 = (S[mt][j][0] > -1e29f) ? __expf(S[mt][j][0] - mnA) : 0.0f;
                    float p1 = (S[mt][j][1] > -1e29f) ? __expf(S[mt][j][1] - mnA) : 0.0f;
                    float p2 = (S[mt][j][2] > -1e29f) ? __expf(S[mt][j][2] - mnB) : 0.0f;
                    float p3 = (S[mt][j][3] > -1e29f) ? __expf(S[mt][j][3] - mnB) : 0.0f;
                    p[mt][j][0] = p0; p[mt][j][1] = p1; p[mt][j][2] = p2; p[mt][j][3] = p3;
                    sA += p0 + p1; sB += p2 + p3;
                }
                sA += __shfl_xor_sync(0xffffffffu, sA, 1);
                sA += __shfl_xor_sync(0xffffffffu, sA, 2);
                sB += __shfl_xor_sync(0xffffffffu, sB, 1);
                sB += __shfl_xor_sync(0xffffffffu, sB, 2);
                lrow[mt][0] = lrow[mt][0] * scA + sA;
                lrow[mt][1] = lrow[mt][1] * scB + sB;
                #pragma unroll
                for (int dj = 0; dj < 8; dj++) {
                    O[mt][dj][0] *= scA; O[mt][dj][1] *= scA;
                    O[mt][dj][2] *= scB; O[mt][dj][3] *= scB;
                }
            }

            uint32_t Phi[2][2][4], Plo[2][2][4];
            #pragma unroll
            for (int mt = 0; mt < 2; mt++)
                #pragma unroll
                for (int kk = 0; kk < 2; kk++) {
                    #pragma unroll
                    for (int q = 0; q < 4; q++) {
                        int j = 2 * kk + (q >> 1);
                        int r0 = (q & 1) * 2;
                        float x0 = p[mt][j][r0], x1 = p[mt][j][r0 + 1];
                        __nv_bfloat162 hh = __floats2bfloat162_rn(x0, x1);
                        Phi[mt][kk][q] = *(uint32_t*)&hh;
                        Plo[mt][kk][q] = pack_bf16x2(x0 - __bfloat162float(hh.x),
                                                     x1 - __bfloat162float(hh.y));
                    }
                }

            #pragma unroll
            for (int djp = 0; djp < 4; djp++) {
                #pragma unroll
                for (int kk = 0; kk < 2; kk++) {
                    int vrow = kk * 16 + (lane & 7) + 8 * ((lane >> 3) & 1);
                    int chunk = djp * 2 + (lane >> 4);
                    uint32_t ad = (uint32_t)(vrow * 128 + ((chunk ^ (vrow & 7)) << 4));
                    uint32_t h0, h1, h2, h3, l0, l1, l2, l3;
                    ldsm4t(h0, h1, h2, h3, KB + 8192 + ad);
                    ldsm4t(l0, l1, l2, l3, KB + 12288 + ad);
                    #pragma unroll
                    for (int mt = 0; mt < 2; mt++) {
                        float* o0 = O[mt][djp * 2];
                        float* o1 = O[mt][djp * 2 + 1];
                        mma_bf16(o0[0], o0[1], o0[2], o0[3],
                                 Phi[mt][kk][0], Phi[mt][kk][1], Phi[mt][kk][2], Phi[mt][kk][3],
                                 h0, h1);
                        mma_bf16(o0[0], o0[1], o0[2], o0[3],
                                 Plo[mt][kk][0], Plo[mt][kk][1], Plo[mt][kk][2], Plo[mt][kk][3],
                                 h0, h1);
                        mma_bf16(o0[0], o0[1], o0[2], o0[3],
                                 Phi[mt][kk][0], Phi[mt][kk][1], Phi[mt][kk][2], Phi[mt][kk][3],
                                 l0, l1);
                        mma_bf16(o1[0], o1[1], o1[2], o1[3],
                                 Phi[mt][kk][0], Phi[mt][kk][1], Phi[mt][kk][2], Phi[mt][kk][3],
                                 h2, h3);
                        mma_bf16(o1[0], o1[1], o1[2], o1[3],
                                 Plo[mt][kk][0], Plo[mt][kk][1], Plo[mt][kk][2], Plo[mt][kk][3],
                                 h2, h3);
                        mma_bf16(o1[0], o1[1], o1[2], o1[3],
                                 Phi[mt][kk][0], Phi[mt][kk][1], Phi[mt][kk][2], Phi[mt][kk][3],
                                 l2, l3);
                    }
                }
            }
        }
        __syncthreads();   // WAR guard
    }

    #pragma unroll
    for (int mt = 0; mt < 2; mt++) {
        float invA = (lrow[mt][0] > 0.0f) ? (1.0f / lrow[mt][0]) : 0.0f;
        float invB = (lrow[mt][1] > 0.0f) ? (1.0f / lrow[mt][1]) : 0.0f;
        int rA = q0 + mBase + mt * 16 + gid;
        int rB = rA + 8;
        #pragma unroll
        for (int dj = 0; dj < 8; dj++) {
            int col = h * 64 + dj * 8 + tig * 2;
            float v0 = O[mt][dj][0] * invA, v1 = O[mt][dj][1] * invA;
            float v2 = O[mt][dj][2] * invB, v3 = O[mt][dj][3] * invB;
            size_t iA = ((size_t)rA * DIM + col) >> 1;
            size_t iB = ((size_t)rB * DIM + col) >> 1;
            __nv_bfloat162 hA = __floats2bfloat162_rn(v0, v1);
            __nv_bfloat162 hB = __floats2bfloat162_rn(v2, v3);
            ((uint32_t*)oh)[iA] = *(uint32_t*)&hA;
            ((uint32_t*)oh)[iB] = *(uint32_t*)&hB;
            ((uint32_t*)ol)[iA] = pack_bf16x2(v0 - __bfloat162float(hA.x),
                                              v1 - __bfloat162float(hA.y));
            ((uint32_t*)ol)[iB] = pack_bf16x2(v2 - __bfloat162float(hB.x),
                                              v3 - __bfloat162float(hB.y));
        }
    }
}

// ---------------- classification heads (768 -> 512 relu -> nout) ------------
__global__ void head_kernel(const float* __restrict__ x, const float* __restrict__ W1,
                            const float* __restrict__ b1, const float* __restrict__ W2,
                            const float* __restrict__ b2, float* __restrict__ out, int nout) {
    __shared__ float xs[768];
    __shared__ float hsm[512];
    int t = threadIdx.x;
    for (int i = t; i < 768; i += 512) xs[i] = x[i];
    __syncthreads();
    float acc = b1[t];
    for (int kk = 0; kk < 768; kk++) acc += xs[kk] * W1[(size_t)kk * 512 + t];
    hsm[t] = fmaxf(acc, 0.0f);
    __syncthreads();
    if (t < nout) {
        float ov = b2[t];
        for (int kk = 0; kk < 512; kk++) ov += hsm[kk] * W2[(size_t)kk * nout + t];
        out[t] = ov;
    }
}

// ---------------- host launcher ---------------------------------------------
extern "C" void kernel_launch(void* const* d_in, const int* in_sizes, int n_in,
                              void* d_out, int out_size) {
    const int*   ids      = (const int*)d_in[0];
    const int*   mask     = (const int*)d_in[1];
    const float* emb_word = (const float*)d_in[2];
    const float* emb_pos  = (const float*)d_in[3];
    const float* emb_type = (const float*)d_in[4];
    const float* emb_g    = (const float*)d_in[5];
    const float* emb_b    = (const float*)d_in[6];
    const float* Wq = (const float*)d_in[7];
    const float* bq = (const float*)d_in[8];
    const float* Wk = (const float*)d_in[9];
    const float* bk = (const float*)d_in[10];
    const float* Wv = (const float*)d_in[11];
    const float* bv = (const float*)d_in[12];
    const float* Wo = (const float*)d_in[13];
    const float* bo = (const float*)d_in[14];
    const float* ln1g = (const float*)d_in[15];
    const float* ln1b = (const float*)d_in[16];
    const float* W1 = (const float*)d_in[17];
    const float* b1 = (const float*)d_in[18];
    const float* W2 = (const float*)d_in[19];
    const float* b2 = (const float*)d_in[20];
    const float* ln2g = (const float*)d_in[21];
    const float* ln2b = (const float*)d_in[22];
    const float* cW1 = (const float*)d_in[23];
    const float* cb1 = (const float*)d_in[24];
    const float* cW2 = (const float*)d_in[25];
    const float* cb2 = (const float*)d_in[26];
    const float* dW1 = (const float*)d_in[27];
    const float* db1 = (const float*)d_in[28];
    const float* dW2 = (const float*)d_in[29];
    const float* db2 = (const float*)d_in[30];
    float* out = (float*)d_out;

    float *x, *t, *t2, *bcat;
    int* pos;
    __nv_bfloat16 *xh, *xl, *qkvh, *qkvl, *ah, *al, *hh, *hl;
    __nv_bfloat16 *wqh, *wql, *w1h, *w1l, *w2h, *w2l, *woh, *wol;
    cudaGetSymbolAddress((void**)&x, g_x);
    cudaGetSymbolAddress((void**)&t, g_t);
    cudaGetSymbolAddress((void**)&t2, g_t2);
    cudaGetSymbolAddress((void**)&bcat, g_bcat);
    cudaGetSymbolAddress((void**)&pos, g_pos);
    cudaGetSymbolAddress((void**)&xh, g_xh);
    cudaGetSymbolAddress((void**)&xl, g_xl);
    cudaGetSymbolAddress((void**)&qkvh, g_qkvh);
    cudaGetSymbolAddress((void**)&qkvl, g_qkvl);
    cudaGetSymbolAddress((void**)&ah, g_ah);
    cudaGetSymbolAddress((void**)&al, g_al);
    cudaGetSymbolAddress((void**)&hh, g_hh);
    cudaGetSymbolAddress((void**)&hl, g_hl);
    cudaGetSymbolAddress((void**)&wqh, g_wqh);
    cudaGetSymbolAddress((void**)&wql, g_wql);
    cudaGetSymbolAddress((void**)&w1h, g_w1h);
    cudaGetSymbolAddress((void**)&w1l, g_w1l);
    cudaGetSymbolAddress((void**)&w2h, g_w2h);
    cudaGetSymbolAddress((void**)&w2l, g_w2l);
    cudaGetSymbolAddress((void**)&woh, g_woh);
    cudaGetSymbolAddress((void**)&wol, g_wol);

    const int SM128 = 2 * (2 * 128 * 64 + 16384);   // 65536
    const int SM64  = 3 * (2 * 64 * 64 + 16384);    // 73728 (3-stage)
    cudaFuncSetAttribute(tgemm_kernel<128, 3, 2>, cudaFuncAttributeMaxDynamicSharedMemorySize, SM128);
    cudaFuncSetAttribute(tgemm_kernel<128, 2, 2>, cudaFuncAttributeMaxDynamicSharedMemorySize, SM128);
    cudaFuncSetAttribute(tgemm_kernel<64, 0, 3>, cudaFuncAttributeMaxDynamicSharedMemorySize, SM64);
    cudaFuncSetAttribute(attn_mma_kernel, cudaFuncAttributeMaxDynamicSharedMemorySize, ATT_SMEM);

    pos_kernel<<<1, 1024>>>(mask, pos);
    embed_ln_kernel<<<SEQ, 256>>>(ids, pos, emb_word, emb_pos, emb_type, emb_g, emb_b, x, xh, xl);

    dim3 gqkv(3 * DIM / 128, SEQ / 128, 1);   // (18, 32)
    dim3 go(DIM / 128, SEQ / 64, 2);          // (6, 64, 2) split-K
    dim3 gff1(FFD / 128, SEQ / 128, 1);       // (24, 32)
    dim3 gff2(DIM / 128, SEQ / 64, 2);        // (6, 64, 2) split-K
    dim3 gattn(SEQ / 128, NH);

    for (int i = 0; i < NL; i++) {
        const float* wq = Wq + (size_t)i * DIM * DIM;
        const float* wk = Wk + (size_t)i * DIM * DIM;
        const float* wv = Wv + (size_t)i * DIM * DIM;
        const float* wo = Wo + (size_t)i * DIM * DIM;
        const float* w1 = W1 + (size_t)i * DIM * FFD;
        const float* w2 = W2 + (size_t)i * FFD * DIM;

        prep_kernel<<<5760, 256>>>(w1, w2, wo, wq, wk, wv,
                                   bq + i * DIM, bk + i * DIM, bv + i * DIM,
                                   w1h, w1l, w2h, w2l, woh, wol, wqh, wql, bcat);

        tgemm_kernel<128, 3, 2><<<gqkv, 256, SM128>>>(xh, xl, wqh, wql, bcat, nullptr, nullptr,
                                                      qkvh, qkvl, SEQ, 3 * DIM, DIM, DIM);
        attn_mma_kernel<<<gattn, 128, ATT_SMEM>>>(qkvh, qkvl, mask, ah, al);
        tgemm_kernel<64, 0, 3><<<go, 256, SM64>>>(ah, al, woh, wol, bo + i * DIM, t, t2,
                                                  nullptr, nullptr, SEQ, DIM, DIM, DIM);
        lnres_kernel<<<SEQ, 256>>>(x, t, t2, ln1g + i * DIM, ln1b + i * DIM, xh, xl);
        tgemm_kernel<128, 2, 2><<<gff1, 256, SM128>>>(xh, xl, w1h, w1l, b1 + i * FFD, nullptr,
                                                      nullptr, hh, hl, SEQ, FFD, DIM, DIM);
        tgemm_kernel<64, 0, 3><<<gff2, 256, SM64>>>(hh, hl, w2h, w2l, b2 + i * DIM, t, t2,
                                                    nullptr, nullptr, SEQ, DIM, FFD, FFD);
        lnres_kernel<<<SEQ, 256>>>(x, t, t2, ln2g + i * DIM, ln2b + i * DIM, xh, xl);
    }

    head_kernel<<<1, 512>>>(x, cW1, cb1, cW2, cb2, out, 5);
    head_kernel<<<1, 512>>>(x, dW1, db1, dW2, db2, out + 5, 10);
}

// round 15
// speedup vs baseline: 1.0455x; 1.0291x over previous
#include <cuda_runtime.h>
#include <cuda_bf16.h>
#include <stdint.h>
#include <math.h>

#define SEQ 4096
#define DIM 768
#define NH  12
#define HD  64
#define NL  12
#define FFD 3072
#define WIN 256
#define EPSF 1e-5f

// ---------------- scratch (static device globals; no runtime allocation) ----
__device__ float g_x[SEQ * DIM];
__device__ float g_t[SEQ * DIM];
__device__ float g_t2[SEQ * DIM];
__device__ float g_bcat[3 * DIM];
__device__ int   g_pos[SEQ];

__device__ __nv_bfloat16 g_xh[SEQ * DIM],  g_xl[SEQ * DIM];
__device__ __nv_bfloat16 g_qkvh[SEQ * 3 * DIM], g_qkvl[SEQ * 3 * DIM];
__device__ __nv_bfloat16 g_ah[SEQ * DIM],  g_al[SEQ * DIM];
__device__ __nv_bfloat16 g_hh[SEQ * FFD],  g_hl[SEQ * FFD];
__device__ __nv_bfloat16 g_wqh[DIM * 3 * DIM], g_wql[DIM * 3 * DIM];
__device__ __nv_bfloat16 g_w1h[DIM * FFD], g_w1l[DIM * FFD];
__device__ __nv_bfloat16 g_w2h[FFD * DIM], g_w2l[FFD * DIM];
__device__ __nv_bfloat16 g_woh[DIM * DIM], g_wol[DIM * DIM];

// ---------------- helpers ---------------------------------------------------
__device__ __forceinline__ float gelu_exact(float x) {
    return 0.5f * x * (1.0f + erff(x * 0.70710678118654752f));
}

__device__ __forceinline__ uint32_t pack_bf16x2(float x, float y) {
    __nv_bfloat162 h = __floats2bfloat162_rn(x, y);
    return *(uint32_t*)&h;
}

__device__ __forceinline__ void mma_bf16(float& d0, float& d1, float& d2, float& d3,
                                         uint32_t a0, uint32_t a1, uint32_t a2, uint32_t a3,
                                         uint32_t b0, uint32_t b1) {
    asm volatile("mma.sync.aligned.m16n8k16.row.col.f32.bf16.bf16.f32 "
                 "{%0,%1,%2,%3}, {%4,%5,%6,%7}, {%8,%9}, {%0,%1,%2,%3};"
                 : "+f"(d0), "+f"(d1), "+f"(d2), "+f"(d3)
                 : "r"(a0), "r"(a1), "r"(a2), "r"(a3), "r"(b0), "r"(b1));
}

__device__ __forceinline__ void ldsm4(uint32_t& r0, uint32_t& r1, uint32_t& r2, uint32_t& r3,
                                      uint32_t addr) {
    asm volatile("ldmatrix.sync.aligned.m8n8.x4.shared.b16 {%0,%1,%2,%3}, [%4];"
                 : "=r"(r0), "=r"(r1), "=r"(r2), "=r"(r3) : "r"(addr));
}

__device__ __forceinline__ void ldsm4t(uint32_t& r0, uint32_t& r1, uint32_t& r2, uint32_t& r3,
                                       uint32_t addr) {
    asm volatile("ldmatrix.sync.aligned.m8n8.x4.trans.shared.b16 {%0,%1,%2,%3}, [%4];"
                 : "=r"(r0), "=r"(r1), "=r"(r2), "=r"(r3) : "r"(addr));
}

__device__ __forceinline__ void cp16(uint32_t saddr, const void* gaddr) {
    asm volatile("cp.async.cg.shared.global [%0], [%1], 16;" :: "r"(saddr), "l"(gaddr));
}

__device__ __forceinline__ float blk_sum256(float v, float* red) {
    #pragma unroll
    for (int o = 16; o > 0; o >>= 1) v += __shfl_down_sync(0xffffffffu, v, o);
    int w = threadIdx.x >> 5;
    if ((threadIdx.x & 31) == 0) red[w] = v;
    __syncthreads();
    if (threadIdx.x < 32) {
        v = (threadIdx.x < 8) ? red[threadIdx.x] : 0.0f;
        #pragma unroll
        for (int o = 4; o > 0; o >>= 1) v += __shfl_down_sync(0xffffffffu, v, o);
        if (threadIdx.x == 0) red[0] = v;
    }
    __syncthreads();
    float r = red[0];
    __syncthreads();
    return r;
}

// ---------------- pos_ids = cumsum(mask)*mask + 1 ---------------------------
__global__ void pos_kernel(const int* __restrict__ mask, int* __restrict__ pos) {
    __shared__ int ss[1024];
    int t = threadIdx.x;
    int m0 = mask[t * 4 + 0], m1 = mask[t * 4 + 1];
    int m2 = mask[t * 4 + 2], m3 = mask[t * 4 + 3];
    int s = m0 + m1 + m2 + m3;
    ss[t] = s;
    __syncthreads();
    for (int off = 1; off < 1024; off <<= 1) {
        int vprev = (t >= off) ? ss[t - off] : 0;
        __syncthreads();
        ss[t] += vprev;
        __syncthreads();
    }
    int run = ss[t] - s;
    run += m0; pos[t * 4 + 0] = run * m0 + 1;
    run += m1; pos[t * 4 + 1] = run * m1 + 1;
    run += m2; pos[t * 4 + 2] = run * m2 + 1;
    run += m3; pos[t * 4 + 3] = run * m3 + 1;
}

// ---------------- embedding + layernorm (writes f32 + bf16 hi/lo) -----------
__global__ void embed_ln_kernel(const int* __restrict__ ids, const int* __restrict__ pos,
                                const float* __restrict__ ew, const float* __restrict__ ep,
                                const float* __restrict__ et, const float* __restrict__ g,
                                const float* __restrict__ b, float* __restrict__ x,
                                __nv_bfloat16* __restrict__ xh, __nv_bfloat16* __restrict__ xl) {
    __shared__ float red[32];
    int srow = blockIdx.x;
    int t = threadIdx.x;
    int wid = ids[srow];
    int pid = pos[srow];
    float val[3];
    #pragma unroll
    for (int r = 0; r < 3; r++) {
        int i = t + r * 256;
        val[r] = ew[(size_t)wid * DIM + i] + ep[(size_t)pid * DIM + i] + et[i];
    }
    float mu = blk_sum256(val[0] + val[1] + val[2], red) * (1.0f / DIM);
    float vs = 0.0f;
    #pragma unroll
    for (int r = 0; r < 3; r++) { float d = val[r] - mu; vs += d * d; }
    float var = blk_sum256(vs, red) * (1.0f / DIM);
    float rs = rsqrtf(var + EPSF);
    #pragma unroll
    for (int r = 0; r < 3; r++) {
        int i = t + r * 256;
        float y = (val[r] - mu) * rs * g[i] + b[i];
        size_t idx = (size_t)srow * DIM + i;
        x[idx] = y;
        __nv_bfloat16 h = __float2bfloat16_rn(y);
        xh[idx] = h;
        xl[idx] = __float2bfloat16_rn(y - __bfloat162float(h));
    }
}

// ---------------- x = LN(x + d1 + d2), writes f32 + bf16 hi/lo ---------------
__global__ void lnres_kernel(float* __restrict__ x, const float* __restrict__ d1,
                             const float* __restrict__ d2,
                             const float* __restrict__ g, const float* __restrict__ b,
                             __nv_bfloat16* __restrict__ xh, __nv_bfloat16* __restrict__ xl) {
    __shared__ float red[32];
    int srow = blockIdx.x;
    int t = threadIdx.x;
    float val[3];
    #pragma unroll
    for (int r = 0; r < 3; r++) {
        int i = t + r * 256;
        size_t idx = (size_t)srow * DIM + i;
        val[r] = x[idx] + d1[idx] + d2[idx];
    }
    float mu = blk_sum256(val[0] + val[1] + val[2], red) * (1.0f / DIM);
    float vs = 0.0f;
    #pragma unroll
    for (int r = 0; r < 3; r++) { float d = val[r] - mu; vs += d * d; }
    float var = blk_sum256(vs, red) * (1.0f / DIM);
    float rs = rsqrtf(var + EPSF);
    #pragma unroll
    for (int r = 0; r < 3; r++) {
        int i = t + r * 256;
        float y = (val[r] - mu) * rs * g[i] + b[i];
        size_t idx = (size_t)srow * DIM + i;
        x[idx] = y;
        __nv_bfloat16 h = __float2bfloat16_rn(y);
        xh[idx] = h;
        xl[idx] = __float2bfloat16_rn(y - __bfloat162float(h));
    }
}

// ---------------- fused weight prep: w1 | w2 | wo | qkv-concat ---------------
__device__ __forceinline__ void split4(const float* __restrict__ s,
                                       __nv_bfloat16* __restrict__ hi,
                                       __nv_bfloat16* __restrict__ lo, int i) {
    float4 v = ((const float4*)s)[i];
    __nv_bfloat16 h0 = __float2bfloat16_rn(v.x), h1 = __float2bfloat16_rn(v.y);
    __nv_bfloat16 h2 = __float2bfloat16_rn(v.z), h3 = __float2bfloat16_rn(v.w);
    uint2 hp, lp;
    hp.x = ((uint32_t)*(uint16_t*)&h0) | ((uint32_t)*(uint16_t*)&h1 << 16);
    hp.y = ((uint32_t)*(uint16_t*)&h2) | ((uint32_t)*(uint16_t*)&h3 << 16);
    lp.x = pack_bf16x2(v.x - __bfloat162float(h0), v.y - __bfloat162float(h1));
    lp.y = pack_bf16x2(v.z - __bfloat162float(h2), v.w - __bfloat162float(h3));
    ((uint2*)hi)[i] = hp;
    ((uint2*)lo)[i] = lp;
}

__global__ void prep_kernel(const float* __restrict__ w1, const float* __restrict__ w2,
                            const float* __restrict__ wo,
                            const float* __restrict__ Wq, const float* __restrict__ Wk,
                            const float* __restrict__ Wv, const float* __restrict__ bq,
                            const float* __restrict__ bk, const float* __restrict__ bv,
                            __nv_bfloat16* __restrict__ w1h, __nv_bfloat16* __restrict__ w1l,
                            __nv_bfloat16* __restrict__ w2h, __nv_bfloat16* __restrict__ w2l,
                            __nv_bfloat16* __restrict__ woh, __nv_bfloat16* __restrict__ wol,
                            __nv_bfloat16* __restrict__ Wh, __nv_bfloat16* __restrict__ Wl,
                            float* __restrict__ bc) {
    int b = blockIdx.x;
    int tid = threadIdx.x;
    if (b < 2304) {
        split4(w1, w1h, w1l, b * 256 + tid);
    } else if (b < 4608) {
        split4(w2, w2h, w2l, (b - 2304) * 256 + tid);
    } else if (b < 5184) {
        split4(wo, woh, wol, (b - 4608) * 256 + tid);
    } else {
        int i4 = (b - 5184) * 256 + tid;
        int k = i4 / (DIM / 4);
        int n4 = i4 % (DIM / 4);
        const float* srcs[3] = {Wq, Wk, Wv};
        #pragma unroll
        for (int s = 0; s < 3; s++) {
            float4 v = ((const float4*)srcs[s])[i4];
            __nv_bfloat16 h0 = __float2bfloat16_rn(v.x), h1 = __float2bfloat16_rn(v.y);
            __nv_bfloat16 h2 = __float2bfloat16_rn(v.z), h3 = __float2bfloat16_rn(v.w);
            uint2 hp, lp;
            hp.x = ((uint32_t)*(uint16_t*)&h0) | ((uint32_t)*(uint16_t*)&h1 << 16);
            hp.y = ((uint32_t)*(uint16_t*)&h2) | ((uint32_t)*(uint16_t*)&h3 << 16);
            lp.x = pack_bf16x2(v.x - __bfloat162float(h0), v.y - __bfloat162float(h1));
            lp.y = pack_bf16x2(v.z - __bfloat162float(h2), v.w - __bfloat162float(h3));
            int e = k * 3 * DIM + s * DIM + n4 * 4;
            ((uint2*)Wh)[e >> 2] = hp;
            ((uint2*)Wl)[e >> 2] = lp;
        }
        if (i4 < DIM / 4) {
            ((float4*)bc)[i4] = ((const float4*)bq)[i4];
            ((float4*)(bc + DIM))[i4] = ((const float4*)bk)[i4];
            ((float4*)(bc + 2 * DIM))[i4] = ((const float4*)bv)[i4];
        }
    }
}

// ---------------- bf16x3 tensor-core GEMM (BK=32, cp.async, split-K) ---------
// __launch_bounds__(256, 2): cap regs at 128 -> 2 blocks/SM (occupancy fix).
template <int BM, int OUT, int NS>
__global__ __launch_bounds__(256, 2) void tgemm_kernel(
    const __nv_bfloat16* __restrict__ Ah, const __nv_bfloat16* __restrict__ Al,
    const __nv_bfloat16* __restrict__ Bh, const __nv_bfloat16* __restrict__ Bl,
    const float* __restrict__ bias, float* __restrict__ C, float* __restrict__ C2,
    __nv_bfloat16* __restrict__ Chi, __nv_bfloat16* __restrict__ Clo,
    int M, int N, int K, int lda) {
    constexpr int MT = BM / 64;
    constexpr int OFF_AL = BM * 64;
    constexpr int OFF_BH = 2 * BM * 64;
    constexpr int OFF_BL = 2 * BM * 64 + 8192;
    constexpr int STAGE  = 2 * BM * 64 + 16384;
    constexpr int AITERS = BM * 4 / 256;

    extern __shared__ __align__(16) unsigned char smem_raw[];
    uint32_t smemb = (uint32_t)__cvta_generic_to_shared(smem_raw);

    const int bx = blockIdx.x;
    const int by = blockIdx.y;
    const int Klocal = K / gridDim.z;
    const int kbase = blockIdx.z * Klocal;
    const int tid = threadIdx.x;
    const int lane = tid & 31;
    const int wid = tid >> 5;
    const int warpM = wid & 3;
    const int warpN = wid >> 2;
    const int gid = lane >> 2;
    const int tig = lane & 3;
    const int mBase = warpM * 16 * MT;
    const int nBase = warpN * 64;
    const int rowbase = by * BM;
    const int colbase = bx * 128;

    float acc[MT][8][4];
    #pragma unroll
    for (int mt = 0; mt < MT; mt++)
        #pragma unroll
        for (int nt = 0; nt < 8; nt++)
            #pragma unroll
            for (int r = 0; r < 4; r++) acc[mt][nt][r] = 0.0f;

    auto issue = [&](int st, int k0) {
        uint32_t sb = smemb + st * STAGE;
        #pragma unroll
        for (int it = 0; it < AITERS; it++) {
            int idx = tid + it * 256;
            int r = idx >> 2, ch = idx & 3;
            size_t go = (size_t)(rowbase + r) * lda + kbase + k0 + ch * 8;
            uint32_t so = (uint32_t)(r * 64 + ((ch ^ ((r >> 1) & 3)) << 4));
            cp16(sb + so, Ah + go);
            cp16(sb + OFF_AL + so, Al + go);
        }
        #pragma unroll
        for (int it = 0; it < 2; it++) {
            int idx = tid + it * 256;
            int krow = idx >> 4, ch = idx & 15;
            size_t go = (size_t)(kbase + k0 + krow) * N + colbase + ch * 8;
            uint32_t so = (uint32_t)(krow * 256 + ((ch ^ (krow & 7)) << 4));
            cp16(sb + OFF_BH + so, Bh + go);
            cp16(sb + OFF_BL + so, Bl + go);
        }
        asm volatile("cp.async.commit_group;" ::: "memory");
    };

    const int KT = Klocal >> 5;
    issue(0, 0);
    if (NS == 3 && KT > 1) issue(1, 32);

    const int lane15 = lane & 15;
    const int laneh = lane >> 4;
    const int bk = lane & 15;
    const int bs = (lane >> 4) & 1;

    for (int t = 0; t < KT; t++) {
        if (NS == 2) {
            if (t + 1 < KT) {
                issue((t + 1) & 1, (t + 1) * 32);
                asm volatile("cp.async.wait_group 1;" ::: "memory");
            } else {
                asm volatile("cp.async.wait_group 0;" ::: "memory");
            }
        } else {
            if (t + 2 < KT) {
                int nb = t + 2;
                nb = nb - (nb / 3) * 3;
                issue(nb, (t + 2) * 32);
            }
            if (t + 3 <= KT) {
                asm volatile("cp.async.wait_group 2;" ::: "memory");
            } else if (t + 2 == KT) {
                asm volatile("cp.async.wait_group 1;" ::: "memory");
            } else {
                asm volatile("cp.async.wait_group 0;" ::: "memory");
            }
        }
        __syncthreads();

        int buf = (NS == 2) ? (t & 1) : (t - (t / 3) * 3);
        uint32_t sb = smemb + buf * STAGE;
        #pragma unroll
        for (int kk = 0; kk < 2; kk++) {
            uint32_t aHi[MT][4], aLo[MT][4];
            #pragma unroll
            for (int mt = 0; mt < MT; mt++) {
                int row = mBase + mt * 16 + lane15;
                int ch = (kk * 2 + laneh) ^ ((row >> 1) & 3);
                uint32_t ad = sb + (uint32_t)(row * 64 + (ch << 4));
                ldsm4(aHi[mt][0], aHi[mt][1], aHi[mt][2], aHi[mt][3], ad);
                ldsm4(aLo[mt][0], aLo[mt][1], aLo[mt][2], aLo[mt][3], ad + OFF_AL);
            }
            int krow = kk * 16 + bk;
            uint32_t bRow = sb + OFF_BH + (uint32_t)(krow * 256);
            #pragma unroll
            for (int nt2 = 0; nt2 < 4; nt2++) {
                uint32_t ch = (uint32_t)((((warpN * 8 + nt2 * 2 + bs) ^ (bk & 7))) * 16);
                uint32_t bh0, bh1, bh2, bh3, bl0, bl1, bl2, bl3;
                ldsm4t(bh0, bh1, bh2, bh3, bRow + ch);
                ldsm4t(bl0, bl1, bl2, bl3, bRow + (OFF_BL - OFF_BH) + ch);
                #pragma unroll
                for (int mt = 0; mt < MT; mt++) {
                    float* a0 = acc[mt][nt2 * 2];
                    mma_bf16(a0[0], a0[1], a0[2], a0[3],
                             aHi[mt][0], aHi[mt][1], aHi[mt][2], aHi[mt][3], bh0, bh1);
                    mma_bf16(a0[0], a0[1], a0[2], a0[3],
                             aHi[mt][0], aHi[mt][1], aHi[mt][2], aHi[mt][3], bl0, bl1);
                    mma_bf16(a0[0], a0[1], a0[2], a0[3],
                             aLo[mt][0], aLo[mt][1], aLo[mt][2], aLo[mt][3], bh0, bh1);
                    float* a1 = acc[mt][nt2 * 2 + 1];
                    mma_bf16(a1[0], a1[1], a1[2], a1[3],
                             aHi[mt][0], aHi[mt][1], aHi[mt][2], aHi[mt][3], bh2, bh3);
                    mma_bf16(a1[0], a1[1], a1[2], a1[3],
                             aHi[mt][0], aHi[mt][1], aHi[mt][2], aHi[mt][3], bl2, bl3);
                    mma_bf16(a1[0], a1[1], a1[2], a1[3],
                             aLo[mt][0], aLo[mt][1], aLo[mt][2], aLo[mt][3], bh2, bh3);
                }
            }
        }
        __syncthreads();
    }

    float* Cout = (blockIdx.z == 0) ? C : C2;
    const bool addb = (blockIdx.z == 0);
    #pragma unroll
    for (int nt = 0; nt < 8; nt++) {
        int col = colbase + nBase + nt * 8 + tig * 2;
        float b0 = addb ? bias[col] : 0.0f;
        float b1 = addb ? bias[col + 1] : 0.0f;
        #pragma unroll
        for (int mt = 0; mt < MT; mt++) {
            int row0 = rowbase + mBase + mt * 16 + gid;
            float v0 = acc[mt][nt][0] + b0;
            float v1 = acc[mt][nt][1] + b1;
            float v2 = acc[mt][nt][2] + b0;
            float v3 = acc[mt][nt][3] + b1;
            if (OUT == 0) {
                *(float2*)(Cout + (size_t)row0 * N + col) = make_float2(v0, v1);
                *(float2*)(Cout + (size_t)(row0 + 8) * N + col) = make_float2(v2, v3);
            } else {
                if (OUT == 2) {
                    v0 = gelu_exact(v0); v1 = gelu_exact(v1);
                    v2 = gelu_exact(v2); v3 = gelu_exact(v3);
                }
                size_t i0 = ((size_t)row0 * N + col) >> 1;
                size_t i1 = ((size_t)(row0 + 8) * N + col) >> 1;
                __nv_bfloat16 h0 = __float2bfloat16_rn(v0), h1 = __float2bfloat16_rn(v1);
                __nv_bfloat16 h2 = __float2bfloat16_rn(v2), h3 = __float2bfloat16_rn(v3);
                ((uint32_t*)Chi)[i0] = ((uint32_t)*(uint16_t*)&h0) | ((uint32_t)*(uint16_t*)&h1 << 16);
                ((uint32_t*)Chi)[i1] = ((uint32_t)*(uint16_t*)&h2) | ((uint32_t)*(uint16_t*)&h3 << 16);
                ((uint32_t*)Clo)[i0] = pack_bf16x2(v0 - __bfloat162float(h0), v1 - __bfloat162float(h1));
                ((uint32_t*)Clo)[i1] = pack_bf16x2(v2 - __bfloat162float(h2), v3 - __bfloat162float(h3));
            }
        }
    }
}

// ---------------- tensor-core sliding-window flash attention ------------------
#define ATT_SMEM (65536 + 256)
__global__ __launch_bounds__(128) void attn_mma_kernel(
    const __nv_bfloat16* __restrict__ qkvh, const __nv_bfloat16* __restrict__ qkvl,
    const int* __restrict__ mask,
    __nv_bfloat16* __restrict__ oh, __nv_bfloat16* __restrict__ ol) {
    extern __shared__ __align__(16) unsigned char asmem[];
    const uint32_t sb = (uint32_t)__cvta_generic_to_shared(asmem);
    const uint32_t QH = sb, QL = sb + 16384;
    int* mskbuf = (int*)(asmem + 65536);

    const int h = blockIdx.y;
    const int q0 = blockIdx.x * 128;
    const int tid = threadIdx.x, lane = tid & 31, wid = tid >> 5;
    const int gid = lane >> 2, tig = lane & 3;
    const int mBase = wid * 32;
    const int STR = 3 * DIM;
    const int NC = (128 + 2 * WIN) / 32;

    auto issueKV = [&](int st, int c) {
        uint32_t kb = sb + 32768 + st * 16384;
        #pragma unroll
        for (int i = 0; i < 2; i++) {
            int idx = tid + i * 128;
            int row = idx >> 3, ch = idx & 7;
            int kp = c + row;
            int kc = kp < 0 ? 0 : (kp >= SEQ ? SEQ - 1 : kp);
            size_t gk = (size_t)kc * STR + DIM + h * 64 + ch * 8;
            size_t gv = (size_t)kc * STR + 2 * DIM + h * 64 + ch * 8;
            uint32_t so = (uint32_t)(row * 128 + ((ch ^ (row & 7)) << 4));
            cp16(kb + so, qkvh + gk);
            cp16(kb + 4096 + so, qkvl + gk);
            cp16(kb + 8192 + so, qkvh + gv);
            cp16(kb + 12288 + so, qkvl + gv);
        }
        if (tid < 32) {
            int kp = c + tid;
            mskbuf[st * 32 + tid] = (kp >= 0 && kp < SEQ) ? mask[kp] : 0;
        }
    };

    #pragma unroll
    for (int i = 0; i < 8; i++) {
        int idx = tid + i * 128;
        int row = idx >> 3, ch = idx & 7;
        size_t gq = (size_t)(q0 + row) * STR + h * 64 + ch * 8;
        uint32_t so = (uint32_t)(row * 128 + ((ch ^ (row & 7)) << 4));
        cp16(QH + so, qkvh + gq);
        cp16(QL + so, qkvl + gq);
    }
    const int cstart = q0 - WIN;
    issueKV(0, cstart);
    asm volatile("cp.async.commit_group;" ::: "memory");

    uint32_t Qhi[2][4][4], Qlo[2][4][4];
    float O[2][8][4];
    #pragma unroll
    for (int mt = 0; mt < 2; mt++)
        #pragma unroll
        for (int dj = 0; dj < 8; dj++)
            #pragma unroll
            for (int r = 0; r < 4; r++) O[mt][dj][r] = 0.0f;
    float mrow[2][2] = {{-1e30f, -1e30f}, {-1e30f, -1e30f}};
    float lrow[2][2] = {{0.0f, 0.0f}, {0.0f, 0.0f}};

    const int warpLo = q0 + mBase - WIN;
    const int warpHi = q0 + mBase + 31 + WIN;

    for (int t = 0; t < NC; t++) {
        const int c = cstart + t * 32;
        if (t + 1 < NC) {
            issueKV((t + 1) & 1, c + 32);
            asm volatile("cp.async.commit_group;" ::: "memory");
            asm volatile("cp.async.wait_group 1;" ::: "memory");
        } else {
            asm volatile("cp.async.wait_group 0;" ::: "memory");
        }
        __syncthreads();

        if (t == 0) {
            int arow = (lane & 7) + 8 * ((lane >> 3) & 1);
            int achsel = lane >> 4;
            #pragma unroll
            for (int mt = 0; mt < 2; mt++) {
                int row = mBase + mt * 16 + arow;
                #pragma unroll
                for (int kk = 0; kk < 4; kk++) {
                    int chunk = kk * 2 + achsel;
                    uint32_t ad = (uint32_t)(row * 128 + ((chunk ^ (row & 7)) << 4));
                    ldsm4(Qhi[mt][kk][0], Qhi[mt][kk][1], Qhi[mt][kk][2], Qhi[mt][kk][3], QH + ad);
                    ldsm4(Qlo[mt][kk][0], Qlo[mt][kk][1], Qlo[mt][kk][2], Qlo[mt][kk][3], QL + ad);
                }
            }
        }

        if (c + 31 >= warpLo && c <= warpHi) {
            const uint32_t KB = sb + 32768 + (t & 1) * 16384;
            const int* msk = mskbuf + (t & 1) * 32;

            float S[2][4][4];
            #pragma unroll
            for (int mt = 0; mt < 2; mt++)
                #pragma unroll
                for (int j = 0; j < 4; j++)
                    #pragma unroll
                    for (int r = 0; r < 4; r++) S[mt][j][r] = 0.0f;

            #pragma unroll
            for (int j = 0; j < 4; j++) {
                uint32_t kh[4][2], kl[4][2];
                int krow = j * 8 + (lane & 7);
                #pragma unroll
                for (int h32 = 0; h32 < 2; h32++) {
                    int chunk = h32 * 4 + (lane >> 3);
                    uint32_t ad = (uint32_t)(krow * 128 + ((chunk ^ (krow & 7)) << 4));
                    uint32_t r0, r1, r2, r3;
                    ldsm4(r0, r1, r2, r3, KB + ad);
                    kh[h32 * 2][0] = r0; kh[h32 * 2][1] = r1;
                    kh[h32 * 2 + 1][0] = r2; kh[h32 * 2 + 1][1] = r3;
                    ldsm4(r0, r1, r2, r3, KB + 4096 + ad);
                    kl[h32 * 2][0] = r0; kl[h32 * 2][1] = r1;
                    kl[h32 * 2 + 1][0] = r2; kl[h32 * 2 + 1][1] = r3;
                }
                #pragma unroll
                for (int kk = 0; kk < 4; kk++)
                    #pragma unroll
                    for (int mt = 0; mt < 2; mt++) {
                        float* s = S[mt][j];
                        mma_bf16(s[0], s[1], s[2], s[3],
                                 Qhi[mt][kk][0], Qhi[mt][kk][1], Qhi[mt][kk][2], Qhi[mt][kk][3],
                                 kh[kk][0], kh[kk][1]);
                        mma_bf16(s[0], s[1], s[2], s[3],
                                 Qhi[mt][kk][0], Qhi[mt][kk][1], Qhi[mt][kk][2], Qhi[mt][kk][3],
                                 kl[kk][0], kl[kk][1]);
                        mma_bf16(s[0], s[1], s[2], s[3],
                                 Qlo[mt][kk][0], Qlo[mt][kk][1], Qlo[mt][kk][2], Qlo[mt][kk][3],
                                 kh[kk][0], kh[kk][1]);
                    }
            }

            float p[2][4][4];
            #pragma unroll
            for (int mt = 0; mt < 2; mt++) {
                int rA = q0 + mBase + mt * 16 + gid;
                int rB = rA + 8;
                float mxA = -1e30f, mxB = -1e30f;
                #pragma unroll
                for (int j = 0; j < 4; j++) {
                    int c0 = c + j * 8 + tig * 2;
                    int c1 = c0 + 1;
                    int mk0 = msk[j * 8 + tig * 2];
                    int mk1 = msk[j * 8 + tig * 2 + 1];
                    bool v00 = mk0 && (c0 >= rA - WIN) && (c0 <= rA + WIN);
                    bool v01 = mk1 && (c1 >= rA - WIN) && (c1 <= rA + WIN);
                    bool v10 = mk0 && (c0 >= rB - WIN) && (c0 <= rB + WIN);
                    bool v11 = mk1 && (c1 >= rB - WIN) && (c1 <= rB + WIN);
                    S[mt][j][0] = v00 ? S[mt][j][0] * 0.125f : -1e30f;
                    S[mt][j][1] = v01 ? S[mt][j][1] * 0.125f : -1e30f;
                    S[mt][j][2] = v10 ? S[mt][j][2] * 0.125f : -1e30f;
                    S[mt][j][3] = v11 ? S[mt][j][3] * 0.125f : -1e30f;
                    mxA = fmaxf(mxA, fmaxf(S[mt][j][0], S[mt][j][1]));
                    mxB = fmaxf(mxB, fmaxf(S[mt][j][2], S[mt][j][3]));
                }
                mxA = fmaxf(mxA, __shfl_xor_sync(0xffffffffu, mxA, 1));
                mxA = fmaxf(mxA, __shfl_xor_sync(0xffffffffu, mxA, 2));
                mxB = fmaxf(mxB, __shfl_xor_sync(0xffffffffu, mxB, 1));
                mxB = fmaxf(mxB, __shfl_xor_sync(0xffffffffu, mxB, 2));
                float mnA = fmaxf(mrow[mt][0], mxA);
                float mnB = fmaxf(mrow[mt][1], mxB);
                float scA = __expf(mrow[mt][0] - mnA);
                float scB = __expf(mrow[mt][1] - mnB);
                mrow[mt][0] = mnA; mrow[mt][1] = mnB;
                float sA = 0.0f, sB = 0.0f;
                #pragma unroll
                for (int j = 0; j < 4; j++) {
                    float p0 = (S[mt][j][0] > -1e29f) ? __expf(S[mt][j][0] - mnA) : 0.0f;
                    float p1 = (S[mt][j][1] > -1e29f) ? __expf(S[mt][j][1] - mnA) : 0.0f;
                    float p2 = (S[mt][j][2] > -1e29f) ? __expf(S[mt][j][2] - mnB) : 0.0f;
                    float p3 = (S[mt][j][3] > -1e29f) ? __expf(S[mt][j][3] - mnB) : 0.0f;
                    p[mt][j][0] = p0; p[mt][j][1] = p1; p[mt][j][2] = p2; p[mt][j][3] = p3;
                    sA += p0 + p1; sB += p2 + p3;
                }
                sA += __shfl_xor_sync(0xffffffffu, sA, 1);
                sA += __shfl_xor_sync(0xffffffffu, sA, 2);
                sB += __shfl_xor_sync(0xffffffffu, sB, 1);
                sB += __shfl_xor_sync(0xffffffffu, sB, 2);
                lrow[mt][0] = lrow[mt][0] * scA + sA;
                lrow[mt][1] = lrow[mt][1] * scB + sB;
                #pragma unroll
                for (int dj = 0; dj < 8; dj++) {
                    O[mt][dj][0] *= scA; O[mt][dj][1] *= scA;
                    O[mt][dj][2] *= scB; O[mt][dj][3] *= scB;
                }
            }

            uint32_t Phi[2][2][4], Plo[2][2][4];
            #pragma unroll
            for (int mt = 0; mt < 2; mt++)
                #pragma unroll
                for (int kk = 0; kk < 2; kk++) {
                    #pragma unroll
                    for (int q = 0; q < 4; q++) {
                        int j = 2 * kk + (q >> 1);
                        int r0 = (q & 1) * 2;
                        float x0 = p[mt][j][r0], x1 = p[mt][j][r0 + 1];
                        __nv_bfloat162 hh = __floats2bfloat162_rn(x0, x1);
                        Phi[mt][kk][q] = *(uint32_t*)&hh;
                        Plo[mt][kk][q] = pack_bf16x2(x0 - __bfloat162float(hh.x),
                                                     x1 - __bfloat162float(hh.y));
                    }
                }

            #pragma unroll
            for (int djp = 0; djp < 4; djp++) {
                #pragma unroll
                for (int kk = 0; kk < 2; kk++) {
                    int vrow = kk * 16 + (lane & 7) + 8 * ((lane >> 3) & 1);
                    int chunk = djp * 2 + (lane >> 4);
                    uint32_t ad = (uint32_t)(vrow * 128 + ((chunk ^ (vrow & 7)) << 4));
                    uint32_t h0, h1, h2, h3, l0, l1, l2, l3;
                    ldsm4t(h0, h1, h2, h3, KB + 8192 + ad);
                    ldsm4t(l0, l1, l2, l3, KB + 12288 + ad);
                    #pragma unroll
                    for (int mt = 0; mt < 2; mt++) {
                        float* o0 = O[mt][djp * 2];
                        float* o1 = O[mt][djp * 2 + 1];
                        mma_bf16(o0[0], o0[1], o0[2], o0[3],
                                 Phi[mt][kk][0], Phi[mt][kk][1], Phi[mt][kk][2], Phi[mt][kk][3],
                                 h0, h1);
                        mma_bf16(o0[0], o0[1], o0[2], o0[3],
                                 Plo[mt][kk][0], Plo[mt][kk][1], Plo[mt][kk][2], Plo[mt][kk][3],
                                 h0, h1);
                        mma_bf16(o0[0], o0[1], o0[2], o0[3],
                                 Phi[mt][kk][0], Phi[mt][kk][1], Phi[mt][kk][2], Phi[mt][kk][3],
                                 l0, l1);
                        mma_bf16(o1[0], o1[1], o1[2], o1[3],
                                 Phi[mt][kk][0], Phi[mt][kk][1], Phi[mt][kk][2], Phi[mt][kk][3],
                                 h2, h3);
                        mma_bf16(o1[0], o1[1], o1[2], o1[3],
                                 Plo[mt][kk][0], Plo[mt][kk][1], Plo[mt][kk][2], Plo[mt][kk][3],
                                 h2, h3);
                        mma_bf16(o1[0], o1[1], o1[2], o1[3],
                                 Phi[mt][kk][0], Phi[mt][kk][1], Phi[mt][kk][2], Phi[mt][kk][3],
                                 l2, l3);
                    }
                }
            }
        }
        __syncthreads();   // WAR guard
    }

    #pragma unroll
    for (int mt = 0; mt < 2; mt++) {
        float invA = (lrow[mt][0] > 0.0f) ? (1.0f / lrow[mt][0]) : 0.0f;
        float invB = (lrow[mt][1] > 0.0f) ? (1.0f / lrow[mt][1]) : 0.0f;
        int rA = q0 + mBase + mt * 16 + gid;
        int rB = rA + 8;
        #pragma unroll
        for (int dj = 0; dj < 8; dj++) {
            int col = h * 64 + dj * 8 + tig * 2;
            float v0 = O[mt][dj][0] * invA, v1 = O[mt][dj][1] * invA;
            float v2 = O[mt][dj][2] * invB, v3 = O[mt][dj][3] * invB;
            size_t iA = ((size_t)rA * DIM + col) >> 1;
            size_t iB = ((size_t)rB * DIM + col) >> 1;
            __nv_bfloat162 hA = __floats2bfloat162_rn(v0, v1);
            __nv_bfloat162 hB = __floats2bfloat162_rn(v2, v3);
            ((uint32_t*)oh)[iA] = *(uint32_t*)&hA;
            ((uint32_t*)oh)[iB] = *(uint32_t*)&hB;
            ((uint32_t*)ol)[iA] = pack_bf16x2(v0 - __bfloat162float(hA.x),
                                              v1 - __bfloat162float(hA.y));
            ((uint32_t*)ol)[iB] = pack_bf16x2(v2 - __bfloat162float(hB.x),
                                              v3 - __bfloat162float(hB.y));
        }
    }
}

// ---------------- classification heads (768 -> 512 relu -> nout) ------------
__global__ void head_kernel(const float* __restrict__ x, const float* __restrict__ W1,
                            const float* __restrict__ b1, const float* __restrict__ W2,
                            const float* __restrict__ b2, float* __restrict__ out, int nout) {
    __shared__ float xs[768];
    __shared__ float hsm[512];
    int t = threadIdx.x;
    for (int i = t; i < 768; i += 512) xs[i] = x[i];
    __syncthreads();
    float acc = b1[t];
    for (int kk = 0; kk < 768; kk++) acc += xs[kk] * W1[(size_t)kk * 512 + t];
    hsm[t] = fmaxf(acc, 0.0f);
    __syncthreads();
    if (t < nout) {
        float ov = b2[t];
        for (int kk = 0; kk < 512; kk++) ov += hsm[kk] * W2[(size_t)kk * nout + t];
        out[t] = ov;
    }
}

// ---------------- host launcher ---------------------------------------------
extern "C" void kernel_launch(void* const* d_in, const int* in_sizes, int n_in,
                              void* d_out, int out_size) {
    const int*   ids      = (const int*)d_in[0];
    const int*   mask     = (const int*)d_in[1];
    const float* emb_word = (const float*)d_in[2];
    const float* emb_pos  = (const float*)d_in[3];
    const float* emb_type = (const float*)d_in[4];
    const float* emb_g    = (const float*)d_in[5];
    const float* emb_b    = (const float*)d_in[6];
    const float* Wq = (const float*)d_in[7];
    const float* bq = (const float*)d_in[8];
    const float* Wk = (const float*)d_in[9];
    const float* bk = (const float*)d_in[10];
    const float* Wv = (const float*)d_in[11];
    const float* bv = (const float*)d_in[12];
    const float* Wo = (const float*)d_in[13];
    const float* bo = (const float*)d_in[14];
    const float* ln1g = (const float*)d_in[15];
    const float* ln1b = (const float*)d_in[16];
    const float* W1 = (const float*)d_in[17];
    const float* b1 = (const float*)d_in[18];
    const float* W2 = (const float*)d_in[19];
    const float* b2 = (const float*)d_in[20];
    const float* ln2g = (const float*)d_in[21];
    const float* ln2b = (const float*)d_in[22];
    const float* cW1 = (const float*)d_in[23];
    const float* cb1 = (const float*)d_in[24];
    const float* cW2 = (const float*)d_in[25];
    const float* cb2 = (const float*)d_in[26];
    const float* dW1 = (const float*)d_in[27];
    const float* db1 = (const float*)d_in[28];
    const float* dW2 = (const float*)d_in[29];
    const float* db2 = (const float*)d_in[30];
    float* out = (float*)d_out;

    float *x, *t, *t2, *bcat;
    int* pos;
    __nv_bfloat16 *xh, *xl, *qkvh, *qkvl, *ah, *al, *hh, *hl;
    __nv_bfloat16 *wqh, *wql, *w1h, *w1l, *w2h, *w2l, *woh, *wol;
    cudaGetSymbolAddress((void**)&x, g_x);
    cudaGetSymbolAddress((void**)&t, g_t);
    cudaGetSymbolAddress((void**)&t2, g_t2);
    cudaGetSymbolAddress((void**)&bcat, g_bcat);
    cudaGetSymbolAddress((void**)&pos, g_pos);
    cudaGetSymbolAddress((void**)&xh, g_xh);
    cudaGetSymbolAddress((void**)&xl, g_xl);
    cudaGetSymbolAddress((void**)&qkvh, g_qkvh);
    cudaGetSymbolAddress((void**)&qkvl, g_qkvl);
    cudaGetSymbolAddress((void**)&ah, g_ah);
    cudaGetSymbolAddress((void**)&al, g_al);
    cudaGetSymbolAddress((void**)&hh, g_hh);
    cudaGetSymbolAddress((void**)&hl, g_hl);
    cudaGetSymbolAddress((void**)&wqh, g_wqh);
    cudaGetSymbolAddress((void**)&wql, g_wql);
    cudaGetSymbolAddress((void**)&w1h, g_w1h);
    cudaGetSymbolAddress((void**)&w1l, g_w1l);
    cudaGetSymbolAddress((void**)&w2h, g_w2h);
    cudaGetSymbolAddress((void**)&w2l, g_w2l);
    cudaGetSymbolAddress((void**)&woh, g_woh);
    cudaGetSymbolAddress((void**)&wol, g_wol);

    const int SM128 = 2 * (2 * 128 * 64 + 16384);   // 65536
    const int SM64  = 3 * (2 * 64 * 64 + 16384);    // 73728 (3-stage)
    cudaFuncSetAttribute(tgemm_kernel<128, 3, 2>, cudaFuncAttributeMaxDynamicSharedMemorySize, SM128);
    cudaFuncSetAttribute(tgemm_kernel<128, 2, 2>, cudaFuncAttributeMaxDynamicSharedMemorySize, SM128);
    cudaFuncSetAttribute(tgemm_kernel<64, 0, 3>, cudaFuncAttributeMaxDynamicSharedMemorySize, SM64);
    cudaFuncSetAttribute(attn_mma_kernel, cudaFuncAttributeMaxDynamicSharedMemorySize, ATT_SMEM);

    pos_kernel<<<1, 1024>>>(mask, pos);
    embed_ln_kernel<<<SEQ, 256>>>(ids, pos, emb_word, emb_pos, emb_type, emb_g, emb_b, x, xh, xl);

    dim3 gqkv(3 * DIM / 128, SEQ / 128, 1);   // (18, 32)
    dim3 go(DIM / 128, SEQ / 64, 2);          // (6, 64, 2) split-K
    dim3 gff1(FFD / 128, SEQ / 128, 1);       // (24, 32)
    dim3 gff2(DIM / 128, SEQ / 64, 2);        // (6, 64, 2) split-K
    dim3 gattn(SEQ / 128, NH);

    for (int i = 0; i < NL; i++) {
        const float* wq = Wq + (size_t)i * DIM * DIM;
        const float* wk = Wk + (size_t)i * DIM * DIM;
        const float* wv = Wv + (size_t)i * DIM * DIM;
        const float* wo = Wo + (size_t)i * DIM * DIM;
        const float* w1 = W1 + (size_t)i * DIM * FFD;
        const float* w2 = W2 + (size_t)i * FFD * DIM;

        prep_kernel<<<5760, 256>>>(w1, w2, wo, wq, wk, wv,
                                   bq + i * DIM, bk + i * DIM, bv + i * DIM,
                                   w1h, w1l, w2h, w2l, woh, wol, wqh, wql, bcat);

        tgemm_kernel<128, 3, 2><<<gqkv, 256, SM128>>>(xh, xl, wqh, wql, bcat, nullptr, nullptr,
                                                      qkvh, qkvl, SEQ, 3 * DIM, DIM, DIM);
        attn_mma_kernel<<<gattn, 128, ATT_SMEM>>>(qkvh, qkvl, mask, ah, al);
        tgemm_kernel<64, 0, 3><<<go, 256, SM64>>>(ah, al, woh, wol, bo + i * DIM, t, t2,
                                                  nullptr, nullptr, SEQ, DIM, DIM, DIM);
        lnres_kernel<<<SEQ, 256>>>(x, t, t2, ln1g + i * DIM, ln1b + i * DIM, xh, xl);
        tgemm_kernel<128, 2, 2><<<gff1, 256, SM128>>>(xh, xl, w1h, w1l, b1 + i * FFD, nullptr,
                                                      nullptr, hh, hl, SEQ, FFD, DIM, DIM);
        tgemm_kernel<64, 0, 3><<<gff2, 256, SM64>>>(hh, hl, w2h, w2l, b2 + i * DIM, t, t2,
                                                    nullptr, nullptr, SEQ, DIM, FFD, FFD);
        lnres_kernel<<<SEQ, 256>>>(x, t, t2, ln2g + i * DIM, ln2b + i * DIM, xh, xl);
    }

    head_kernel<<<1, 512>>>(x, cW1, cb1, cW2, cb2, out, 5);
    head_kernel<<<1, 512>>>(x, dW1, db1, dW2, db2, out + 5, 10);
}

// round 16
// speedup vs baseline: 1.0655x; 1.0191x over previous
#include <cuda_runtime.h>
#include <cuda_bf16.h>
#include <stdint.h>
#include <math.h>

#define SEQ 4096
#define DIM 768
#define NH  12
#define HD  64
#define NL  12
#define FFD 3072
#define WIN 256
#define EPSF 1e-5f

// ---------------- scratch (static device globals; no runtime allocation) ----
__device__ float g_x[SEQ * DIM];
__device__ float g_t[SEQ * DIM];
__device__ float g_t2[SEQ * DIM];
__device__ float g_bcat[3 * DIM];
__device__ int   g_pos[SEQ];

__device__ __nv_bfloat16 g_xh[SEQ * DIM],  g_xl[SEQ * DIM];
__device__ __nv_bfloat16 g_qkvh[SEQ * 3 * DIM], g_qkvl[SEQ * 3 * DIM];
__device__ __nv_bfloat16 g_ah[SEQ * DIM],  g_al[SEQ * DIM];
__device__ __nv_bfloat16 g_hh[SEQ * FFD],  g_hl[SEQ * FFD];
__device__ __nv_bfloat16 g_wqh[DIM * 3 * DIM], g_wql[DIM * 3 * DIM];
__device__ __nv_bfloat16 g_w1h[DIM * FFD], g_w1l[DIM * FFD];
__device__ __nv_bfloat16 g_w2h[FFD * DIM], g_w2l[FFD * DIM];
__device__ __nv_bfloat16 g_woh[DIM * DIM], g_wol[DIM * DIM];

// ---------------- helpers ---------------------------------------------------
__device__ __forceinline__ float gelu_exact(float x) {
    return 0.5f * x * (1.0f + erff(x * 0.70710678118654752f));
}

__device__ __forceinline__ uint32_t pack_bf16x2(float x, float y) {
    __nv_bfloat162 h = __floats2bfloat162_rn(x, y);
    return *(uint32_t*)&h;
}

__device__ __forceinline__ void mma_bf16(float& d0, float& d1, float& d2, float& d3,
                                         uint32_t a0, uint32_t a1, uint32_t a2, uint32_t a3,
                                         uint32_t b0, uint32_t b1) {
    asm volatile("mma.sync.aligned.m16n8k16.row.col.f32.bf16.bf16.f32 "
                 "{%0,%1,%2,%3}, {%4,%5,%6,%7}, {%8,%9}, {%0,%1,%2,%3};"
                 : "+f"(d0), "+f"(d1), "+f"(d2), "+f"(d3)
                 : "r"(a0), "r"(a1), "r"(a2), "r"(a3), "r"(b0), "r"(b1));
}

__device__ __forceinline__ void ldsm4(uint32_t& r0, uint32_t& r1, uint32_t& r2, uint32_t& r3,
                                      uint32_t addr) {
    asm volatile("ldmatrix.sync.aligned.m8n8.x4.shared.b16 {%0,%1,%2,%3}, [%4];"
                 : "=r"(r0), "=r"(r1), "=r"(r2), "=r"(r3) : "r"(addr));
}

__device__ __forceinline__ void ldsm4t(uint32_t& r0, uint32_t& r1, uint32_t& r2, uint32_t& r3,
                                       uint32_t addr) {
    asm volatile("ldmatrix.sync.aligned.m8n8.x4.trans.shared.b16 {%0,%1,%2,%3}, [%4];"
                 : "=r"(r0), "=r"(r1), "=r"(r2), "=r"(r3) : "r"(addr));
}

__device__ __forceinline__ void cp16(uint32_t saddr, const void* gaddr) {
    asm volatile("cp.async.cg.shared.global [%0], [%1], 16;" :: "r"(saddr), "l"(gaddr));
}

__device__ __forceinline__ float blk_sum256(float v, float* red) {
    #pragma unroll
    for (int o = 16; o > 0; o >>= 1) v += __shfl_down_sync(0xffffffffu, v, o);
    int w = threadIdx.x >> 5;
    if ((threadIdx.x & 31) == 0) red[w] = v;
    __syncthreads();
    if (threadIdx.x < 32) {
        v = (threadIdx.x < 8) ? red[threadIdx.x] : 0.0f;
        #pragma unroll
        for (int o = 4; o > 0; o >>= 1) v += __shfl_down_sync(0xffffffffu, v, o);
        if (threadIdx.x == 0) red[0] = v;
    }
    __syncthreads();
    float r = red[0];
    __syncthreads();
    return r;
}

// ---------------- pos_ids = cumsum(mask)*mask + 1 ---------------------------
__global__ void pos_kernel(const int* __restrict__ mask, int* __restrict__ pos) {
    __shared__ int ss[1024];
    int t = threadIdx.x;
    int m0 = mask[t * 4 + 0], m1 = mask[t * 4 + 1];
    int m2 = mask[t * 4 + 2], m3 = mask[t * 4 + 3];
    int s = m0 + m1 + m2 + m3;
    ss[t] = s;
    __syncthreads();
    for (int off = 1; off < 1024; off <<= 1) {
        int vprev = (t >= off) ? ss[t - off] : 0;
        __syncthreads();
        ss[t] += vprev;
        __syncthreads();
    }
    int run = ss[t] - s;
    run += m0; pos[t * 4 + 0] = run * m0 + 1;
    run += m1; pos[t * 4 + 1] = run * m1 + 1;
    run += m2; pos[t * 4 + 2] = run * m2 + 1;
    run += m3; pos[t * 4 + 3] = run * m3 + 1;
}

// ---------------- embedding + layernorm (writes f32 + bf16 hi/lo) -----------
__global__ void embed_ln_kernel(const int* __restrict__ ids, const int* __restrict__ pos,
                                const float* __restrict__ ew, const float* __restrict__ ep,
                                const float* __restrict__ et, const float* __restrict__ g,
                                const float* __restrict__ b, float* __restrict__ x,
                                __nv_bfloat16* __restrict__ xh, __nv_bfloat16* __restrict__ xl) {
    __shared__ float red[32];
    int srow = blockIdx.x;
    int t = threadIdx.x;
    int wid = ids[srow];
    int pid = pos[srow];
    float val[3];
    #pragma unroll
    for (int r = 0; r < 3; r++) {
        int i = t + r * 256;
        val[r] = ew[(size_t)wid * DIM + i] + ep[(size_t)pid * DIM + i] + et[i];
    }
    float mu = blk_sum256(val[0] + val[1] + val[2], red) * (1.0f / DIM);
    float vs = 0.0f;
    #pragma unroll
    for (int r = 0; r < 3; r++) { float d = val[r] - mu; vs += d * d; }
    float var = blk_sum256(vs, red) * (1.0f / DIM);
    float rs = rsqrtf(var + EPSF);
    #pragma unroll
    for (int r = 0; r < 3; r++) {
        int i = t + r * 256;
        float y = (val[r] - mu) * rs * g[i] + b[i];
        size_t idx = (size_t)srow * DIM + i;
        x[idx] = y;
        __nv_bfloat16 h = __float2bfloat16_rn(y);
        xh[idx] = h;
        xl[idx] = __float2bfloat16_rn(y - __bfloat162float(h));
    }
}

// ---------------- x = LN(x + d1 + d2), writes f32 + bf16 hi/lo ---------------
__global__ void lnres_kernel(float* __restrict__ x, const float* __restrict__ d1,
                             const float* __restrict__ d2,
                             const float* __restrict__ g, const float* __restrict__ b,
                             __nv_bfloat16* __restrict__ xh, __nv_bfloat16* __restrict__ xl) {
    __shared__ float red[32];
    int srow = blockIdx.x;
    int t = threadIdx.x;
    float val[3];
    #pragma unroll
    for (int r = 0; r < 3; r++) {
        int i = t + r * 256;
        size_t idx = (size_t)srow * DIM + i;
        val[r] = x[idx] + d1[idx] + d2[idx];
    }
    float mu = blk_sum256(val[0] + val[1] + val[2], red) * (1.0f / DIM);
    float vs = 0.0f;
    #pragma unroll
    for (int r = 0; r < 3; r++) { float d = val[r] - mu; vs += d * d; }
    float var = blk_sum256(vs, red) * (1.0f / DIM);
    float rs = rsqrtf(var + EPSF);
    #pragma unroll
    for (int r = 0; r < 3; r++) {
        int i = t + r * 256;
        float y = (val[r] - mu) * rs * g[i] + b[i];
        size_t idx = (size_t)srow * DIM + i;
        x[idx] = y;
        __nv_bfloat16 h = __float2bfloat16_rn(y);
        xh[idx] = h;
        xl[idx] = __float2bfloat16_rn(y - __bfloat162float(h));
    }
}

// ---------------- fused weight prep: w1 | w2 | wo | qkv-concat ---------------
__device__ __forceinline__ void split4(const float* __restrict__ s,
                                       __nv_bfloat16* __restrict__ hi,
                                       __nv_bfloat16* __restrict__ lo, int i) {
    float4 v = ((const float4*)s)[i];
    __nv_bfloat16 h0 = __float2bfloat16_rn(v.x), h1 = __float2bfloat16_rn(v.y);
    __nv_bfloat16 h2 = __float2bfloat16_rn(v.z), h3 = __float2bfloat16_rn(v.w);
    uint2 hp, lp;
    hp.x = ((uint32_t)*(uint16_t*)&h0) | ((uint32_t)*(uint16_t*)&h1 << 16);
    hp.y = ((uint32_t)*(uint16_t*)&h2) | ((uint32_t)*(uint16_t*)&h3 << 16);
    lp.x = pack_bf16x2(v.x - __bfloat162float(h0), v.y - __bfloat162float(h1));
    lp.y = pack_bf16x2(v.z - __bfloat162float(h2), v.w - __bfloat162float(h3));
    ((uint2*)hi)[i] = hp;
    ((uint2*)lo)[i] = lp;
}

__global__ void prep_kernel(const float* __restrict__ w1, const float* __restrict__ w2,
                            const float* __restrict__ wo,
                            const float* __restrict__ Wq, const float* __restrict__ Wk,
                            const float* __restrict__ Wv, const float* __restrict__ bq,
                            const float* __restrict__ bk, const float* __restrict__ bv,
                            __nv_bfloat16* __restrict__ w1h, __nv_bfloat16* __restrict__ w1l,
                            __nv_bfloat16* __restrict__ w2h, __nv_bfloat16* __restrict__ w2l,
                            __nv_bfloat16* __restrict__ woh, __nv_bfloat16* __restrict__ wol,
                            __nv_bfloat16* __restrict__ Wh, __nv_bfloat16* __restrict__ Wl,
                            float* __restrict__ bc) {
    int b = blockIdx.x;
    int tid = threadIdx.x;
    if (b < 2304) {
        split4(w1, w1h, w1l, b * 256 + tid);
    } else if (b < 4608) {
        split4(w2, w2h, w2l, (b - 2304) * 256 + tid);
    } else if (b < 5184) {
        split4(wo, woh, wol, (b - 4608) * 256 + tid);
    } else {
        int i4 = (b - 5184) * 256 + tid;
        int k = i4 / (DIM / 4);
        int n4 = i4 % (DIM / 4);
        const float* srcs[3] = {Wq, Wk, Wv};
        #pragma unroll
        for (int s = 0; s < 3; s++) {
            float4 v = ((const float4*)srcs[s])[i4];
            __nv_bfloat16 h0 = __float2bfloat16_rn(v.x), h1 = __float2bfloat16_rn(v.y);
            __nv_bfloat16 h2 = __float2bfloat16_rn(v.z), h3 = __float2bfloat16_rn(v.w);
            uint2 hp, lp;
            hp.x = ((uint32_t)*(uint16_t*)&h0) | ((uint32_t)*(uint16_t*)&h1 << 16);
            hp.y = ((uint32_t)*(uint16_t*)&h2) | ((uint32_t)*(uint16_t*)&h3 << 16);
            lp.x = pack_bf16x2(v.x - __bfloat162float(h0), v.y - __bfloat162float(h1));
            lp.y = pack_bf16x2(v.z - __bfloat162float(h2), v.w - __bfloat162float(h3));
            int e = k * 3 * DIM + s * DIM + n4 * 4;
            ((uint2*)Wh)[e >> 2] = hp;
            ((uint2*)Wl)[e >> 2] = lp;
        }
        if (i4 < DIM / 4) {
            ((float4*)bc)[i4] = ((const float4*)bq)[i4];
            ((float4*)(bc + DIM))[i4] = ((const float4*)bk)[i4];
            ((float4*)(bc + 2 * DIM))[i4] = ((const float4*)bv)[i4];
        }
    }
}

// ---------------- bf16x3 tensor-core GEMM ------------------------------------
// 3-stage cp.async ring, ONE barrier per k32 step:
//  wait_group(1) ; __syncthreads ; issue(t+2) ; compute(buf t%3)
// The prefetch for t+2 writes buffer (t-1)%3, whose last reader (compute t-1)
// finished before this iteration's barrier -> no trailing barrier needed.
// __launch_bounds__(256, 2): regs capped at 128 -> 2 blocks/SM.
template <int BM, int OUT>
__global__ __launch_bounds__(256, 2) void tgemm_kernel(
    const __nv_bfloat16* __restrict__ Ah, const __nv_bfloat16* __restrict__ Al,
    const __nv_bfloat16* __restrict__ Bh, const __nv_bfloat16* __restrict__ Bl,
    const float* __restrict__ bias, float* __restrict__ C, float* __restrict__ C2,
    __nv_bfloat16* __restrict__ Chi, __nv_bfloat16* __restrict__ Clo,
    int M, int N, int K, int lda) {
    constexpr int MT = BM / 64;
    constexpr int OFF_AL = BM * 64;
    constexpr int OFF_BH = 2 * BM * 64;
    constexpr int OFF_BL = 2 * BM * 64 + 8192;
    constexpr int STAGE  = 2 * BM * 64 + 16384;
    constexpr int AITERS = BM * 4 / 256;

    extern __shared__ __align__(16) unsigned char smem_raw[];
    uint32_t smemb = (uint32_t)__cvta_generic_to_shared(smem_raw);

    const int bx = blockIdx.x;
    const int by = blockIdx.y;
    const int Klocal = K / gridDim.z;
    const int kbase = blockIdx.z * Klocal;
    const int tid = threadIdx.x;
    const int lane = tid & 31;
    const int wid = tid >> 5;
    const int warpM = wid & 3;
    const int warpN = wid >> 2;
    const int gid = lane >> 2;
    const int tig = lane & 3;
    const int mBase = warpM * 16 * MT;
    const int nBase = warpN * 64;
    const int rowbase = by * BM;
    const int colbase = bx * 128;

    float acc[MT][8][4];
    #pragma unroll
    for (int mt = 0; mt < MT; mt++)
        #pragma unroll
        for (int nt = 0; nt < 8; nt++)
            #pragma unroll
            for (int r = 0; r < 4; r++) acc[mt][nt][r] = 0.0f;

    auto issue = [&](int buf, int k0) {
        uint32_t sb = smemb + buf * STAGE;
        #pragma unroll
        for (int it = 0; it < AITERS; it++) {
            int idx = tid + it * 256;
            int r = idx >> 2, ch = idx & 3;
            size_t go = (size_t)(rowbase + r) * lda + kbase + k0 + ch * 8;
            uint32_t so = (uint32_t)(r * 64 + ((ch ^ ((r >> 1) & 3)) << 4));
            cp16(sb + so, Ah + go);
            cp16(sb + OFF_AL + so, Al + go);
        }
        #pragma unroll
        for (int it = 0; it < 2; it++) {
            int idx = tid + it * 256;
            int krow = idx >> 4, ch = idx & 15;
            size_t go = (size_t)(kbase + k0 + krow) * N + colbase + ch * 8;
            uint32_t so = (uint32_t)(krow * 256 + ((ch ^ (krow & 7)) << 4));
            cp16(sb + OFF_BH + so, Bh + go);
            cp16(sb + OFF_BL + so, Bl + go);
        }
        asm volatile("cp.async.commit_group;" ::: "memory");
    };

    const int KT = Klocal >> 5;
    issue(0, 0);
    if (KT > 1) issue(1, 32);

    const int lane15 = lane & 15;
    const int laneh = lane >> 4;
    const int bk = lane & 15;
    const int bs = (lane >> 4) & 1;

    int buf = 0;
    for (int t = 0; t < KT; t++) {
        if (t + 1 < KT) {
            asm volatile("cp.async.wait_group 1;" ::: "memory");
        } else {
            asm volatile("cp.async.wait_group 0;" ::: "memory");
        }
        __syncthreads();
        if (t + 2 < KT) {
            int nb = buf + 2;
            if (nb >= 3) nb -= 3;
            issue(nb, (t + 2) * 32);
        }

        uint32_t sb = smemb + buf * STAGE;
        #pragma unroll
        for (int kk = 0; kk < 2; kk++) {
            uint32_t aHi[MT][4], aLo[MT][4];
            #pragma unroll
            for (int mt = 0; mt < MT; mt++) {
                int row = mBase + mt * 16 + lane15;
                int ch = (kk * 2 + laneh) ^ ((row >> 1) & 3);
                uint32_t ad = sb + (uint32_t)(row * 64 + (ch << 4));
                ldsm4(aHi[mt][0], aHi[mt][1], aHi[mt][2], aHi[mt][3], ad);
                ldsm4(aLo[mt][0], aLo[mt][1], aLo[mt][2], aLo[mt][3], ad + OFF_AL);
            }
            int krow = kk * 16 + bk;
            uint32_t bRow = sb + OFF_BH + (uint32_t)(krow * 256);
            #pragma unroll
            for (int nt2 = 0; nt2 < 4; nt2++) {
                uint32_t ch = (uint32_t)((((warpN * 8 + nt2 * 2 + bs) ^ (bk & 7))) * 16);
                uint32_t bh0, bh1, bh2, bh3, bl0, bl1, bl2, bl3;
                ldsm4t(bh0, bh1, bh2, bh3, bRow + ch);
                ldsm4t(bl0, bl1, bl2, bl3, bRow + (OFF_BL - OFF_BH) + ch);
                #pragma unroll
                for (int mt = 0; mt < MT; mt++) {
                    float* a0 = acc[mt][nt2 * 2];
                    mma_bf16(a0[0], a0[1], a0[2], a0[3],
                             aHi[mt][0], aHi[mt][1], aHi[mt][2], aHi[mt][3], bh0, bh1);
                    mma_bf16(a0[0], a0[1], a0[2], a0[3],
                             aHi[mt][0], aHi[mt][1], aHi[mt][2], aHi[mt][3], bl0, bl1);
                    mma_bf16(a0[0], a0[1], a0[2], a0[3],
                             aLo[mt][0], aLo[mt][1], aLo[mt][2], aLo[mt][3], bh0, bh1);
                    float* a1 = acc[mt][nt2 * 2 + 1];
                    mma_bf16(a1[0], a1[1], a1[2], a1[3],
                             aHi[mt][0], aHi[mt][1], aHi[mt][2], aHi[mt][3], bh2, bh3);
                    mma_bf16(a1[0], a1[1], a1[2], a1[3],
                             aHi[mt][0], aHi[mt][1], aHi[mt][2], aHi[mt][3], bl2, bl3);
                    mma_bf16(a1[0], a1[1], a1[2], a1[3],
                             aLo[mt][0], aLo[mt][1], aLo[mt][2], aLo[mt][3], bh2, bh3);
                }
            }
        }
        buf++;
        if (buf == 3) buf = 0;
    }

    float* Cout = (blockIdx.z == 0) ? C : C2;
    const bool addb = (blockIdx.z == 0);
    #pragma unroll
    for (int nt = 0; nt < 8; nt++) {
        int col = colbase + nBase + nt * 8 + tig * 2;
        float b0 = addb ? bias[col] : 0.0f;
        float b1 = addb ? bias[col + 1] : 0.0f;
        #pragma unroll
        for (int mt = 0; mt < MT; mt++) {
            int row0 = rowbase + mBase + mt * 16 + gid;
            float v0 = acc[mt][nt][0] + b0;
            float v1 = acc[mt][nt][1] + b1;
            float v2 = acc[mt][nt][2] + b0;
            float v3 = acc[mt][nt][3] + b1;
            if (OUT == 0) {
                *(float2*)(Cout + (size_t)row0 * N + col) = make_float2(v0, v1);
                *(float2*)(Cout + (size_t)(row0 + 8) * N + col) = make_float2(v2, v3);
            } else {
                if (OUT == 2) {
                    v0 = gelu_exact(v0); v1 = gelu_exact(v1);
                    v2 = gelu_exact(v2); v3 = gelu_exact(v3);
                }
                size_t i0 = ((size_t)row0 * N + col) >> 1;
                size_t i1 = ((size_t)(row0 + 8) * N + col) >> 1;
                __nv_bfloat16 h0 = __float2bfloat16_rn(v0), h1 = __float2bfloat16_rn(v1);
                __nv_bfloat16 h2 = __float2bfloat16_rn(v2), h3 = __float2bfloat16_rn(v3);
                ((uint32_t*)Chi)[i0] = ((uint32_t)*(uint16_t*)&h0) | ((uint32_t)*(uint16_t*)&h1 << 16);
                ((uint32_t*)Chi)[i1] = ((uint32_t)*(uint16_t*)&h2) | ((uint32_t)*(uint16_t*)&h3 << 16);
                ((uint32_t*)Clo)[i0] = pack_bf16x2(v0 - __bfloat162float(h0), v1 - __bfloat162float(h1));
                ((uint32_t*)Clo)[i1] = pack_bf16x2(v2 - __bfloat162float(h2), v3 - __bfloat162float(h3));
            }
        }
    }
}

// ---------------- tensor-core sliding-window flash attention ------------------
#define ATT_SMEM (65536 + 256)
__global__ __launch_bounds__(128) void attn_mma_kernel(
    const __nv_bfloat16* __restrict__ qkvh, const __nv_bfloat16* __restrict__ qkvl,
    const int* __restrict__ mask,
    __nv_bfloat16* __restrict__ oh, __nv_bfloat16* __restrict__ ol) {
    extern __shared__ __align__(16) unsigned char asmem[];
    const uint32_t sb = (uint32_t)__cvta_generic_to_shared(asmem);
    const uint32_t QH = sb, QL = sb + 16384;
    int* mskbuf = (int*)(asmem + 65536);

    const int h = blockIdx.y;
    const int q0 = blockIdx.x * 128;
    const int tid = threadIdx.x, lane = tid & 31, wid = tid >> 5;
    const int gid = lane >> 2, tig = lane & 3;
    const int mBase = wid * 32;
    const int STR = 3 * DIM;
    const int NC = (128 + 2 * WIN) / 32;

    auto issueKV = [&](int st, int c) {
        uint32_t kb = sb + 32768 + st * 16384;
        #pragma unroll
        for (int i = 0; i < 2; i++) {
            int idx = tid + i * 128;
            int row = idx >> 3, ch = idx & 7;
            int kp = c + row;
            int kc = kp < 0 ? 0 : (kp >= SEQ ? SEQ - 1 : kp);
            size_t gk = (size_t)kc * STR + DIM + h * 64 + ch * 8;
            size_t gv = (size_t)kc * STR + 2 * DIM + h * 64 + ch * 8;
            uint32_t so = (uint32_t)(row * 128 + ((ch ^ (row & 7)) << 4));
            cp16(kb + so, qkvh + gk);
            cp16(kb + 4096 + so, qkvl + gk);
            cp16(kb + 8192 + so, qkvh + gv);
            cp16(kb + 12288 + so, qkvl + gv);
        }
        if (tid < 32) {
            int kp = c + tid;
            mskbuf[st * 32 + tid] = (kp >= 0 && kp < SEQ) ? mask[kp] : 0;
        }
    };

    #pragma unroll
    for (int i = 0; i < 8; i++) {
        int idx = tid + i * 128;
        int row = idx >> 3, ch = idx & 7;
        size_t gq = (size_t)(q0 + row) * STR + h * 64 + ch * 8;
        uint32_t so = (uint32_t)(row * 128 + ((ch ^ (row & 7)) << 4));
        cp16(QH + so, qkvh + gq);
        cp16(QL + so, qkvl + gq);
    }
    const int cstart = q0 - WIN;
    issueKV(0, cstart);
    asm volatile("cp.async.commit_group;" ::: "memory");

    uint32_t Qhi[2][4][4], Qlo[2][4][4];
    float O[2][8][4];
    #pragma unroll
    for (int mt = 0; mt < 2; mt++)
        #pragma unroll
        for (int dj = 0; dj < 8; dj++)
            #pragma unroll
            for (int r = 0; r < 4; r++) O[mt][dj][r] = 0.0f;
    float mrow[2][2] = {{-1e30f, -1e30f}, {-1e30f, -1e30f}};
    float lrow[2][2] = {{0.0f, 0.0f}, {0.0f, 0.0f}};

    const int warpLo = q0 + mBase - WIN;
    const int warpHi = q0 + mBase + 31 + WIN;

    for (int t = 0; t < NC; t++) {
        const int c = cstart + t * 32;
        if (t + 1 < NC) {
            issueKV((t + 1) & 1, c + 32);
            asm volatile("cp.async.commit_group;" ::: "memory");
            asm volatile("cp.async.wait_group 1;" ::: "memory");
        } else {
            asm volatile("cp.async.wait_group 0;" ::: "memory");
        }
        __syncthreads();

        if (t == 0) {
            int arow = (lane & 7) + 8 * ((lane >> 3) & 1);
            int achsel = lane >> 4;
            #pragma unroll
            for (int mt = 0; mt < 2; mt++) {
                int row = mBase + mt * 16 + arow;
                #pragma unroll
                for (int kk = 0; kk < 4; kk++) {
                    int chunk = kk * 2 + achsel;
                    uint32_t ad = (uint32_t)(row * 128 + ((chunk ^ (row & 7)) << 4));
                    ldsm4(Qhi[mt][kk][0], Qhi[mt][kk][1], Qhi[mt][kk][2], Qhi[mt][kk][3], QH + ad);
                    ldsm4(Qlo[mt][kk][0], Qlo[mt][kk][1], Qlo[mt][kk][2], Qlo[mt][kk][3], QL + ad);
                }
            }
        }

        if (c + 31 >= warpLo && c <= warpHi) {
            const uint32_t KB = sb + 32768 + (t & 1) * 16384;
            const int* msk = mskbuf + (t & 1) * 32;

            float S[2][4][4];
            #pragma unroll
            for (int mt = 0; mt < 2; mt++)
                #pragma unroll
                for (int j = 0; j < 4; j++)
                    #pragma unroll
                    for (int r = 0; r < 4; r++) S[mt][j][r] = 0.0f;

            #pragma unroll
            for (int j = 0; j < 4; j++) {
                uint32_t kh[4][2], kl[4][2];
                int krow = j * 8 + (lane & 7);
                #pragma unroll
                for (int h32 = 0; h32 < 2; h32++) {
                    int chunk = h32 * 4 + (lane >> 3);
                    uint32_t ad = (uint32_t)(krow * 128 + ((chunk ^ (krow & 7)) << 4));
                    uint32_t r0, r1, r2, r3;
                    ldsm4(r0, r1, r2, r3, KB + ad);
                    kh[h32 * 2][0] = r0; kh[h32 * 2][1] = r1;
                    kh[h32 * 2 + 1][0] = r2; kh[h32 * 2 + 1][1] = r3;
                    ldsm4(r0, r1, r2, r3, KB + 4096 + ad);
                    kl[h32 * 2][0] = r0; kl[h32 * 2][1] = r1;
                    kl[h32 * 2 + 1][0] = r2; kl[h32 * 2 + 1][1] = r3;
                }
                #pragma unroll
                for (int kk = 0; kk < 4; kk++)
                    #pragma unroll
                    for (int mt = 0; mt < 2; mt++) {
                        float* s = S[mt][j];
                        mma_bf16(s[0], s[1], s[2], s[3],
                                 Qhi[mt][kk][0], Qhi[mt][kk][1], Qhi[mt][kk][2], Qhi[mt][kk][3],
                                 kh[kk][0], kh[kk][1]);
                        mma_bf16(s[0], s[1], s[2], s[3],
                                 Qhi[mt][kk][0], Qhi[mt][kk][1], Qhi[mt][kk][2], Qhi[mt][kk][3],
                                 kl[kk][0], kl[kk][1]);
                        mma_bf16(s[0], s[1], s[2], s[3],
                                 Qlo[mt][kk][0], Qlo[mt][kk][1], Qlo[mt][kk][2], Qlo[mt][kk][3],
                                 kh[kk][0], kh[kk][1]);
                    }
            }

            float p[2][4][4];
            #pragma unroll
            for (int mt = 0; mt < 2; mt++) {
                int rA = q0 + mBase + mt * 16 + gid;
                int rB = rA + 8;
                float mxA = -1e30f, mxB = -1e30f;
                #pragma unroll
                for (int j = 0; j < 4; j++) {
                    int c0 = c + j * 8 + tig * 2;
                    int c1 = c0 + 1;
                    int mk0 = msk[j * 8 + tig * 2];
                    int mk1 = msk[j * 8 + tig * 2 + 1];
                    bool v00 = mk0 && (c0 >= rA - WIN) && (c0 <= rA + WIN);
                    bool v01 = mk1 && (c1 >= rA - WIN) && (c1 <= rA + WIN);
                    bool v10 = mk0 && (c0 >= rB - WIN) && (c0 <= rB + WIN);
                    bool v11 = mk1 && (c1 >= rB - WIN) && (c1 <= rB + WIN);
                    S[mt][j][0] = v00 ? S[mt][j][0] * 0.125f : -1e30f;
                    S[mt][j][1] = v01 ? S[mt][j][1] * 0.125f : -1e30f;
                    S[mt][j][2] = v10 ? S[mt][j][2] * 0.125f : -1e30f;
                    S[mt][j][3] = v11 ? S[mt][j][3] * 0.125f : -1e30f;
                    mxA = fmaxf(mxA, fmaxf(S[mt][j][0], S[mt][j][1]));
                    mxB = fmaxf(mxB, fmaxf(S[mt][j][2], S[mt][j][3]));
                }
                mxA = fmaxf(mxA, __shfl_xor_sync(0xffffffffu, mxA, 1));
                mxA = fmaxf(mxA, __shfl_xor_sync(0xffffffffu, mxA, 2));
                mxB = fmaxf(mxB, __shfl_xor_sync(0xffffffffu, mxB, 1));
                mxB = fmaxf(mxB, __shfl_xor_sync(0xffffffffu, mxB, 2));
                float mnA = fmaxf(mrow[mt][0], mxA);
                float mnB = fmaxf(mrow[mt][1], mxB);
                float scA = __expf(mrow[mt][0] - mnA);
                float scB = __expf(mrow[mt][1] - mnB);
                mrow[mt][0] = mnA; mrow[mt][1] = mnB;
                float sA = 0.0f, sB = 0.0f;
                #pragma unroll
                for (int j = 0; j < 4; j++) {
                    float p0 = (S[mt][j][0] > -1e29f) ? __expf(S[mt][j][0] - mnA) : 0.0f;
                    float p1 = (S[mt][j][1] > -1e29f) ? __expf(S[mt][j][1] - mnA) : 0.0f;
                    float p2 = (S[mt][j][2] > -1e29f) ? __expf(S[mt][j][2] - mnB) : 0.0f;
                    float p3 = (S[mt][j][3] > -1e29f) ? __expf(S[mt][j][3] - mnB) : 0.0f;
                    p[mt][j][0] = p0; p[mt][j][1] = p1; p[mt][j][2] = p2; p[mt][j][3] = p3;
                    sA += p0 + p1; sB += p2 + p3;
                }
                sA += __shfl_xor_sync(0xffffffffu, sA, 1);
                sA += __shfl_xor_sync(0xffffffffu, sA, 2);
                sB += __shfl_xor_sync(0xffffffffu, sB, 1);
                sB += __shfl_xor_sync(0xffffffffu, sB, 2);
                lrow[mt][0] = lrow[mt][0] * scA + sA;
                lrow[mt][1] = lrow[mt][1] * scB + sB;
                #pragma unroll
                for (int dj = 0; dj < 8; dj++) {
                    O[mt][dj][0] *= scA; O[mt][dj][1] *= scA;
                    O[mt][dj][2] *= scB; O[mt][dj][3] *= scB;
                }
            }

            uint32_t Phi[2][2][4], Plo[2][2][4];
            #pragma unroll
            for (int mt = 0; mt < 2; mt++)
                #pragma unroll
                for (int kk = 0; kk < 2; kk++) {
                    #pragma unroll
                    for (int q = 0; q < 4; q++) {
                        int j = 2 * kk + (q >> 1);
                        int r0 = (q & 1) * 2;
                        float x0 = p[mt][j][r0], x1 = p[mt][j][r0 + 1];
                        __nv_bfloat162 hh = __floats2bfloat162_rn(x0, x1);
                        Phi[mt][kk][q] = *(uint32_t*)&hh;
                        Plo[mt][kk][q] = pack_bf16x2(x0 - __bfloat162float(hh.x),
                                                     x1 - __bfloat162float(hh.y));
                    }
                }

            #pragma unroll
            for (int djp = 0; djp < 4; djp++) {
                #pragma unroll
                for (int kk = 0; kk < 2; kk++) {
                    int vrow = kk * 16 + (lane & 7) + 8 * ((lane >> 3) & 1);
                    int chunk = djp * 2 + (lane >> 4);
                    uint32_t ad = (uint32_t)(vrow * 128 + ((chunk ^ (vrow & 7)) << 4));
                    uint32_t h0, h1, h2, h3, l0, l1, l2, l3;
                    ldsm4t(h0, h1, h2, h3, KB + 8192 + ad);
                    ldsm4t(l0, l1, l2, l3, KB + 12288 + ad);
                    #pragma unroll
                    for (int mt = 0; mt < 2; mt++) {
                        float* o0 = O[mt][djp * 2];
                        float* o1 = O[mt][djp * 2 + 1];
                        mma_bf16(o0[0], o0[1], o0[2], o0[3],
                                 Phi[mt][kk][0], Phi[mt][kk][1], Phi[mt][kk][2], Phi[mt][kk][3],
                                 h0, h1);
                        mma_bf16(o0[0], o0[1], o0[2], o0[3],
                                 Plo[mt][kk][0], Plo[mt][kk][1], Plo[mt][kk][2], Plo[mt][kk][3],
                                 h0, h1);
                        mma_bf16(o0[0], o0[1], o0[2], o0[3],
                                 Phi[mt][kk][0], Phi[mt][kk][1], Phi[mt][kk][2], Phi[mt][kk][3],
                                 l0, l1);
                        mma_bf16(o1[0], o1[1], o1[2], o1[3],
                                 Phi[mt][kk][0], Phi[mt][kk][1], Phi[mt][kk][2], Phi[mt][kk][3],
                                 h2, h3);
                        mma_bf16(o1[0], o1[1], o1[2], o1[3],
                                 Plo[mt][kk][0], Plo[mt][kk][1], Plo[mt][kk][2], Plo[mt][kk][3],
                                 h2, h3);
                        mma_bf16(o1[0], o1[1], o1[2], o1[3],
                                 Phi[mt][kk][0], Phi[mt][kk][1], Phi[mt][kk][2], Phi[mt][kk][3],
                                 l2, l3);
                    }
                }
            }
        }
        __syncthreads();   // WAR guard
    }

    #pragma unroll
    for (int mt = 0; mt < 2; mt++) {
        float invA = (lrow[mt][0] > 0.0f) ? (1.0f / lrow[mt][0]) : 0.0f;
        float invB = (lrow[mt][1] > 0.0f) ? (1.0f / lrow[mt][1]) : 0.0f;
        int rA = q0 + mBase + mt * 16 + gid;
        int rB = rA + 8;
        #pragma unroll
        for (int dj = 0; dj < 8; dj++) {
            int col = h * 64 + dj * 8 + tig * 2;
            float v0 = O[mt][dj][0] * invA, v1 = O[mt][dj][1] * invA;
            float v2 = O[mt][dj][2] * invB, v3 = O[mt][dj][3] * invB;
            size_t iA = ((size_t)rA * DIM + col) >> 1;
            size_t iB = ((size_t)rB * DIM + col) >> 1;
            __nv_bfloat162 hA = __floats2bfloat162_rn(v0, v1);
            __nv_bfloat162 hB = __floats2bfloat162_rn(v2, v3);
            ((uint32_t*)oh)[iA] = *(uint32_t*)&hA;
            ((uint32_t*)oh)[iB] = *(uint32_t*)&hB;
            ((uint32_t*)ol)[iA] = pack_bf16x2(v0 - __bfloat162float(hA.x),
                                              v1 - __bfloat162float(hA.y));
            ((uint32_t*)ol)[iB] = pack_bf16x2(v2 - __bfloat162float(hB.x),
                                              v3 - __bfloat162float(hB.y));
        }
    }
}

// ---------------- classification heads (768 -> 512 relu -> nout) ------------
__global__ void head_kernel(const float* __restrict__ x, const float* __restrict__ W1,
                            const float* __restrict__ b1, const float* __restrict__ W2,
                            const float* __restrict__ b2, float* __restrict__ out, int nout) {
    __shared__ float xs[768];
    __shared__ float hsm[512];
    int t = threadIdx.x;
    for (int i = t; i < 768; i += 512) xs[i] = x[i];
    __syncthreads();
    float acc = b1[t];
    for (int kk = 0; kk < 768; kk++) acc += xs[kk] * W1[(size_t)kk * 512 + t];
    hsm[t] = fmaxf(acc, 0.0f);
    __syncthreads();
    if (t < nout) {
        float ov = b2[t];
        for (int kk = 0; kk < 512; kk++) ov += hsm[kk] * W2[(size_t)kk * nout + t];
        out[t] = ov;
    }
}

// ---------------- host launcher ---------------------------------------------
extern "C" void kernel_launch(void* const* d_in, const int* in_sizes, int n_in,
                              void* d_out, int out_size) {
    const int*   ids      = (const int*)d_in[0];
    const int*   mask     = (const int*)d_in[1];
    const float* emb_word = (const float*)d_in[2];
    const float* emb_pos  = (const float*)d_in[3];
    const float* emb_type = (const float*)d_in[4];
    const float* emb_g    = (const float*)d_in[5];
    const float* emb_b    = (const float*)d_in[6];
    const float* Wq = (const float*)d_in[7];
    const float* bq = (const float*)d_in[8];
    const float* Wk = (const float*)d_in[9];
    const float* bk = (const float*)d_in[10];
    const float* Wv = (const float*)d_in[11];
    const float* bv = (const float*)d_in[12];
    const float* Wo = (const float*)d_in[13];
    const float* bo = (const float*)d_in[14];
    const float* ln1g = (const float*)d_in[15];
    const float* ln1b = (const float*)d_in[16];
    const float* W1 = (const float*)d_in[17];
    const float* b1 = (const float*)d_in[18];
    const float* W2 = (const float*)d_in[19];
    const float* b2 = (const float*)d_in[20];
    const float* ln2g = (const float*)d_in[21];
    const float* ln2b = (const float*)d_in[22];
    const float* cW1 = (const float*)d_in[23];
    const float* cb1 = (const float*)d_in[24];
    const float* cW2 = (const float*)d_in[25];
    const float* cb2 = (const float*)d_in[26];
    const float* dW1 = (const float*)d_in[27];
    const float* db1 = (const float*)d_in[28];
    const float* dW2 = (const float*)d_in[29];
    const float* db2 = (const float*)d_in[30];
    float* out = (float*)d_out;

    float *x, *t, *t2, *bcat;
    int* pos;
    __nv_bfloat16 *xh, *xl, *qkvh, *qkvl, *ah, *al, *hh, *hl;
    __nv_bfloat16 *wqh, *wql, *w1h, *w1l, *w2h, *w2l, *woh, *wol;
    cudaGetSymbolAddress((void**)&x, g_x);
    cudaGetSymbolAddress((void**)&t, g_t);
    cudaGetSymbolAddress((void**)&t2, g_t2);
    cudaGetSymbolAddress((void**)&bcat, g_bcat);
    cudaGetSymbolAddress((void**)&pos, g_pos);
    cudaGetSymbolAddress((void**)&xh, g_xh);
    cudaGetSymbolAddress((void**)&xl, g_xl);
    cudaGetSymbolAddress((void**)&qkvh, g_qkvh);
    cudaGetSymbolAddress((void**)&qkvl, g_qkvl);
    cudaGetSymbolAddress((void**)&ah, g_ah);
    cudaGetSymbolAddress((void**)&al, g_al);
    cudaGetSymbolAddress((void**)&hh, g_hh);
    cudaGetSymbolAddress((void**)&hl, g_hl);
    cudaGetSymbolAddress((void**)&wqh, g_wqh);
    cudaGetSymbolAddress((void**)&wql, g_wql);
    cudaGetSymbolAddress((void**)&w1h, g_w1h);
    cudaGetSymbolAddress((void**)&w1l, g_w1l);
    cudaGetSymbolAddress((void**)&w2h, g_w2h);
    cudaGetSymbolAddress((void**)&w2l, g_w2l);
    cudaGetSymbolAddress((void**)&woh, g_woh);
    cudaGetSymbolAddress((void**)&wol, g_wol);

    const int SM128 = 3 * (2 * 128 * 64 + 16384);   // 98304 (3-stage)
    const int SM64  = 3 * (2 * 64 * 64 + 16384);    // 73728 (3-stage)
    cudaFuncSetAttribute(tgemm_kernel<128, 3>, cudaFuncAttributeMaxDynamicSharedMemorySize, SM128);
    cudaFuncSetAttribute(tgemm_kernel<128, 2>, cudaFuncAttributeMaxDynamicSharedMemorySize, SM128);
    cudaFuncSetAttribute(tgemm_kernel<64, 0>, cudaFuncAttributeMaxDynamicSharedMemorySize, SM64);
    cudaFuncSetAttribute(attn_mma_kernel, cudaFuncAttributeMaxDynamicSharedMemorySize, ATT_SMEM);

    pos_kernel<<<1, 1024>>>(mask, pos);
    embed_ln_kernel<<<SEQ, 256>>>(ids, pos, emb_word, emb_pos, emb_type, emb_g, emb_b, x, xh, xl);

    dim3 gqkv(3 * DIM / 128, SEQ / 128, 1);   // (18, 32)
    dim3 go(DIM / 128, SEQ / 64, 2);          // (6, 64, 2) split-K
    dim3 gff1(FFD / 128, SEQ / 128, 1);       // (24, 32)
    dim3 gff2(DIM / 128, SEQ / 64, 2);        // (6, 64, 2) split-K
    dim3 gattn(SEQ / 128, NH);

    for (int i = 0; i < NL; i++) {
        const float* wq = Wq + (size_t)i * DIM * DIM;
        const float* wk = Wk + (size_t)i * DIM * DIM;
        const float* wv = Wv + (size_t)i * DIM * DIM;
        const float* wo = Wo + (size_t)i * DIM * DIM;
        const float* w1 = W1 + (size_t)i * DIM * FFD;
        const float* w2 = W2 + (size_t)i * FFD * DIM;

        prep_kernel<<<5760, 256>>>(w1, w2, wo, wq, wk, wv,
                                   bq + i * DIM, bk + i * DIM, bv + i * DIM,
                                   w1h, w1l, w2h, w2l, woh, wol, wqh, wql, bcat);

        tgemm_kernel<128, 3><<<gqkv, 256, SM128>>>(xh, xl, wqh, wql, bcat, nullptr, nullptr,
                                                   qkvh, qkvl, SEQ, 3 * DIM, DIM, DIM);
        attn_mma_kernel<<<gattn, 128, ATT_SMEM>>>(qkvh, qkvl, mask, ah, al);
        tgemm_kernel<64, 0><<<go, 256, SM64>>>(ah, al, woh, wol, bo + i * DIM, t, t2,
                                               nullptr, nullptr, SEQ, DIM, DIM, DIM);
        lnres_kernel<<<SEQ, 256>>>(x, t, t2, ln1g + i * DIM, ln1b + i * DIM, xh, xl);
        tgemm_kernel<128, 2><<<gff1, 256, SM128>>>(xh, xl, w1h, w1l, b1 + i * FFD, nullptr,
                                                   nullptr, hh, hl, SEQ, FFD, DIM, DIM);
        tgemm_kernel<64, 0><<<gff2, 256, SM64>>>(hh, hl, w2h, w2l, b2 + i * DIM, t, t2,
                                                 nullptr, nullptr, SEQ, DIM, FFD, FFD);
        lnres_kernel<<<SEQ, 256>>>(x, t, t2, ln2g + i * DIM, ln2b + i * DIM, xh, xl);
    }

    head_kernel<<<1, 512>>>(x, cW1, cb1, cW2, cb2, out, 5);
    head_kernel<<<1, 512>>>(x, dW1, db1, dW2, db2, out + 5, 10);
}

// round 17
// speedup vs baseline: 1.0819x; 1.0154x over previous
#include <cuda_runtime.h>
#include <cuda_bf16.h>
#include <stdint.h>
#include <math.h>

#define SEQ 4096
#define DIM 768
#define NH  12
#define HD  64
#define NL  12
#define FFD 3072
#define WIN 256
#define EPSF 1e-5f

// ---------------- scratch (static device globals; no runtime allocation) ----
__device__ float g_x[SEQ * DIM];
__device__ float g_t[SEQ * DIM];
__device__ float g_t2[SEQ * DIM];
__device__ float g_t3[SEQ * DIM];
__device__ float g_t4[SEQ * DIM];
__device__ float g_bcat[3 * DIM];
__device__ int   g_pos[SEQ];

__device__ __nv_bfloat16 g_xh[SEQ * DIM],  g_xl[SEQ * DIM];
__device__ __nv_bfloat16 g_qkvh[SEQ * 3 * DIM], g_qkvl[SEQ * 3 * DIM];
__device__ __nv_bfloat16 g_ah[SEQ * DIM],  g_al[SEQ * DIM];
__device__ __nv_bfloat16 g_hh[SEQ * FFD],  g_hl[SEQ * FFD];
__device__ __nv_bfloat16 g_wqh[DIM * 3 * DIM], g_wql[DIM * 3 * DIM];
__device__ __nv_bfloat16 g_w1h[DIM * FFD], g_w1l[DIM * FFD];
__device__ __nv_bfloat16 g_w2h[FFD * DIM], g_w2l[FFD * DIM];
__device__ __nv_bfloat16 g_woh[DIM * DIM], g_wol[DIM * DIM];

// ---------------- helpers ---------------------------------------------------
__device__ __forceinline__ float gelu_exact(float x) {
    return 0.5f * x * (1.0f + erff(x * 0.70710678118654752f));
}

__device__ __forceinline__ uint32_t pack_bf16x2(float x, float y) {
    __nv_bfloat162 h = __floats2bfloat162_rn(x, y);
    return *(uint32_t*)&h;
}

__device__ __forceinline__ void mma_bf16(float& d0, float& d1, float& d2, float& d3,
                                         uint32_t a0, uint32_t a1, uint32_t a2, uint32_t a3,
                                         uint32_t b0, uint32_t b1) {
    asm volatile("mma.sync.aligned.m16n8k16.row.col.f32.bf16.bf16.f32 "
                 "{%0,%1,%2,%3}, {%4,%5,%6,%7}, {%8,%9}, {%0,%1,%2,%3};"
                 : "+f"(d0), "+f"(d1), "+f"(d2), "+f"(d3)
                 : "r"(a0), "r"(a1), "r"(a2), "r"(a3), "r"(b0), "r"(b1));
}

__device__ __forceinline__ void ldsm4(uint32_t& r0, uint32_t& r1, uint32_t& r2, uint32_t& r3,
                                      uint32_t addr) {
    asm volatile("ldmatrix.sync.aligned.m8n8.x4.shared.b16 {%0,%1,%2,%3}, [%4];"
                 : "=r"(r0), "=r"(r1), "=r"(r2), "=r"(r3) : "r"(addr));
}

__device__ __forceinline__ void ldsm4t(uint32_t& r0, uint32_t& r1, uint32_t& r2, uint32_t& r3,
                                       uint32_t addr) {
    asm volatile("ldmatrix.sync.aligned.m8n8.x4.trans.shared.b16 {%0,%1,%2,%3}, [%4];"
                 : "=r"(r0), "=r"(r1), "=r"(r2), "=r"(r3) : "r"(addr));
}

__device__ __forceinline__ void cp16(uint32_t saddr, const void* gaddr) {
    asm volatile("cp.async.cg.shared.global [%0], [%1], 16;" :: "r"(saddr), "l"(gaddr));
}

__device__ __forceinline__ float blk_sum256(float v, float* red) {
    #pragma unroll
    for (int o = 16; o > 0; o >>= 1) v += __shfl_down_sync(0xffffffffu, v, o);
    int w = threadIdx.x >> 5;
    if ((threadIdx.x & 31) == 0) red[w] = v;
    __syncthreads();
    if (threadIdx.x < 32) {
        v = (threadIdx.x < 8) ? red[threadIdx.x] : 0.0f;
        #pragma unroll
        for (int o = 4; o > 0; o >>= 1) v += __shfl_down_sync(0xffffffffu, v, o);
        if (threadIdx.x == 0) red[0] = v;
    }
    __syncthreads();
    float r = red[0];
    __syncthreads();
    return r;
}

// ---------------- pos_ids = cumsum(mask)*mask + 1 ---------------------------
__global__ void pos_kernel(const int* __restrict__ mask, int* __restrict__ pos) {
    __shared__ int ss[1024];
    int t = threadIdx.x;
    int m0 = mask[t * 4 + 0], m1 = mask[t * 4 + 1];
    int m2 = mask[t * 4 + 2], m3 = mask[t * 4 + 3];
    int s = m0 + m1 + m2 + m3;
    ss[t] = s;
    __syncthreads();
    for (int off = 1; off < 1024; off <<= 1) {
        int vprev = (t >= off) ? ss[t - off] : 0;
        __syncthreads();
        ss[t] += vprev;
        __syncthreads();
    }
    int run = ss[t] - s;
    run += m0; pos[t * 4 + 0] = run * m0 + 1;
    run += m1; pos[t * 4 + 1] = run * m1 + 1;
    run += m2; pos[t * 4 + 2] = run * m2 + 1;
    run += m3; pos[t * 4 + 3] = run * m3 + 1;
}

// ---------------- embedding + layernorm (writes f32 + bf16 hi/lo) -----------
__global__ void embed_ln_kernel(const int* __restrict__ ids, const int* __restrict__ pos,
                                const float* __restrict__ ew, const float* __restrict__ ep,
                                const float* __restrict__ et, const float* __restrict__ g,
                                const float* __restrict__ b, float* __restrict__ x,
                                __nv_bfloat16* __restrict__ xh, __nv_bfloat16* __restrict__ xl) {
    __shared__ float red[32];
    int srow = blockIdx.x;
    int t = threadIdx.x;
    int wid = ids[srow];
    int pid = pos[srow];
    float val[3];
    #pragma unroll
    for (int r = 0; r < 3; r++) {
        int i = t + r * 256;
        val[r] = ew[(size_t)wid * DIM + i] + ep[(size_t)pid * DIM + i] + et[i];
    }
    float mu = blk_sum256(val[0] + val[1] + val[2], red) * (1.0f / DIM);
    float vs = 0.0f;
    #pragma unroll
    for (int r = 0; r < 3; r++) { float d = val[r] - mu; vs += d * d; }
    float var = blk_sum256(vs, red) * (1.0f / DIM);
    float rs = rsqrtf(var + EPSF);
    #pragma unroll
    for (int r = 0; r < 3; r++) {
        int i = t + r * 256;
        float y = (val[r] - mu) * rs * g[i] + b[i];
        size_t idx = (size_t)srow * DIM + i;
        x[idx] = y;
        __nv_bfloat16 h = __float2bfloat16_rn(y);
        xh[idx] = h;
        xl[idx] = __float2bfloat16_rn(y - __bfloat162float(h));
    }
}

// ---------------- x = LN(x + d1 + d2 + d3 + d4), writes f32 + bf16 hi/lo ----
__global__ void lnres_kernel(float* __restrict__ x, const float* __restrict__ d1,
                             const float* __restrict__ d2, const float* __restrict__ d3,
                             const float* __restrict__ d4,
                             const float* __restrict__ g, const float* __restrict__ b,
                             __nv_bfloat16* __restrict__ xh, __nv_bfloat16* __restrict__ xl) {
    __shared__ float red[32];
    int srow = blockIdx.x;
    int t = threadIdx.x;
    float val[3];
    #pragma unroll
    for (int r = 0; r < 3; r++) {
        int i = t + r * 256;
        size_t idx = (size_t)srow * DIM + i;
        val[r] = x[idx] + ((d1[idx] + d2[idx]) + (d3[idx] + d4[idx]));
    }
    float mu = blk_sum256(val[0] + val[1] + val[2], red) * (1.0f / DIM);
    float vs = 0.0f;
    #pragma unroll
    for (int r = 0; r < 3; r++) { float d = val[r] - mu; vs += d * d; }
    float var = blk_sum256(vs, red) * (1.0f / DIM);
    float rs = rsqrtf(var + EPSF);
    #pragma unroll
    for (int r = 0; r < 3; r++) {
        int i = t + r * 256;
        float y = (val[r] - mu) * rs * g[i] + b[i];
        size_t idx = (size_t)srow * DIM + i;
        x[idx] = y;
        __nv_bfloat16 h = __float2bfloat16_rn(y);
        xh[idx] = h;
        xl[idx] = __float2bfloat16_rn(y - __bfloat162float(h));
    }
}

// ---------------- fused weight prep: w1 | w2 | wo | qkv-concat ---------------
__device__ __forceinline__ void split4(const float* __restrict__ s,
                                       __nv_bfloat16* __restrict__ hi,
                                       __nv_bfloat16* __restrict__ lo, int i) {
    float4 v = ((const float4*)s)[i];
    __nv_bfloat16 h0 = __float2bfloat16_rn(v.x), h1 = __float2bfloat16_rn(v.y);
    __nv_bfloat16 h2 = __float2bfloat16_rn(v.z), h3 = __float2bfloat16_rn(v.w);
    uint2 hp, lp;
    hp.x = ((uint32_t)*(uint16_t*)&h0) | ((uint32_t)*(uint16_t*)&h1 << 16);
    hp.y = ((uint32_t)*(uint16_t*)&h2) | ((uint32_t)*(uint16_t*)&h3 << 16);
    lp.x = pack_bf16x2(v.x - __bfloat162float(h0), v.y - __bfloat162float(h1));
    lp.y = pack_bf16x2(v.z - __bfloat162float(h2), v.w - __bfloat162float(h3));
    ((uint2*)hi)[i] = hp;
    ((uint2*)lo)[i] = lp;
}

__global__ void prep_kernel(const float* __restrict__ w1, const float* __restrict__ w2,
                            const float* __restrict__ wo,
                            const float* __restrict__ Wq, const float* __restrict__ Wk,
                            const float* __restrict__ Wv, const float* __restrict__ bq,
                            const float* __restrict__ bk, const float* __restrict__ bv,
                            __nv_bfloat16* __restrict__ w1h, __nv_bfloat16* __restrict__ w1l,
                            __nv_bfloat16* __restrict__ w2h, __nv_bfloat16* __restrict__ w2l,
                            __nv_bfloat16* __restrict__ woh, __nv_bfloat16* __restrict__ wol,
                            __nv_bfloat16* __restrict__ Wh, __nv_bfloat16* __restrict__ Wl,
                            float* __restrict__ bc) {
    int b = blockIdx.x;
    int tid = threadIdx.x;
    if (b < 2304) {
        split4(w1, w1h, w1l, b * 256 + tid);
    } else if (b < 4608) {
        split4(w2, w2h, w2l, (b - 2304) * 256 + tid);
    } else if (b < 5184) {
        split4(wo, woh, wol, (b - 4608) * 256 + tid);
    } else {
        int i4 = (b - 5184) * 256 + tid;
        int k = i4 / (DIM / 4);
        int n4 = i4 % (DIM / 4);
        const float* srcs[3] = {Wq, Wk, Wv};
        #pragma unroll
        for (int s = 0; s < 3; s++) {
            float4 v = ((const float4*)srcs[s])[i4];
            __nv_bfloat16 h0 = __float2bfloat16_rn(v.x), h1 = __float2bfloat16_rn(v.y);
            __nv_bfloat16 h2 = __float2bfloat16_rn(v.z), h3 = __float2bfloat16_rn(v.w);
            uint2 hp, lp;
            hp.x = ((uint32_t)*(uint16_t*)&h0) | ((uint32_t)*(uint16_t*)&h1 << 16);
            hp.y = ((uint32_t)*(uint16_t*)&h2) | ((uint32_t)*(uint16_t*)&h3 << 16);
            lp.x = pack_bf16x2(v.x - __bfloat162float(h0), v.y - __bfloat162float(h1));
            lp.y = pack_bf16x2(v.z - __bfloat162float(h2), v.w - __bfloat162float(h3));
            int e = k * 3 * DIM + s * DIM + n4 * 4;
            ((uint2*)Wh)[e >> 2] = hp;
            ((uint2*)Wl)[e >> 2] = lp;
        }
        if (i4 < DIM / 4) {
            ((float4*)bc)[i4] = ((const float4*)bq)[i4];
            ((float4*)(bc + DIM))[i4] = ((const float4*)bk)[i4];
            ((float4*)(bc + 2 * DIM))[i4] = ((const float4*)bv)[i4];
        }
    }
}

// ---------------- bf16x3 tensor-core GEMM ------------------------------------
// BM=128, BN=128, BK=32. 3-stage cp.async ring, one barrier per k-step.
// split-K via gridDim.z (up to 4): z=0 -> C (+bias), z=1..3 -> C2/C3/C4.
// OUT=0 f32; OUT=2 gelu->bf16 hi/lo; OUT=3 ->bf16 hi/lo.
template <int OUT>
__global__ __launch_bounds__(256, 2) void tgemm_kernel(
    const __nv_bfloat16* __restrict__ Ah, const __nv_bfloat16* __restrict__ Al,
    const __nv_bfloat16* __restrict__ Bh, const __nv_bfloat16* __restrict__ Bl,
    const float* __restrict__ bias, float* __restrict__ C, float* __restrict__ C2,
    float* __restrict__ C3, float* __restrict__ C4,
    __nv_bfloat16* __restrict__ Chi, __nv_bfloat16* __restrict__ Clo,
    int M, int N, int K, int lda) {
    constexpr int BM = 128;
    constexpr int MT = 2;
    constexpr int OFF_AL = BM * 64;
    constexpr int OFF_BH = 2 * BM * 64;
    constexpr int OFF_BL = 2 * BM * 64 + 8192;
    constexpr int STAGE  = 2 * BM * 64 + 16384;

    extern __shared__ __align__(16) unsigned char smem_raw[];
    uint32_t smemb = (uint32_t)__cvta_generic_to_shared(smem_raw);

    const int bx = blockIdx.x;
    const int by = blockIdx.y;
    const int Klocal = K / gridDim.z;
    const int kbase = blockIdx.z * Klocal;
    const int tid = threadIdx.x;
    const int lane = tid & 31;
    const int wid = tid >> 5;
    const int warpM = wid & 3;
    const int warpN = wid >> 2;
    const int gid = lane >> 2;
    const int tig = lane & 3;
    const int mBase = warpM * 16 * MT;
    const int nBase = warpN * 64;
    const int rowbase = by * BM;
    const int colbase = bx * 128;

    float acc[MT][8][4];
    #pragma unroll
    for (int mt = 0; mt < MT; mt++)
        #pragma unroll
        for (int nt = 0; nt < 8; nt++)
            #pragma unroll
            for (int r = 0; r < 4; r++) acc[mt][nt][r] = 0.0f;

    auto issue = [&](int buf, int k0) {
        uint32_t sb = smemb + buf * STAGE;
        #pragma unroll
        for (int it = 0; it < 2; it++) {
            int idx = tid + it * 256;
            int r = idx >> 2, ch = idx & 3;
            size_t go = (size_t)(rowbase + r) * lda + kbase + k0 + ch * 8;
            uint32_t so = (uint32_t)(r * 64 + ((ch ^ ((r >> 1) & 3)) << 4));
            cp16(sb + so, Ah + go);
            cp16(sb + OFF_AL + so, Al + go);
        }
        #pragma unroll
        for (int it = 0; it < 2; it++) {
            int idx = tid + it * 256;
            int krow = idx >> 4, ch = idx & 15;
            size_t go = (size_t)(kbase + k0 + krow) * N + colbase + ch * 8;
            uint32_t so = (uint32_t)(krow * 256 + ((ch ^ (krow & 7)) << 4));
            cp16(sb + OFF_BH + so, Bh + go);
            cp16(sb + OFF_BL + so, Bl + go);
        }
        asm volatile("cp.async.commit_group;" ::: "memory");
    };

    const int KT = Klocal >> 5;
    issue(0, 0);
    if (KT > 1) issue(1, 32);

    const int lane15 = lane & 15;
    const int laneh = lane >> 4;
    const int bk = lane & 15;
    const int bs = (lane >> 4) & 1;

    int buf = 0;
    for (int t = 0; t < KT; t++) {
        if (t + 1 < KT) {
            asm volatile("cp.async.wait_group 1;" ::: "memory");
        } else {
            asm volatile("cp.async.wait_group 0;" ::: "memory");
        }
        __syncthreads();
        if (t + 2 < KT) {
            int nb = buf + 2;
            if (nb >= 3) nb -= 3;
            issue(nb, (t + 2) * 32);
        }

        uint32_t sb = smemb + buf * STAGE;
        #pragma unroll
        for (int kk = 0; kk < 2; kk++) {
            uint32_t aHi[MT][4], aLo[MT][4];
            #pragma unroll
            for (int mt = 0; mt < MT; mt++) {
                int row = mBase + mt * 16 + lane15;
                int ch = (kk * 2 + laneh) ^ ((row >> 1) & 3);
                uint32_t ad = sb + (uint32_t)(row * 64 + (ch << 4));
                ldsm4(aHi[mt][0], aHi[mt][1], aHi[mt][2], aHi[mt][3], ad);
                ldsm4(aLo[mt][0], aLo[mt][1], aLo[mt][2], aLo[mt][3], ad + OFF_AL);
            }
            int krow = kk * 16 + bk;
            uint32_t bRow = sb + OFF_BH + (uint32_t)(krow * 256);
            #pragma unroll
            for (int nt2 = 0; nt2 < 4; nt2++) {
                uint32_t ch = (uint32_t)((((warpN * 8 + nt2 * 2 + bs) ^ (bk & 7))) * 16);
                uint32_t bh0, bh1, bh2, bh3, bl0, bl1, bl2, bl3;
                ldsm4t(bh0, bh1, bh2, bh3, bRow + ch);
                ldsm4t(bl0, bl1, bl2, bl3, bRow + (OFF_BL - OFF_BH) + ch);
                #pragma unroll
                for (int mt = 0; mt < MT; mt++) {
                    float* a0 = acc[mt][nt2 * 2];
                    mma_bf16(a0[0], a0[1], a0[2], a0[3],
                             aHi[mt][0], aHi[mt][1], aHi[mt][2], aHi[mt][3], bh0, bh1);
                    mma_bf16(a0[0], a0[1], a0[2], a0[3],
                             aHi[mt][0], aHi[mt][1], aHi[mt][2], aHi[mt][3], bl0, bl1);
                    mma_bf16(a0[0], a0[1], a0[2], a0[3],
                             aLo[mt][0], aLo[mt][1], aLo[mt][2], aLo[mt][3], bh0, bh1);
                    float* a1 = acc[mt][nt2 * 2 + 1];
                    mma_bf16(a1[0], a1[1], a1[2], a1[3],
                             aHi[mt][0], aHi[mt][1], aHi[mt][2], aHi[mt][3], bh2, bh3);
                    mma_bf16(a1[0], a1[1], a1[2], a1[3],
                             aHi[mt][0], aHi[mt][1], aHi[mt][2], aHi[mt][3], bl2, bl3);
                    mma_bf16(a1[0], a1[1], a1[2], a1[3],
                             aLo[mt][0], aLo[mt][1], aLo[mt][2], aLo[mt][3], bh2, bh3);
                }
            }
        }
        buf++;
        if (buf == 3) buf = 0;
    }

    float* Cout = C;
    if (blockIdx.z == 1) Cout = C2;
    else if (blockIdx.z == 2) Cout = C3;
    else if (blockIdx.z == 3) Cout = C4;
    const bool addb = (blockIdx.z == 0);
    #pragma unroll
    for (int nt = 0; nt < 8; nt++) {
        int col = colbase + nBase + nt * 8 + tig * 2;
        float b0 = addb ? bias[col] : 0.0f;
        float b1 = addb ? bias[col + 1] : 0.0f;
        #pragma unroll
        for (int mt = 0; mt < MT; mt++) {
            int row0 = rowbase + mBase + mt * 16 + gid;
            float v0 = acc[mt][nt][0] + b0;
            float v1 = acc[mt][nt][1] + b1;
            float v2 = acc[mt][nt][2] + b0;
            float v3 = acc[mt][nt][3] + b1;
            if (OUT == 0) {
                *(float2*)(Cout + (size_t)row0 * N + col) = make_float2(v0, v1);
                *(float2*)(Cout + (size_t)(row0 + 8) * N + col) = make_float2(v2, v3);
            } else {
                if (OUT == 2) {
                    v0 = gelu_exact(v0); v1 = gelu_exact(v1);
                    v2 = gelu_exact(v2); v3 = gelu_exact(v3);
                }
                size_t i0 = ((size_t)row0 * N + col) >> 1;
                size_t i1 = ((size_t)(row0 + 8) * N + col) >> 1;
                __nv_bfloat16 h0 = __float2bfloat16_rn(v0), h1 = __float2bfloat16_rn(v1);
                __nv_bfloat16 h2 = __float2bfloat16_rn(v2), h3 = __float2bfloat16_rn(v3);
                ((uint32_t*)Chi)[i0] = ((uint32_t)*(uint16_t*)&h0) | ((uint32_t)*(uint16_t*)&h1 << 16);
                ((uint32_t*)Chi)[i1] = ((uint32_t)*(uint16_t*)&h2) | ((uint32_t)*(uint16_t*)&h3 << 16);
                ((uint32_t*)Clo)[i0] = pack_bf16x2(v0 - __bfloat162float(h0), v1 - __bfloat162float(h1));
                ((uint32_t*)Clo)[i1] = pack_bf16x2(v2 - __bfloat162float(h2), v3 - __bfloat162float(h3));
            }
        }
    }
}

// ---------------- tensor-core sliding-window flash attention ------------------
#define ATT_SMEM (65536 + 256)
__global__ __launch_bounds__(128) void attn_mma_kernel(
    const __nv_bfloat16* __restrict__ qkvh, const __nv_bfloat16* __restrict__ qkvl,
    const int* __restrict__ mask,
    __nv_bfloat16* __restrict__ oh, __nv_bfloat16* __restrict__ ol) {
    extern __shared__ __align__(16) unsigned char asmem[];
    const uint32_t sb = (uint32_t)__cvta_generic_to_shared(asmem);
    const uint32_t QH = sb, QL = sb + 16384;
    int* mskbuf = (int*)(asmem + 65536);

    const int h = blockIdx.y;
    const int q0 = blockIdx.x * 128;
    const int tid = threadIdx.x, lane = tid & 31, wid = tid >> 5;
    const int gid = lane >> 2, tig = lane & 3;
    const int mBase = wid * 32;
    const int STR = 3 * DIM;
    const int NC = (128 + 2 * WIN) / 32;

    auto issueKV = [&](int st, int c) {
        uint32_t kb = sb + 32768 + st * 16384;
        #pragma unroll
        for (int i = 0; i < 2; i++) {
            int idx = tid + i * 128;
            int row = idx >> 3, ch = idx & 7;
            int kp = c + row;
            int kc = kp < 0 ? 0 : (kp >= SEQ ? SEQ - 1 : kp);
            size_t gk = (size_t)kc * STR + DIM + h * 64 + ch * 8;
            size_t gv = (size_t)kc * STR + 2 * DIM + h * 64 + ch * 8;
            uint32_t so = (uint32_t)(row * 128 + ((ch ^ (row & 7)) << 4));
            cp16(kb + so, qkvh + gk);
            cp16(kb + 4096 + so, qkvl + gk);
            cp16(kb + 8192 + so, qkvh + gv);
            cp16(kb + 12288 + so, qkvl + gv);
        }
        if (tid < 32) {
            int kp = c + tid;
            mskbuf[st * 32 + tid] = (kp >= 0 && kp < SEQ) ? mask[kp] : 0;
        }
    };

    #pragma unroll
    for (int i = 0; i < 8; i++) {
        int idx = tid + i * 128;
        int row = idx >> 3, ch = idx & 7;
        size_t gq = (size_t)(q0 + row) * STR + h * 64 + ch * 8;
        uint32_t so = (uint32_t)(row * 128 + ((ch ^ (row & 7)) << 4));
        cp16(QH + so, qkvh + gq);
        cp16(QL + so, qkvl + gq);
    }
    const int cstart = q0 - WIN;
    issueKV(0, cstart);
    asm volatile("cp.async.commit_group;" ::: "memory");

    uint32_t Qhi[2][4][4], Qlo[2][4][4];
    float O[2][8][4];
    #pragma unroll
    for (int mt = 0; mt < 2; mt++)
        #pragma unroll
        for (int dj = 0; dj < 8; dj++)
            #pragma unroll
            for (int r = 0; r < 4; r++) O[mt][dj][r] = 0.0f;
    float mrow[2][2] = {{-1e30f, -1e30f}, {-1e30f, -1e30f}};
    float lrow[2][2] = {{0.0f, 0.0f}, {0.0f, 0.0f}};

    const int warpLo = q0 + mBase - WIN;
    const int warpHi = q0 + mBase + 31 + WIN;

    for (int t = 0; t < NC; t++) {
        const int c = cstart + t * 32;
        if (t + 1 < NC) {
            issueKV((t + 1) & 1, c + 32);
            asm volatile("cp.async.commit_group;" ::: "memory");
            asm volatile("cp.async.wait_group 1;" ::: "memory");
        } else {
            asm volatile("cp.async.wait_group 0;" ::: "memory");
        }
        __syncthreads();

        if (t == 0) {
            int arow = (lane & 7) + 8 * ((lane >> 3) & 1);
            int achsel = lane >> 4;
            #pragma unroll
            for (int mt = 0; mt < 2; mt++) {
                int row = mBase + mt * 16 + arow;
                #pragma unroll
                for (int kk = 0; kk < 4; kk++) {
                    int chunk = kk * 2 + achsel;
                    uint32_t ad = (uint32_t)(row * 128 + ((chunk ^ (row & 7)) << 4));
                    ldsm4(Qhi[mt][kk][0], Qhi[mt][kk][1], Qhi[mt][kk][2], Qhi[mt][kk][3], QH + ad);
                    ldsm4(Qlo[mt][kk][0], Qlo[mt][kk][1], Qlo[mt][kk][2], Qlo[mt][kk][3], QL + ad);
                }
            }
        }

        if (c + 31 >= warpLo && c <= warpHi) {
            const uint32_t KB = sb + 32768 + (t & 1) * 16384;
            const int* msk = mskbuf + (t & 1) * 32;

            float S[2][4][4];
            #pragma unroll
            for (int mt = 0; mt < 2; mt++)
                #pragma unroll
                for (int j = 0; j < 4; j++)
                    #pragma unroll
                    for (int r = 0; r < 4; r++) S[mt][j][r] = 0.0f;

            #pragma unroll
            for (int j = 0; j < 4; j++) {
                uint32_t kh[4][2], kl[4][2];
                int krow = j * 8 + (lane & 7);
                #pragma unroll
                for (int h32 = 0; h32 < 2; h32++) {
                    int chunk = h32 * 4 + (lane >> 3);
                    uint32_t ad = (uint32_t)(krow * 128 + ((chunk ^ (krow & 7)) << 4));
                    uint32_t r0, r1, r2, r3;
                    ldsm4(r0, r1, r2, r3, KB + ad);
                    kh[h32 * 2][0] = r0; kh[h32 * 2][1] = r1;
                    kh[h32 * 2 + 1][0] = r2; kh[h32 * 2 + 1][1] = r3;
                    ldsm4(r0, r1, r2, r3, KB + 4096 + ad);
                    kl[h32 * 2][0] = r0; kl[h32 * 2][1] = r1;
                    kl[h32 * 2 + 1][0] = r2; kl[h32 * 2 + 1][1] = r3;
                }
                #pragma unroll
                for (int kk = 0; kk < 4; kk++)
                    #pragma unroll
                    for (int mt = 0; mt < 2; mt++) {
                        float* s = S[mt][j];
                        mma_bf16(s[0], s[1], s[2], s[3],
                                 Qhi[mt][kk][0], Qhi[mt][kk][1], Qhi[mt][kk][2], Qhi[mt][kk][3],
                                 kh[kk][0], kh[kk][1]);
                        mma_bf16(s[0], s[1], s[2], s[3],
                                 Qhi[mt][kk][0], Qhi[mt][kk][1], Qhi[mt][kk][2], Qhi[mt][kk][3],
                                 kl[kk][0], kl[kk][1]);
                        mma_bf16(s[0], s[1], s[2], s[3],
                                 Qlo[mt][kk][0], Qlo[mt][kk][1], Qlo[mt][kk][2], Qlo[mt][kk][3],
                                 kh[kk][0], kh[kk][1]);
                    }
            }

            float p[2][4][4];
            #pragma unroll
            for (int mt = 0; mt < 2; mt++) {
                int rA = q0 + mBase + mt * 16 + gid;
                int rB = rA + 8;
                float mxA = -1e30f, mxB = -1e30f;
                #pragma unroll
                for (int j = 0; j < 4; j++) {
                    int c0 = c + j * 8 + tig * 2;
                    int c1 = c0 + 1;
                    int mk0 = msk[j * 8 + tig * 2];
                    int mk1 = msk[j * 8 + tig * 2 + 1];
                    bool v00 = mk0 && (c0 >= rA - WIN) && (c0 <= rA + WIN);
                    bool v01 = mk1 && (c1 >= rA - WIN) && (c1 <= rA + WIN);
                    bool v10 = mk0 && (c0 >= rB - WIN) && (c0 <= rB + WIN);
                    bool v11 = mk1 && (c1 >= rB - WIN) && (c1 <= rB + WIN);
                    S[mt][j][0] = v00 ? S[mt][j][0] * 0.125f : -1e30f;
                    S[mt][j][1] = v01 ? S[mt][j][1] * 0.125f : -1e30f;
                    S[mt][j][2] = v10 ? S[mt][j][2] * 0.125f : -1e30f;
                    S[mt][j][3] = v11 ? S[mt][j][3] * 0.125f : -1e30f;
                    mxA = fmaxf(mxA, fmaxf(S[mt][j][0], S[mt][j][1]));
                    mxB = fmaxf(mxB, fmaxf(S[mt][j][2], S[mt][j][3]));
                }
                mxA = fmaxf(mxA, __shfl_xor_sync(0xffffffffu, mxA, 1));
                mxA = fmaxf(mxA, __shfl_xor_sync(0xffffffffu, mxA, 2));
                mxB = fmaxf(mxB, __shfl_xor_sync(0xffffffffu, mxB, 1));
                mxB = fmaxf(mxB, __shfl_xor_sync(0xffffffffu, mxB, 2));
                float mnA = fmaxf(mrow[mt][0], mxA);
                float mnB = fmaxf(mrow[mt][1], mxB);
                float scA = __expf(mrow[mt][0] - mnA);
                float scB = __expf(mrow[mt][1] - mnB);
                mrow[mt][0] = mnA; mrow[mt][1] = mnB;
                float sA = 0.0f, sB = 0.0f;
                #pragma unroll
                for (int j = 0; j < 4; j++) {
                    float p0 = (S[mt][j][0] > -1e29f) ? __expf(S[mt][j][0] - mnA) : 0.0f;
                    float p1 = (S[mt][j][1] > -1e29f) ? __expf(S[mt][j][1] - mnA) : 0.0f;
                    float p2 = (S[mt][j][2] > -1e29f) ? __expf(S[mt][j][2] - mnB) : 0.0f;
                    float p3 = (S[mt][j][3] > -1e29f) ? __expf(S[mt][j][3] - mnB) : 0.0f;
                    p[mt][j][0] = p0; p[mt][j][1] = p1; p[mt][j][2] = p2; p[mt][j][3] = p3;
                    sA += p0 + p1; sB += p2 + p3;
                }
                sA += __shfl_xor_sync(0xffffffffu, sA, 1);
                sA += __shfl_xor_sync(0xffffffffu, sA, 2);
                sB += __shfl_xor_sync(0xffffffffu, sB, 1);
                sB += __shfl_xor_sync(0xffffffffu, sB, 2);
                lrow[mt][0] = lrow[mt][0] * scA + sA;
                lrow[mt][1] = lrow[mt][1] * scB + sB;
                #pragma unroll
                for (int dj = 0; dj < 8; dj++) {
                    O[mt][dj][0] *= scA; O[mt][dj][1] *= scA;
                    O[mt][dj][2] *= scB; O[mt][dj][3] *= scB;
                }
            }

            uint32_t Phi[2][2][4], Plo[2][2][4];
            #pragma unroll
            for (int mt = 0; mt < 2; mt++)
                #pragma unroll
                for (int kk = 0; kk < 2; kk++) {
                    #pragma unroll
                    for (int q = 0; q < 4; q++) {
                        int j = 2 * kk + (q >> 1);
                        int r0 = (q & 1) * 2;
                        float x0 = p[mt][j][r0], x1 = p[mt][j][r0 + 1];
                        __nv_bfloat162 hh = __floats2bfloat162_rn(x0, x1);
                        Phi[mt][kk][q] = *(uint32_t*)&hh;
                        Plo[mt][kk][q] = pack_bf16x2(x0 - __bfloat162float(hh.x),
                                                     x1 - __bfloat162float(hh.y));
                    }
                }

            #pragma unroll
            for (int djp = 0; djp < 4; djp++) {
                #pragma unroll
                for (int kk = 0; kk < 2; kk++) {
                    int vrow = kk * 16 + (lane & 7) + 8 * ((lane >> 3) & 1);
                    int chunk = djp * 2 + (lane >> 4);
                    uint32_t ad = (uint32_t)(vrow * 128 + ((chunk ^ (vrow & 7)) << 4));
                    uint32_t h0, h1, h2, h3, l0, l1, l2, l3;
                    ldsm4t(h0, h1, h2, h3, KB + 8192 + ad);
                    ldsm4t(l0, l1, l2, l3, KB + 12288 + ad);
                    #pragma unroll
                    for (int mt = 0; mt < 2; mt++) {
                        float* o0 = O[mt][djp * 2];
                        float* o1 = O[mt][djp * 2 + 1];
                        mma_bf16(o0[0], o0[1], o0[2], o0[3],
                                 Phi[mt][kk][0], Phi[mt][kk][1], Phi[mt][kk][2], Phi[mt][kk][3],
                                 h0, h1);
                        mma_bf16(o0[0], o0[1], o0[2], o0[3],
                                 Plo[mt][kk][0], Plo[mt][kk][1], Plo[mt][kk][2], Plo[mt][kk][3],
                                 h0, h1);
                        mma_bf16(o0[0], o0[1], o0[2], o0[3],
                                 Phi[mt][kk][0], Phi[mt][kk][1], Phi[mt][kk][2], Phi[mt][kk][3],
                                 l0, l1);
                        mma_bf16(o1[0], o1[1], o1[2], o1[3],
                                 Phi[mt][kk][0], Phi[mt][kk][1], Phi[mt][kk][2], Phi[mt][kk][3],
                                 h2, h3);
                        mma_bf16(o1[0], o1[1], o1[2], o1[3],
                                 Plo[mt][kk][0], Plo[mt][kk][1], Plo[mt][kk][2], Plo[mt][kk][3],
                                 h2, h3);
                        mma_bf16(o1[0], o1[1], o1[2], o1[3],
                                 Phi[mt][kk][0], Phi[mt][kk][1], Phi[mt][kk][2], Phi[mt][kk][3],
                                 l2, l3);
                    }
                }
            }
        }
        __syncthreads();   // WAR guard
    }

    #pragma unroll
    for (int mt = 0; mt < 2; mt++) {
        float invA = (lrow[mt][0] > 0.0f) ? (1.0f / lrow[mt][0]) : 0.0f;
        float invB = (lrow[mt][1] > 0.0f) ? (1.0f / lrow[mt][1]) : 0.0f;
        int rA = q0 + mBase + mt * 16 + gid;
        int rB = rA + 8;
        #pragma unroll
        for (int dj = 0; dj < 8; dj++) {
            int col = h * 64 + dj * 8 + tig * 2;
            float v0 = O[mt][dj][0] * invA, v1 = O[mt][dj][1] * invA;
            float v2 = O[mt][dj][2] * invB, v3 = O[mt][dj][3] * invB;
            size_t iA = ((size_t)rA * DIM + col) >> 1;
            size_t iB = ((size_t)rB * DIM + col) >> 1;
            __nv_bfloat162 hA = __floats2bfloat162_rn(v0, v1);
            __nv_bfloat162 hB = __floats2bfloat162_rn(v2, v3);
            ((uint32_t*)oh)[iA] = *(uint32_t*)&hA;
            ((uint32_t*)oh)[iB] = *(uint32_t*)&hB;
            ((uint32_t*)ol)[iA] = pack_bf16x2(v0 - __bfloat162float(hA.x),
                                              v1 - __bfloat162float(hA.y));
            ((uint32_t*)ol)[iB] = pack_bf16x2(v2 - __bfloat162float(hB.x),
                                              v3 - __bfloat162float(hB.y));
        }
    }
}

// ---------------- classification heads (768 -> 512 relu -> nout) ------------
__global__ void head_kernel(const float* __restrict__ x, const float* __restrict__ W1,
                            const float* __restrict__ b1, const float* __restrict__ W2,
                            const float* __restrict__ b2, float* __restrict__ out, int nout) {
    __shared__ float xs[768];
    __shared__ float hsm[512];
    int t = threadIdx.x;
    for (int i = t; i < 768; i += 512) xs[i] = x[i];
    __syncthreads();
    float acc = b1[t];
    for (int kk = 0; kk < 768; kk++) acc += xs[kk] * W1[(size_t)kk * 512 + t];
    hsm[t] = fmaxf(acc, 0.0f);
    __syncthreads();
    if (t < nout) {
        float ov = b2[t];
        for (int kk = 0; kk < 512; kk++) ov += hsm[kk] * W2[(size_t)kk * nout + t];
        out[t] = ov;
    }
}

// ---------------- host launcher ---------------------------------------------
extern "C" void kernel_launch(void* const* d_in, const int* in_sizes, int n_in,
                              void* d_out, int out_size) {
    const int*   ids      = (const int*)d_in[0];
    const int*   mask     = (const int*)d_in[1];
    const float* emb_word = (const float*)d_in[2];
    const float* emb_pos  = (const float*)d_in[3];
    const float* emb_type = (const float*)d_in[4];
    const float* emb_g    = (const float*)d_in[5];
    const float* emb_b    = (const float*)d_in[6];
    const float* Wq = (const float*)d_in[7];
    const float* bq = (const float*)d_in[8];
    const float* Wk = (const float*)d_in[9];
    const float* bk = (const float*)d_in[10];
    const float* Wv = (const float*)d_in[11];
    const float* bv = (const float*)d_in[12];
    const float* Wo = (const float*)d_in[13];
    const float* bo = (const float*)d_in[14];
    const float* ln1g = (const float*)d_in[15];
    const float* ln1b = (const float*)d_in[16];
    const float* W1 = (const float*)d_in[17];
    const float* b1 = (const float*)d_in[18];
    const float* W2 = (const float*)d_in[19];
    const float* b2 = (const float*)d_in[20];
    const float* ln2g = (const float*)d_in[21];
    const float* ln2b = (const float*)d_in[22];
    const float* cW1 = (const float*)d_in[23];
    const float* cb1 = (const float*)d_in[24];
    const float* cW2 = (const float*)d_in[25];
    const float* cb2 = (const float*)d_in[26];
    const float* dW1 = (const float*)d_in[27];
    const float* db1 = (const float*)d_in[28];
    const float* dW2 = (const float*)d_in[29];
    const float* db2 = (const float*)d_in[30];
    float* out = (float*)d_out;

    float *x, *t, *t2, *t3, *t4, *bcat;
    int* pos;
    __nv_bfloat16 *xh, *xl, *qkvh, *qkvl, *ah, *al, *hh, *hl;
    __nv_bfloat16 *wqh, *wql, *w1h, *w1l, *w2h, *w2l, *woh, *wol;
    cudaGetSymbolAddress((void**)&x, g_x);
    cudaGetSymbolAddress((void**)&t, g_t);
    cudaGetSymbolAddress((void**)&t2, g_t2);
    cudaGetSymbolAddress((void**)&t3, g_t3);
    cudaGetSymbolAddress((void**)&t4, g_t4);
    cudaGetSymbolAddress((void**)&bcat, g_bcat);
    cudaGetSymbolAddress((void**)&pos, g_pos);
    cudaGetSymbolAddress((void**)&xh, g_xh);
    cudaGetSymbolAddress((void**)&xl, g_xl);
    cudaGetSymbolAddress((void**)&qkvh, g_qkvh);
    cudaGetSymbolAddress((void**)&qkvl, g_qkvl);
    cudaGetSymbolAddress((void**)&ah, g_ah);
    cudaGetSymbolAddress((void**)&al, g_al);
    cudaGetSymbolAddress((void**)&hh, g_hh);
    cudaGetSymbolAddress((void**)&hl, g_hl);
    cudaGetSymbolAddress((void**)&wqh, g_wqh);
    cudaGetSymbolAddress((void**)&wql, g_wql);
    cudaGetSymbolAddress((void**)&w1h, g_w1h);
    cudaGetSymbolAddress((void**)&w1l, g_w1l);
    cudaGetSymbolAddress((void**)&w2h, g_w2h);
    cudaGetSymbolAddress((void**)&w2l, g_w2l);
    cudaGetSymbolAddress((void**)&woh, g_woh);
    cudaGetSymbolAddress((void**)&wol, g_wol);

    const int SM128 = 3 * (2 * 128 * 64 + 16384);   // 98304 (3-stage)
    cudaFuncSetAttribute(tgemm_kernel<0>, cudaFuncAttributeMaxDynamicSharedMemorySize, SM128);
    cudaFuncSetAttribute(tgemm_kernel<2>, cudaFuncAttributeMaxDynamicSharedMemorySize, SM128);
    cudaFuncSetAttribute(tgemm_kernel<3>, cudaFuncAttributeMaxDynamicSharedMemorySize, SM128);
    cudaFuncSetAttribute(attn_mma_kernel, cudaFuncAttributeMaxDynamicSharedMemorySize, ATT_SMEM);

    pos_kernel<<<1, 1024>>>(mask, pos);
    embed_ln_kernel<<<SEQ, 256>>>(ids, pos, emb_word, emb_pos, emb_type, emb_g, emb_b, x, xh, xl);

    dim3 gqkv(3 * DIM / 128, SEQ / 128, 1);   // (18, 32)
    dim3 go(DIM / 128, SEQ / 128, 4);         // (6, 32, 4) split-K4, BM=128
    dim3 gff1(FFD / 128, SEQ / 128, 1);       // (24, 32)
    dim3 gff2(DIM / 128, SEQ / 128, 4);       // (6, 32, 4) split-K4, BM=128
    dim3 gattn(SEQ / 128, NH);

    for (int i = 0; i < NL; i++) {
        const float* wq = Wq + (size_t)i * DIM * DIM;
        const float* wk = Wk + (size_t)i * DIM * DIM;
        const float* wv = Wv + (size_t)i * DIM * DIM;
        const float* wo = Wo + (size_t)i * DIM * DIM;
        const float* w1 = W1 + (size_t)i * DIM * FFD;
        const float* w2 = W2 + (size_t)i * FFD * DIM;

        prep_kernel<<<5760, 256>>>(w1, w2, wo, wq, wk, wv,
                                   bq + i * DIM, bk + i * DIM, bv + i * DIM,
                                   w1h, w1l, w2h, w2l, woh, wol, wqh, wql, bcat);

        tgemm_kernel<3><<<gqkv, 256, SM128>>>(xh, xl, wqh, wql, bcat,
                                              nullptr, nullptr, nullptr, nullptr,
                                              qkvh, qkvl, SEQ, 3 * DIM, DIM, DIM);
        attn_mma_kernel<<<gattn, 128, ATT_SMEM>>>(qkvh, qkvl, mask, ah, al);
        tgemm_kernel<0><<<go, 256, SM128>>>(ah, al, woh, wol, bo + i * DIM,
                                            t, t2, t3, t4, nullptr, nullptr,
                                            SEQ, DIM, DIM, DIM);
        lnres_kernel<<<SEQ, 256>>>(x, t, t2, t3, t4, ln1g + i * DIM, ln1b + i * DIM, xh, xl);
        tgemm_kernel<2><<<gff1, 256, SM128>>>(xh, xl, w1h, w1l, b1 + i * FFD,
                                              nullptr, nullptr, nullptr, nullptr,
                                              hh, hl, SEQ, FFD, DIM, DIM);
        tgemm_kernel<0><<<gff2, 256, SM128>>>(hh, hl, w2h, w2l, b2 + i * DIM,
                                              t, t2, t3, t4, nullptr, nullptr,
                                              SEQ, DIM, FFD, FFD);
        lnres_kernel<<<SEQ, 256>>>(x, t, t2, t3, t4, ln2g + i * DIM, ln2b + i * DIM, xh, xl);
    }

    head_kernel<<<1, 512>>>(x, cW1, cb1, cW2, cb2, out, 5);
    head_kernel<<<1, 512>>>(x, dW1, db1, dW2, db2, out + 5, 10);
}